// round 10
// baseline (speedup 1.0000x reference)
#include <cuda_runtime.h>
#include <cuda_fp16.h>
#include <math.h>
#include <stdint.h>

// Problem constants
#define BB 2
#define LL 2048
#define DD 4096
#define HH 32
#define HDIM 128
#define MM (BB*LL)          // 4096 rows
#define ATT_SCALE 0.08838834764831845f

// ---------------------------------------------------------------------------
// Scratch (allocation-free rule: __device__ globals)
// ---------------------------------------------------------------------------
__device__ __half g_ah[(size_t)MM*DD];       // A hi (x or ctx)
__device__ __half g_al[(size_t)MM*DD];       // A lo
__device__ __half g_bq[(size_t)DD*DD];       // Wq^T fp16 [N,K]
__device__ __half g_bk[(size_t)DD*DD];
__device__ __half g_bv[(size_t)DD*DD];
__device__ __half g_bo[(size_t)DD*DD];
__device__ __half g_qh[(size_t)MM*DD];       // q hi (scaled) [B,H,L,d]
__device__ __half g_ql[(size_t)MM*DD];       // q lo
__device__ __half g_kh[(size_t)MM*DD];       // k fp16
__device__ __half g_vh[(size_t)MM*DD];       // v fp16

__device__ __forceinline__ uint32_t smem_u32(const void* p) {
    uint32_t a;
    asm("{ .reg .u64 t; cvta.to.shared.u64 t, %1; cvt.u32.u64 %0, t; }"
        : "=r"(a) : "l"(p));
    return a;
}

#define LDSM4(r, addr) \
    asm volatile("ldmatrix.sync.aligned.m8n8.x4.shared.b16 {%0,%1,%2,%3}, [%4];" \
        : "=r"((r)[0]), "=r"((r)[1]), "=r"((r)[2]), "=r"((r)[3]) : "r"(addr))
#define LDSM4T(r, addr) \
    asm volatile("ldmatrix.sync.aligned.m8n8.x4.trans.shared.b16 {%0,%1,%2,%3}, [%4];" \
        : "=r"((r)[0]), "=r"((r)[1]), "=r"((r)[2]), "=r"((r)[3]) : "r"(addr))

#define MMA_F16(d, a, b0, b1) \
    asm volatile("mma.sync.aligned.m16n8k16.row.col.f32.f16.f16.f32 " \
        "{%0,%1,%2,%3}, {%4,%5,%6,%7}, {%8,%9}, {%0,%1,%2,%3};" \
        : "+f"((d)[0]), "+f"((d)[1]), "+f"((d)[2]), "+f"((d)[3]) \
        : "r"((a)[0]), "r"((a)[1]), "r"((a)[2]), "r"((a)[3]), "r"(b0), "r"(b1))

#define CP_ASYNC16(dst, src) \
    asm volatile("cp.async.cg.shared.global [%0], [%1], 16;" \
        :: "r"(dst), "l"(src) : "memory")
#define CP_COMMIT() asm volatile("cp.async.commit_group;" ::: "memory")
#define CP_WAIT0() asm volatile("cp.async.wait_group 0;" ::: "memory")

__device__ __forceinline__ uint32_t pack_h2(float x, float y) {
    __half2 t = __floats2half2_rn(x, y);
    return *(uint32_t*)&t;
}

// ---------------------------------------------------------------------------
// Conversion kernels
// ---------------------------------------------------------------------------
struct __align__(8) h16x4 { __half v[4]; };

__global__ __launch_bounds__(256) void conv_split_kernel(
    const float4* __restrict__ in, h16x4* __restrict__ oh, h16x4* __restrict__ ol, int n4)
{
    int i = blockIdx.x * 256 + threadIdx.x;
    if (i >= n4) return;
    float4 x = in[i];
    h16x4 h, l;
    h.v[0] = __float2half_rn(x.x); l.v[0] = __float2half_rn(x.x - __half2float(h.v[0]));
    h.v[1] = __float2half_rn(x.y); l.v[1] = __float2half_rn(x.y - __half2float(h.v[1]));
    h.v[2] = __float2half_rn(x.z); l.v[2] = __float2half_rn(x.z - __half2float(h.v[2]));
    h.v[3] = __float2half_rn(x.w); l.v[3] = __float2half_rn(x.w - __half2float(h.v[3]));
    oh[i] = h;
    ol[i] = l;
}

// 4 weight transposes fused: W [K,N] f32 -> Wt fp16 [N,K], blockIdx.z picks W.
__global__ __launch_bounds__(256) void conv_tr4_kernel(
    const float* __restrict__ W0, const float* __restrict__ W1,
    const float* __restrict__ W2, const float* __restrict__ W3,
    __half* __restrict__ T0, __half* __restrict__ T1,
    __half* __restrict__ T2, __half* __restrict__ T3)
{
    const float* W = (blockIdx.z == 0) ? W0 : (blockIdx.z == 1) ? W1
                    : (blockIdx.z == 2) ? W2 : W3;
    __half* Th = (blockIdx.z == 0) ? T0 : (blockIdx.z == 1) ? T1
                : (blockIdx.z == 2) ? T2 : T3;
    __shared__ float sm[32][33];
    const int k0 = blockIdx.x * 32, n0 = blockIdx.y * 32;
    const int tx = threadIdx.x, ty = threadIdx.y;     // (32, 8)
#pragma unroll
    for (int i = 0; i < 4; i++)
        sm[ty + 8 * i][tx] = W[(size_t)(k0 + ty + 8 * i) * DD + n0 + tx];
    __syncthreads();
#pragma unroll
    for (int i = 0; i < 4; i++) {
        float v = sm[tx][ty + 8 * i];
        Th[(size_t)(n0 + ty + 8 * i) * DD + k0 + tx] = __float2half_rn(v);
    }
}

// ---------------------------------------------------------------------------
// HMMA GEMM: out[M,N] = A[M,K] @ W[K,N] + bias, fp16 2-term split (A hi/lo).
// CTA 128x128, 4 warps 2x2, warp tile 64x64, K-chunk 64, XOR-swizzled smem.
// 2 CTAs/SM, single __syncthreads per chunk (load issued post-sync).
// blockIdx.y selects one of up to 3 jobs (fused QKV launch merges tail waves).
// mode 0: fp32 row-major; 1: fp16 hi/lo scaled head-split (Q);
// 2: fp32 head-split + fp16 head-split (K,V)
// ---------------------------------------------------------------------------
#define KCH 64
#define TILE_SZ 16384                     // 128 rows x 128 B
#define STAGE_BYTES (3 * TILE_SZ)         // 49152  (Ah, Al, B)
#define GEMM_SMEM (2 * STAGE_BYTES)       // 98304
#define NCHUNK (DD / KCH)                 // 64

struct GemmJob {
    const __half* B;      // W^T fp16 [N,K]
    const float* bias;
    float* out;
    __half* oh;
    __half* ol;
    float scale;
    int mode;
};

__global__ __launch_bounds__(128, 2) void gemm_mma_kernel(
    const __half* __restrict__ Ah, const __half* __restrict__ Al,
    GemmJob j0, GemmJob j1, GemmJob j2)
{
    const GemmJob j = (blockIdx.y == 0) ? j0 : (blockIdx.y == 1) ? j1 : j2;

    extern __shared__ __align__(16) char smem[];
    const uint32_t sb = smem_u32(smem);
    const int tid = threadIdx.x, lane = tid & 31, wid = tid >> 5;
    const int wm = wid >> 1;              // 0..1
    const int wn = wid & 1;               // 0..1
    // swizzled block mapping: groups of (32 m x 8 n)
    const int gid = blockIdx.x;
    const int m0 = (((gid & 255) >> 3)) * 128;
    const int n0 = (((gid >> 8) << 3) | (gid & 7)) * 128;

    const __half* gsrc[3];
    gsrc[0] = Ah + (size_t)m0 * DD;
    gsrc[1] = Al + (size_t)m0 * DD;
    gsrc[2] = j.B + (size_t)n0 * DD;

    float acc[4][8][4];
#pragma unroll
    for (int i = 0; i < 4; i++)
#pragma unroll
        for (int jj = 0; jj < 8; jj++)
#pragma unroll
            for (int e = 0; e < 4; e++) acc[i][jj][e] = 0.f;

    // per-lane LDSM addressing (swizzled): row stride 128B, granule ^= (row&7)
    const int rowA = wm * 64 + (lane & 15);       // +16*i
    const int a_half = lane >> 4;
    const int s_a = lane & 7;
    const int rowB = wn * 64 + ((lane >> 4) << 3) + (lane & 7);   // +16*j
    const int b_half = (lane >> 3) & 1;
    const int s_b = lane & 7;

#define LOAD_CHUNK(cc, st) do {                                                \
    const uint32_t stage_ = sb + (uint32_t)(st) * STAGE_BYTES;                 \
    _Pragma("unroll")                                                          \
    for (int t_ = 0; t_ < 3; ++t_) {                                           \
        const __half* gp_ = gsrc[t_] + (size_t)(cc) * KCH;                     \
        _Pragma("unroll")                                                      \
        for (int i_ = 0; i_ < 8; ++i_) {                                       \
            int f_ = tid + i_ * 128;              /* 0..1023 */                \
            int r_ = f_ >> 3, g_ = f_ & 7;                                     \
            const void* src_ = gp_ + (size_t)r_ * DD + g_ * 8;                 \
            uint32_t dst_ = stage_ + t_ * TILE_SZ + r_ * 128                   \
                            + ((g_ ^ (r_ & 7)) << 4);                          \
            CP_ASYNC16(dst_, src_);                                            \
        }                                                                      \
    }                                                                          \
    CP_COMMIT();                                                               \
} while (0)

    LOAD_CHUNK(0, 0);

#pragma unroll 1
    for (int c = 0; c < NCHUNK; ++c) {
        CP_WAIT0();           // load(c) landed (was issued before compute(c-1))
        __syncthreads();      // all warps done with compute(c-1); data c visible
        if (c + 1 < NCHUNK) LOAD_CHUNK(c + 1, (c + 1) & 1);   // overlaps compute(c)

        const uint32_t stage = sb + (uint32_t)(c & 1) * STAGE_BYTES;

#pragma unroll
        for (int kk = 0; kk < 4; ++kk) {
            const uint32_t ga = (uint32_t)(((2 * kk + a_half) ^ s_a) << 4);
            const uint32_t gb = (uint32_t)(((2 * kk + b_half) ^ s_b) << 4);
            uint32_t ah_[4][4], al_[4][4], bf_[4][4];
#pragma unroll
            for (int i = 0; i < 4; ++i) {
                const uint32_t ra = (uint32_t)(rowA + i * 16) * 128 + ga;
                LDSM4(ah_[i], stage + ra);
                LDSM4(al_[i], stage + TILE_SZ + ra);
            }
#pragma unroll
            for (int jj = 0; jj < 4; ++jj)
                LDSM4(bf_[jj], stage + 2 * TILE_SZ
                              + (uint32_t)(rowB + jj * 16) * 128 + gb);
#pragma unroll
            for (int i = 0; i < 4; ++i)
#pragma unroll
                for (int jn = 0; jn < 8; ++jn)
                    MMA_F16(acc[i][jn], ah_[i], bf_[jn >> 1][(jn & 1) * 2],
                            bf_[jn >> 1][(jn & 1) * 2 + 1]);
#pragma unroll
            for (int i = 0; i < 4; ++i)
#pragma unroll
                for (int jn = 0; jn < 8; ++jn)
                    MMA_F16(acc[i][jn], al_[i], bf_[jn >> 1][(jn & 1) * 2],
                            bf_[jn >> 1][(jn & 1) * 2 + 1]);
        }
    }
#undef LOAD_CHUNK

    // epilogue
#pragma unroll
    for (int i = 0; i < 4; ++i) {
        const int r_lo = m0 + wm * 64 + i * 16 + (lane >> 2);
#pragma unroll
        for (int jn = 0; jn < 8; ++jn) {
            const int colg = n0 + wn * 64 + jn * 8 + (lane & 3) * 2;
            const float bv0 = j.bias[colg], bv1 = j.bias[colg + 1];
#pragma unroll
            for (int half_ = 0; half_ < 2; ++half_) {
                const int row = r_lo + half_ * 8;
                float vx = acc[i][jn][half_ * 2 + 0] + bv0;
                float vy = acc[i][jn][half_ * 2 + 1] + bv1;
                if (j.mode == 0) {
                    float2 v; v.x = vx; v.y = vy;
                    *(float2*)(j.out + (size_t)row * DD + colg) = v;
                } else {
                    int b_ = row >> 11, l_ = row & 2047, h_ = colg >> 7, dd = colg & 127;
                    size_t idx = ((((size_t)b_ * HH + h_) * LL + l_) * HDIM) + dd;
                    if (j.mode == 2) {
                        float2 v; v.x = vx; v.y = vy;
                        *(float2*)(j.out + idx) = v;
                        *(uint32_t*)(j.oh + idx) = pack_h2(vx, vy);
                    } else {
                        float sx = vx * j.scale, sy = vy * j.scale;
                        __half hx = __float2half_rn(sx), hy = __float2half_rn(sy);
                        float rx = sx - __half2float(hx), ry = sy - __half2float(hy);
                        __half2 hp; hp.x = hx; hp.y = hy;
                        *(uint32_t*)(j.oh + idx) = *(uint32_t*)&hp;
                        *(uint32_t*)(j.ol + idx) = pack_h2(rx, ry);
                    }
                }
            }
        }
    }
}

// ---------------------------------------------------------------------------
// Flash attention (causal), HMMA fp16 2-term.
// Grid (L/128, H, B), 256 threads (8 warps x 16 q-rows).
// Single-sync double-buffered K/V.
// ---------------------------------------------------------------------------
#define AROWSTR 272                        // 128 fp16 = 256 B + 16 pad
#define ATILE_Q (128 * AROWSTR)            // 34816
#define ATILE_KV (64 * AROWSTR)            // 17408
#define ATT_SMEM (2 * ATILE_Q + 4 * ATILE_KV)   // 139264

__global__ __launch_bounds__(256, 1) void attn_mma_kernel(
    const __half* __restrict__ qh, const __half* __restrict__ ql,
    const __half* __restrict__ kh, const __half* __restrict__ vh,
    __half* __restrict__ cth, __half* __restrict__ ctl)
{
    extern __shared__ __align__(16) char smem[];
    const uint32_t sb = smem_u32(smem);
    const int tid = threadIdx.x, lane = tid & 31, wid = tid >> 5;
    const int wr = wid * 16;

    const int qt = blockIdx.x, h = blockIdx.y, b = blockIdx.z;
    const int q0 = qt * 128;
    const size_t hb = ((size_t)b * HH + h) * LL * HDIM;

    {
        const __half* srcs[2] = { qh + hb, ql + hb };
#pragma unroll
        for (int t = 0; t < 2; ++t)
#pragma unroll
            for (int i = 0; i < 8; ++i) {
                int f = tid + i * 256;
                int r = f >> 4, s = f & 15;
                CP_ASYNC16(sb + t * ATILE_Q + r * AROWSTR + s * 16,
                           srcs[t] + (size_t)(q0 + r) * HDIM + s * 8);
            }
        CP_COMMIT();
    }

#define LOAD_KV(kt_, buf_) do {                                                \
    const int k0_ = (kt_) * 64;                                                \
    const __half* srcs_[2] = { kh + hb, vh + hb };                             \
    _Pragma("unroll")                                                          \
    for (int t_ = 0; t_ < 2; ++t_)                                             \
        _Pragma("unroll")                                                      \
        for (int i_ = 0; i_ < 4; ++i_) {                                       \
            int f_ = tid + i_ * 256;                                           \
            int r_ = f_ >> 4, s_ = f_ & 15;                                    \
            CP_ASYNC16(sb + 2 * ATILE_Q + (2 * (buf_) + t_) * ATILE_KV         \
                          + r_ * AROWSTR + s_ * 16,                            \
                       srcs_[t_] + (size_t)(k0_ + r_) * HDIM + s_ * 8);        \
        }                                                                      \
    CP_COMMIT();                                                               \
} while (0)

    LOAD_KV(0, 0);

    float o[16][4];
#pragma unroll
    for (int i = 0; i < 16; ++i)
#pragma unroll
        for (int e = 0; e < 4; ++e) o[i][e] = 0.f;
    float m_i[2] = { -1e30f, -1e30f };
    float l_i[2] = { 0.f, 0.f };

    const uint32_t qa_off = (uint32_t)(wr + (lane & 15)) * AROWSTR + ((lane >> 4) << 4);
    const uint32_t kb_off = (uint32_t)(((lane >> 4) << 3) + (lane & 7)) * AROWSTR
                            + (((lane >> 3) & 1) << 4);
    const uint32_t vb_off = (uint32_t)(((lane >> 3) & 1) * 8 + (lane & 7)) * AROWSTR
                            + ((lane >> 4) << 4);

    const int ktmax = 2 * qt + 1;

#pragma unroll 1
    for (int kt = 0; kt <= ktmax; ++kt) {
        const int k0 = kt * 64;
        CP_WAIT0();           // tile kt landed
        __syncthreads();      // all warps done with tile kt-1; data visible
        if (kt + 1 <= ktmax) LOAD_KV(kt + 1, (kt + 1) & 1);   // overlaps compute

        const bool active = (k0 <= q0 + wr + 15);
        if (active) {
            const uint32_t kt_s = sb + 2 * ATILE_Q + (2 * (kt & 1)) * ATILE_KV;
            const uint32_t vt_s = kt_s + ATILE_KV;

            float s[8][4];
#pragma unroll
            for (int i = 0; i < 8; ++i)
#pragma unroll
                for (int e = 0; e < 4; ++e) s[i][e] = 0.f;

#pragma unroll
            for (int kk = 0; kk < 8; ++kk) {
                uint32_t qa_h[4], qa_l[4], kb_[4][4];
                LDSM4(qa_h, sb + 0 * ATILE_Q + qa_off + kk * 32);
                LDSM4(qa_l, sb + 1 * ATILE_Q + qa_off + kk * 32);
#pragma unroll
                for (int g = 0; g < 4; ++g)
                    LDSM4(kb_[g], kt_s + g * 16 * AROWSTR + kb_off + kk * 32);
#pragma unroll
                for (int g = 0; g < 4; ++g)
#pragma unroll
                    for (int jj = 0; jj < 2; ++jj)
                        MMA_F16(s[2 * g + jj], qa_h, kb_[g][jj * 2], kb_[g][jj * 2 + 1]);
#pragma unroll
                for (int g = 0; g < 4; ++g)
#pragma unroll
                    for (int jj = 0; jj < 2; ++jj)
                        MMA_F16(s[2 * g + jj], qa_l, kb_[g][jj * 2], kb_[g][jj * 2 + 1]);
            }

            const int r0g = q0 + wr + (lane >> 2);
            if (k0 + 63 > q0 + wr) {
#pragma unroll
                for (int nt = 0; nt < 8; ++nt) {
                    const int cg = k0 + nt * 8 + (lane & 3) * 2;
#pragma unroll
                    for (int e = 0; e < 4; ++e) {
                        const int rr = r0g + (e >> 1) * 8;
                        const int cc = cg + (e & 1);
                        if (cc > rr) s[nt][e] = -1e30f;
                    }
                }
            }

            float scl[2];
#pragma unroll
            for (int rh = 0; rh < 2; ++rh) {
                float mx = -1e30f;
#pragma unroll
                for (int nt = 0; nt < 8; ++nt)
                    mx = fmaxf(mx, fmaxf(s[nt][rh * 2], s[nt][rh * 2 + 1]));
                mx = fmaxf(mx, __shfl_xor_sync(0xffffffffu, mx, 1));
                mx = fmaxf(mx, __shfl_xor_sync(0xffffffffu, mx, 2));
                const float m_new = fmaxf(m_i[rh], mx);
                scl[rh] = __expf(m_i[rh] - m_new);
                float rs = 0.f;
#pragma unroll
                for (int nt = 0; nt < 8; ++nt) {
                    float p0 = __expf(s[nt][rh * 2] - m_new);
                    float p1 = __expf(s[nt][rh * 2 + 1] - m_new);
                    s[nt][rh * 2] = p0;
                    s[nt][rh * 2 + 1] = p1;
                    rs += p0 + p1;
                }
                rs += __shfl_xor_sync(0xffffffffu, rs, 1);
                rs += __shfl_xor_sync(0xffffffffu, rs, 2);
                l_i[rh] = l_i[rh] * scl[rh] + rs;
                m_i[rh] = m_new;
            }
#pragma unroll
            for (int i = 0; i < 16; ++i) {
                o[i][0] *= scl[0]; o[i][1] *= scl[0];
                o[i][2] *= scl[1]; o[i][3] *= scl[1];
            }

            uint32_t pa_h[4][4], pa_l[4][4];
#pragma unroll
            for (int kk = 0; kk < 4; ++kk) {
                const int t0 = 2 * kk, t1 = 2 * kk + 1;
                const float pv[8] = { s[t0][0], s[t0][1], s[t0][2], s[t0][3],
                                      s[t1][0], s[t1][1], s[t1][2], s[t1][3] };
                float ph[8], pr[8];
#pragma unroll
                for (int e = 0; e < 8; ++e) {
                    __half hh = __float2half_rn(pv[e]);
                    ph[e] = __half2float(hh);
                    pr[e] = pv[e] - ph[e];
                }
                pa_h[kk][0] = pack_h2(ph[0], ph[1]);
                pa_h[kk][1] = pack_h2(ph[2], ph[3]);
                pa_h[kk][2] = pack_h2(ph[4], ph[5]);
                pa_h[kk][3] = pack_h2(ph[6], ph[7]);
                pa_l[kk][0] = pack_h2(pr[0], pr[1]);
                pa_l[kk][1] = pack_h2(pr[2], pr[3]);
                pa_l[kk][2] = pack_h2(pr[4], pr[5]);
                pa_l[kk][3] = pack_h2(pr[6], pr[7]);
            }

#pragma unroll
            for (int g = 0; g < 8; ++g) {
                const int nt0 = 2 * g, nt1 = 2 * g + 1;
#pragma unroll
                for (int kk = 0; kk < 4; ++kk) {
                    uint32_t vb_[4];
                    LDSM4T(vb_, vt_s + (uint32_t)(kk * 16) * AROWSTR + g * 32 + vb_off);
                    MMA_F16(o[nt0], pa_h[kk], vb_[0], vb_[1]);
                    MMA_F16(o[nt1], pa_h[kk], vb_[2], vb_[3]);
                    MMA_F16(o[nt0], pa_l[kk], vb_[0], vb_[1]);
                    MMA_F16(o[nt1], pa_l[kk], vb_[2], vb_[3]);
                }
            }
        }
    }
#undef LOAD_KV

    const float inv0 = 1.0f / l_i[0];
    const float inv1 = 1.0f / l_i[1];
    const int rg0 = b * LL + q0 + wr + (lane >> 2);
    const int rg1 = rg0 + 8;
#pragma unroll
    for (int nt = 0; nt < 16; ++nt) {
        const int col = h * HDIM + nt * 8 + (lane & 3) * 2;
        {
            float vx = o[nt][0] * inv0, vy = o[nt][1] * inv0;
            __half hx = __float2half_rn(vx), hy = __float2half_rn(vy);
            float rx = vx - __half2float(hx), ry = vy - __half2float(hy);
            __half2 hp; hp.x = hx; hp.y = hy;
            size_t idx = (size_t)rg0 * DD + col;
            *(uint32_t*)(cth + idx) = *(uint32_t*)&hp;
            *(uint32_t*)(ctl + idx) = pack_h2(rx, ry);
        }
        {
            float vx = o[nt][2] * inv1, vy = o[nt][3] * inv1;
            __half hx = __float2half_rn(vx), hy = __float2half_rn(vy);
            float rx = vx - __half2float(hx), ry = vy - __half2float(hy);
            __half2 hp; hp.x = hx; hp.y = hy;
            size_t idx = (size_t)rg1 * DD + col;
            *(uint32_t*)(cth + idx) = *(uint32_t*)&hp;
            *(uint32_t*)(ctl + idx) = pack_h2(rx, ry);
        }
    }
}

// ---------------------------------------------------------------------------
// Launch.  d_out layout: [ out (B*L*D) | k (B*H*L*d) | v (B*H*L*d) ]
// ---------------------------------------------------------------------------
extern "C" void kernel_launch(void* const* d_in, const int* in_sizes, int n_in,
                              void* d_out, int out_size)
{
    const float* x  = (const float*)d_in[0];
    const float* Wq = (const float*)d_in[2];
    const float* bq = (const float*)d_in[3];
    const float* Wk = (const float*)d_in[4];
    const float* bk = (const float*)d_in[5];
    const float* Wv = (const float*)d_in[6];
    const float* bv = (const float*)d_in[7];
    const float* Wo = (const float*)d_in[8];
    const float* bo = (const float*)d_in[9];

    float* out_p = (float*)d_out;
    float* k_out = out_p + (size_t)BB * LL * DD;
    float* v_out = k_out + (size_t)BB * HH * LL * HDIM;

    __half *ah, *al, *btq, *btk, *btv, *bto, *qh, *ql, *kh, *vh;
    cudaGetSymbolAddress((void**)&ah, g_ah);
    cudaGetSymbolAddress((void**)&al, g_al);
    cudaGetSymbolAddress((void**)&btq, g_bq);
    cudaGetSymbolAddress((void**)&btk, g_bk);
    cudaGetSymbolAddress((void**)&btv, g_bv);
    cudaGetSymbolAddress((void**)&bto, g_bo);
    cudaGetSymbolAddress((void**)&qh, g_qh);
    cudaGetSymbolAddress((void**)&ql, g_ql);
    cudaGetSymbolAddress((void**)&kh, g_kh);
    cudaGetSymbolAddress((void**)&vh, g_vh);

    cudaFuncSetAttribute(gemm_mma_kernel, cudaFuncAttributeMaxDynamicSharedMemorySize, GEMM_SMEM);
    cudaFuncSetAttribute(attn_mma_kernel, cudaFuncAttributeMaxDynamicSharedMemorySize, ATT_SMEM);

    const int n4 = MM * DD / 4;
    const int cs_blocks = n4 / 256;
    dim3 tr_grid(DD / 32, DD / 32, 4);
    dim3 tr_block(32, 8);
    const int gemm_blocks = (MM / 128) * (DD / 128);   // 1024

    // upfront conversions
    conv_split_kernel<<<cs_blocks, 256>>>((const float4*)x, (h16x4*)ah, (h16x4*)al, n4);
    conv_tr4_kernel<<<tr_grid, tr_block>>>(Wq, Wk, Wv, Wo, btq, btk, btv, bto);

    // fused Q/K/V projections — one launch, merged tail waves
    GemmJob jq; jq.B = btq; jq.bias = bq; jq.out = nullptr; jq.oh = qh; jq.ol = ql;
    jq.scale = ATT_SCALE; jq.mode = 1;
    GemmJob jk; jk.B = btk; jk.bias = bk; jk.out = k_out; jk.oh = kh; jk.ol = nullptr;
    jk.scale = 1.0f; jk.mode = 2;
    GemmJob jv; jv.B = btv; jv.bias = bv; jv.out = v_out; jv.oh = vh; jv.ol = nullptr;
    jv.scale = 1.0f; jv.mode = 2;
    gemm_mma_kernel<<<dim3(gemm_blocks, 3), 128, GEMM_SMEM>>>(ah, al, jq, jk, jv);

    // attention -> ctx fp16 split into ah/al
    dim3 ag(LL / 128, HH, BB);
    attn_mma_kernel<<<ag, 256, ATT_SMEM>>>(qh, ql, kh, vh, ah, al);

    // output projection
    GemmJob jo; jo.B = bto; jo.bias = bo; jo.out = out_p; jo.oh = nullptr; jo.ol = nullptr;
    jo.scale = 1.0f; jo.mode = 0;
    gemm_mma_kernel<<<dim3(gemm_blocks, 1), 128, GEMM_SMEM>>>(ah, al, jo, jo, jo);
}

// round 11
// speedup vs baseline: 1.0429x; 1.0429x over previous
#include <cuda_runtime.h>
#include <cuda_fp16.h>
#include <math.h>
#include <stdint.h>

// Problem constants
#define BB 2
#define LL 2048
#define DD 4096
#define HH 32
#define HDIM 128
#define MM (BB*LL)          // 4096 rows
#define ATT_SCALE 0.08838834764831845f

// ---------------------------------------------------------------------------
// Scratch (allocation-free rule: __device__ globals)
// ---------------------------------------------------------------------------
__device__ __half g_ah[(size_t)MM*DD];       // A hi (x or ctx)
__device__ __half g_al[(size_t)MM*DD];       // A lo
__device__ __half g_bq[(size_t)DD*DD];       // Wq^T fp16 [N,K]
__device__ __half g_bk[(size_t)DD*DD];
__device__ __half g_bv[(size_t)DD*DD];
__device__ __half g_bo[(size_t)DD*DD];
__device__ __half g_qh[(size_t)MM*DD];       // q hi (scaled) [B,H,L,d]
__device__ __half g_ql[(size_t)MM*DD];       // q lo
__device__ __half g_kh[(size_t)MM*DD];       // k fp16
__device__ __half g_vh[(size_t)MM*DD];       // v fp16

__device__ __forceinline__ uint32_t smem_u32(const void* p) {
    uint32_t a;
    asm("{ .reg .u64 t; cvta.to.shared.u64 t, %1; cvt.u32.u64 %0, t; }"
        : "=r"(a) : "l"(p));
    return a;
}

#define LDSM4(r, addr) \
    asm volatile("ldmatrix.sync.aligned.m8n8.x4.shared.b16 {%0,%1,%2,%3}, [%4];" \
        : "=r"((r)[0]), "=r"((r)[1]), "=r"((r)[2]), "=r"((r)[3]) : "r"(addr))
#define LDSM4T(r, addr) \
    asm volatile("ldmatrix.sync.aligned.m8n8.x4.trans.shared.b16 {%0,%1,%2,%3}, [%4];" \
        : "=r"((r)[0]), "=r"((r)[1]), "=r"((r)[2]), "=r"((r)[3]) : "r"(addr))

#define MMA_F16(d, a, b0, b1) \
    asm volatile("mma.sync.aligned.m16n8k16.row.col.f32.f16.f16.f32 " \
        "{%0,%1,%2,%3}, {%4,%5,%6,%7}, {%8,%9}, {%0,%1,%2,%3};" \
        : "+f"((d)[0]), "+f"((d)[1]), "+f"((d)[2]), "+f"((d)[3]) \
        : "r"((a)[0]), "r"((a)[1]), "r"((a)[2]), "r"((a)[3]), "r"(b0), "r"(b1))

#define CP_ASYNC16(dst, src) \
    asm volatile("cp.async.cg.shared.global [%0], [%1], 16;" \
        :: "r"(dst), "l"(src) : "memory")
#define CP_COMMIT() asm volatile("cp.async.commit_group;" ::: "memory")
#define CP_WAIT1() asm volatile("cp.async.wait_group 1;" ::: "memory")
#define CP_WAIT0() asm volatile("cp.async.wait_group 0;" ::: "memory")

__device__ __forceinline__ uint32_t pack_h2(float x, float y) {
    __half2 t = __floats2half2_rn(x, y);
    return *(uint32_t*)&t;
}

// ---------------------------------------------------------------------------
// Conversion kernels
// ---------------------------------------------------------------------------
struct __align__(8) h16x4 { __half v[4]; };

__global__ __launch_bounds__(256) void conv_split_kernel(
    const float4* __restrict__ in, h16x4* __restrict__ oh, h16x4* __restrict__ ol, int n4)
{
    int i = blockIdx.x * 256 + threadIdx.x;
    if (i >= n4) return;
    float4 x = in[i];
    h16x4 h, l;
    h.v[0] = __float2half_rn(x.x); l.v[0] = __float2half_rn(x.x - __half2float(h.v[0]));
    h.v[1] = __float2half_rn(x.y); l.v[1] = __float2half_rn(x.y - __half2float(h.v[1]));
    h.v[2] = __float2half_rn(x.z); l.v[2] = __float2half_rn(x.z - __half2float(h.v[2]));
    h.v[3] = __float2half_rn(x.w); l.v[3] = __float2half_rn(x.w - __half2float(h.v[3]));
    oh[i] = h;
    ol[i] = l;
}

// 4 weight transposes fused: W [K,N] f32 -> Wt fp16 [N,K], blockIdx.z picks W.
__global__ __launch_bounds__(256) void conv_tr4_kernel(
    const float* __restrict__ W0, const float* __restrict__ W1,
    const float* __restrict__ W2, const float* __restrict__ W3,
    __half* __restrict__ T0, __half* __restrict__ T1,
    __half* __restrict__ T2, __half* __restrict__ T3)
{
    const float* W = (blockIdx.z == 0) ? W0 : (blockIdx.z == 1) ? W1
                    : (blockIdx.z == 2) ? W2 : W3;
    __half* Th = (blockIdx.z == 0) ? T0 : (blockIdx.z == 1) ? T1
                : (blockIdx.z == 2) ? T2 : T3;
    __shared__ float sm[32][33];
    const int k0 = blockIdx.x * 32, n0 = blockIdx.y * 32;
    const int tx = threadIdx.x, ty = threadIdx.y;     // (32, 8)
#pragma unroll
    for (int i = 0; i < 4; i++)
        sm[ty + 8 * i][tx] = W[(size_t)(k0 + ty + 8 * i) * DD + n0 + tx];
    __syncthreads();
#pragma unroll
    for (int i = 0; i < 4; i++) {
        float v = sm[tx][ty + 8 * i];
        Th[(size_t)(n0 + ty + 8 * i) * DD + k0 + tx] = __float2half_rn(v);
    }
}

// ---------------------------------------------------------------------------
// HMMA GEMM (R9-proven): CTA 128x128, 4 warps 2x2, warp tile 64x64,
// K-chunk 64, XOR-swizzled smem, 2 stages, 2 CTAs/SM, two-sync pipeline.
// out_mode 0: fp32 row-major; 1: fp16 hi/lo scaled head-split (Q);
// 2: fp32 head-split + fp16 head-split (K,V)
// ---------------------------------------------------------------------------
#define KCH 64
#define TILE_SZ 16384                     // 128 rows x 128 B
#define STAGE_BYTES (3 * TILE_SZ)         // 49152  (Ah, Al, B)
#define GEMM_SMEM (2 * STAGE_BYTES)       // 98304
#define NCHUNK (DD / KCH)                 // 64

__global__ __launch_bounds__(128, 2) void gemm_mma_kernel(
    const __half* __restrict__ Ah, const __half* __restrict__ Al,
    const __half* __restrict__ B,
    const float* __restrict__ bias, float* __restrict__ out,
    __half* __restrict__ oh, __half* __restrict__ ol,
    float scale, int out_mode)
{
    extern __shared__ __align__(16) char smem[];
    const uint32_t sb = smem_u32(smem);
    const int tid = threadIdx.x, lane = tid & 31, wid = tid >> 5;
    const int wm = wid >> 1;              // 0..1
    const int wn = wid & 1;               // 0..1
    // swizzled block mapping: groups of (32 m x 8 n)
    const int gid = blockIdx.x;
    const int m0 = (((gid & 255) >> 3)) * 128;
    const int n0 = (((gid >> 8) << 3) | (gid & 7)) * 128;

    const __half* gsrc[3];
    gsrc[0] = Ah + (size_t)m0 * DD;
    gsrc[1] = Al + (size_t)m0 * DD;
    gsrc[2] = B + (size_t)n0 * DD;

    float acc[4][8][4];
#pragma unroll
    for (int i = 0; i < 4; i++)
#pragma unroll
        for (int j = 0; j < 8; j++)
#pragma unroll
            for (int e = 0; e < 4; e++) acc[i][j][e] = 0.f;

    // per-lane LDSM addressing (swizzled): row stride 128B, granule ^= (row&7)
    const int rowA = wm * 64 + (lane & 15);       // +16*i
    const int a_half = lane >> 4;
    const int s_a = lane & 7;
    const int rowB = wn * 64 + ((lane >> 4) << 3) + (lane & 7);   // +16*j
    const int b_half = (lane >> 3) & 1;
    const int s_b = lane & 7;

#define LOAD_CHUNK(cc, st) do {                                                \
    const uint32_t stage_ = sb + (uint32_t)(st) * STAGE_BYTES;                 \
    _Pragma("unroll")                                                          \
    for (int t_ = 0; t_ < 3; ++t_) {                                           \
        const __half* gp_ = gsrc[t_] + (size_t)(cc) * KCH;                     \
        _Pragma("unroll")                                                      \
        for (int i_ = 0; i_ < 8; ++i_) {                                       \
            int f_ = tid + i_ * 128;              /* 0..1023 */                \
            int r_ = f_ >> 3, g_ = f_ & 7;                                     \
            const void* src_ = gp_ + (size_t)r_ * DD + g_ * 8;                 \
            uint32_t dst_ = stage_ + t_ * TILE_SZ + r_ * 128                   \
                            + ((g_ ^ (r_ & 7)) << 4);                          \
            CP_ASYNC16(dst_, src_);                                            \
        }                                                                      \
    }                                                                          \
    CP_COMMIT();                                                               \
} while (0)

    LOAD_CHUNK(0, 0);

#pragma unroll 1
    for (int c = 0; c < NCHUNK; ++c) {
        if (c + 1 < NCHUNK) {
            LOAD_CHUNK(c + 1, (c + 1) & 1);
            CP_WAIT1();
        } else {
            CP_WAIT0();
        }
        __syncthreads();

        const uint32_t stage = sb + (uint32_t)(c & 1) * STAGE_BYTES;

#pragma unroll
        for (int kk = 0; kk < 4; ++kk) {
            const uint32_t ga = (uint32_t)(((2 * kk + a_half) ^ s_a) << 4);
            const uint32_t gb = (uint32_t)(((2 * kk + b_half) ^ s_b) << 4);
            uint32_t ah_[4][4], al_[4][4], bf_[4][4];
#pragma unroll
            for (int i = 0; i < 4; ++i) {
                const uint32_t ra = (uint32_t)(rowA + i * 16) * 128 + ga;
                LDSM4(ah_[i], stage + ra);
                LDSM4(al_[i], stage + TILE_SZ + ra);
            }
#pragma unroll
            for (int j = 0; j < 4; ++j)
                LDSM4(bf_[j], stage + 2 * TILE_SZ
                              + (uint32_t)(rowB + j * 16) * 128 + gb);
#pragma unroll
            for (int i = 0; i < 4; ++i)
#pragma unroll
                for (int jn = 0; jn < 8; ++jn)
                    MMA_F16(acc[i][jn], ah_[i], bf_[jn >> 1][(jn & 1) * 2],
                            bf_[jn >> 1][(jn & 1) * 2 + 1]);
#pragma unroll
            for (int i = 0; i < 4; ++i)
#pragma unroll
                for (int jn = 0; jn < 8; ++jn)
                    MMA_F16(acc[i][jn], al_[i], bf_[jn >> 1][(jn & 1) * 2],
                            bf_[jn >> 1][(jn & 1) * 2 + 1]);
        }
        __syncthreads();
    }
#undef LOAD_CHUNK

    // epilogue
#pragma unroll
    for (int i = 0; i < 4; ++i) {
        const int r_lo = m0 + wm * 64 + i * 16 + (lane >> 2);
#pragma unroll
        for (int jn = 0; jn < 8; ++jn) {
            const int colg = n0 + wn * 64 + jn * 8 + (lane & 3) * 2;
            const float bv0 = bias[colg], bv1 = bias[colg + 1];
#pragma unroll
            for (int half_ = 0; half_ < 2; ++half_) {
                const int row = r_lo + half_ * 8;
                float vx = acc[i][jn][half_ * 2 + 0] + bv0;
                float vy = acc[i][jn][half_ * 2 + 1] + bv1;
                if (out_mode == 0) {
                    float2 v; v.x = vx; v.y = vy;
                    *(float2*)(out + (size_t)row * DD + colg) = v;
                } else {
                    int b_ = row >> 11, l_ = row & 2047, h_ = colg >> 7, dd = colg & 127;
                    size_t idx = ((((size_t)b_ * HH + h_) * LL + l_) * HDIM) + dd;
                    if (out_mode == 2) {
                        float2 v; v.x = vx; v.y = vy;
                        *(float2*)(out + idx) = v;
                        *(uint32_t*)(oh + idx) = pack_h2(vx, vy);
                    } else {
                        float sx = vx * scale, sy = vy * scale;
                        __half hx = __float2half_rn(sx), hy = __float2half_rn(sy);
                        float rx = sx - __half2float(hx), ry = sy - __half2float(hy);
                        __half2 hp; hp.x = hx; hp.y = hy;
                        *(uint32_t*)(oh + idx) = *(uint32_t*)&hp;
                        *(uint32_t*)(ol + idx) = pack_h2(rx, ry);
                    }
                }
            }
        }
    }
}

// ---------------------------------------------------------------------------
// Flash attention (causal), HMMA fp16 2-term. R9 structure, with PV MMAs
// reordered kk-outer / g-inner (two-phase hi/lo, V-frags cached) so each
// accumulator is reused at distance 16 MMAs instead of 2 (kills RAW stall).
// Grid (L/128, H, B), 256 threads (8 warps x 16 q-rows).
// ---------------------------------------------------------------------------
#define AROWSTR 272                        // 128 fp16 = 256 B + 16 pad
#define ATILE_Q (128 * AROWSTR)            // 34816
#define ATILE_KV (64 * AROWSTR)            // 17408
#define ATT_SMEM (2 * ATILE_Q + 4 * ATILE_KV)   // 139264

__global__ __launch_bounds__(256, 1) void attn_mma_kernel(
    const __half* __restrict__ qh, const __half* __restrict__ ql,
    const __half* __restrict__ kh, const __half* __restrict__ vh,
    __half* __restrict__ cth, __half* __restrict__ ctl)
{
    extern __shared__ __align__(16) char smem[];
    const uint32_t sb = smem_u32(smem);
    const int tid = threadIdx.x, lane = tid & 31, wid = tid >> 5;
    const int wr = wid * 16;

    const int qt = blockIdx.x, h = blockIdx.y, b = blockIdx.z;
    const int q0 = qt * 128;
    const size_t hb = ((size_t)b * HH + h) * LL * HDIM;

    {
        const __half* srcs[2] = { qh + hb, ql + hb };
#pragma unroll
        for (int t = 0; t < 2; ++t)
#pragma unroll
            for (int i = 0; i < 8; ++i) {
                int f = tid + i * 256;
                int r = f >> 4, s = f & 15;
                CP_ASYNC16(sb + t * ATILE_Q + r * AROWSTR + s * 16,
                           srcs[t] + (size_t)(q0 + r) * HDIM + s * 8);
            }
        CP_COMMIT();
    }

#define LOAD_KV(kt_, buf_) do {                                                \
    const int k0_ = (kt_) * 64;                                                \
    const __half* srcs_[2] = { kh + hb, vh + hb };                             \
    _Pragma("unroll")                                                          \
    for (int t_ = 0; t_ < 2; ++t_)                                             \
        _Pragma("unroll")                                                      \
        for (int i_ = 0; i_ < 4; ++i_) {                                       \
            int f_ = tid + i_ * 256;                                           \
            int r_ = f_ >> 4, s_ = f_ & 15;                                    \
            CP_ASYNC16(sb + 2 * ATILE_Q + (2 * (buf_) + t_) * ATILE_KV         \
                          + r_ * AROWSTR + s_ * 16,                            \
                       srcs_[t_] + (size_t)(k0_ + r_) * HDIM + s_ * 8);        \
        }                                                                      \
    CP_COMMIT();                                                               \
} while (0)

    LOAD_KV(0, 0);

    float o[16][4];
#pragma unroll
    for (int i = 0; i < 16; ++i)
#pragma unroll
        for (int e = 0; e < 4; ++e) o[i][e] = 0.f;
    float m_i[2] = { -1e30f, -1e30f };
    float l_i[2] = { 0.f, 0.f };

    const uint32_t qa_off = (uint32_t)(wr + (lane & 15)) * AROWSTR + ((lane >> 4) << 4);
    const uint32_t kb_off = (uint32_t)(((lane >> 4) << 3) + (lane & 7)) * AROWSTR
                            + (((lane >> 3) & 1) << 4);
    const uint32_t vb_off = (uint32_t)(((lane >> 3) & 1) * 8 + (lane & 7)) * AROWSTR
                            + ((lane >> 4) << 4);

    const int ktmax = 2 * qt + 1;

#pragma unroll 1
    for (int kt = 0; kt <= ktmax; ++kt) {
        const int k0 = kt * 64;
        __syncthreads();
        if (kt + 1 <= ktmax) {
            LOAD_KV(kt + 1, (kt + 1) & 1);
            CP_WAIT1();
        } else {
            CP_WAIT0();
        }
        __syncthreads();

        const bool active = (k0 <= q0 + wr + 15);
        if (active) {
            const uint32_t kt_s = sb + 2 * ATILE_Q + (2 * (kt & 1)) * ATILE_KV;
            const uint32_t vt_s = kt_s + ATILE_KV;

            float s[8][4];
#pragma unroll
            for (int i = 0; i < 8; ++i)
#pragma unroll
                for (int e = 0; e < 4; ++e) s[i][e] = 0.f;

#pragma unroll
            for (int kk = 0; kk < 8; ++kk) {
                uint32_t qa_h[4], qa_l[4], kb_[4][4];
                LDSM4(qa_h, sb + 0 * ATILE_Q + qa_off + kk * 32);
                LDSM4(qa_l, sb + 1 * ATILE_Q + qa_off + kk * 32);
#pragma unroll
                for (int g = 0; g < 4; ++g)
                    LDSM4(kb_[g], kt_s + g * 16 * AROWSTR + kb_off + kk * 32);
#pragma unroll
                for (int g = 0; g < 4; ++g)
#pragma unroll
                    for (int jj = 0; jj < 2; ++jj)
                        MMA_F16(s[2 * g + jj], qa_h, kb_[g][jj * 2], kb_[g][jj * 2 + 1]);
#pragma unroll
                for (int g = 0; g < 4; ++g)
#pragma unroll
                    for (int jj = 0; jj < 2; ++jj)
                        MMA_F16(s[2 * g + jj], qa_l, kb_[g][jj * 2], kb_[g][jj * 2 + 1]);
            }

            const int r0g = q0 + wr + (lane >> 2);
            if (k0 + 63 > q0 + wr) {
#pragma unroll
                for (int nt = 0; nt < 8; ++nt) {
                    const int cg = k0 + nt * 8 + (lane & 3) * 2;
#pragma unroll
                    for (int e = 0; e < 4; ++e) {
                        const int rr = r0g + (e >> 1) * 8;
                        const int cc = cg + (e & 1);
                        if (cc > rr) s[nt][e] = -1e30f;
                    }
                }
            }

            float scl[2];
#pragma unroll
            for (int rh = 0; rh < 2; ++rh) {
                float mx = -1e30f;
#pragma unroll
                for (int nt = 0; nt < 8; ++nt)
                    mx = fmaxf(mx, fmaxf(s[nt][rh * 2], s[nt][rh * 2 + 1]));
                mx = fmaxf(mx, __shfl_xor_sync(0xffffffffu, mx, 1));
                mx = fmaxf(mx, __shfl_xor_sync(0xffffffffu, mx, 2));
                const float m_new = fmaxf(m_i[rh], mx);
                scl[rh] = __expf(m_i[rh] - m_new);
                float rs = 0.f;
#pragma unroll
                for (int nt = 0; nt < 8; ++nt) {
                    float p0 = __expf(s[nt][rh * 2] - m_new);
                    float p1 = __expf(s[nt][rh * 2 + 1] - m_new);
                    s[nt][rh * 2] = p0;
                    s[nt][rh * 2 + 1] = p1;
                    rs += p0 + p1;
                }
                rs += __shfl_xor_sync(0xffffffffu, rs, 1);
                rs += __shfl_xor_sync(0xffffffffu, rs, 2);
                l_i[rh] = l_i[rh] * scl[rh] + rs;
                m_i[rh] = m_new;
            }
#pragma unroll
            for (int i = 0; i < 16; ++i) {
                o[i][0] *= scl[0]; o[i][1] *= scl[0];
                o[i][2] *= scl[1]; o[i][3] *= scl[1];
            }

            uint32_t pa_h[4][4], pa_l[4][4];
#pragma unroll
            for (int kk = 0; kk < 4; ++kk) {
                const int t0 = 2 * kk, t1 = 2 * kk + 1;
                const float pv[8] = { s[t0][0], s[t0][1], s[t0][2], s[t0][3],
                                      s[t1][0], s[t1][1], s[t1][2], s[t1][3] };
                float ph[8], pr[8];
#pragma unroll
                for (int e = 0; e < 8; ++e) {
                    __half hh = __float2half_rn(pv[e]);
                    ph[e] = __half2float(hh);
                    pr[e] = pv[e] - ph[e];
                }
                pa_h[kk][0] = pack_h2(ph[0], ph[1]);
                pa_h[kk][1] = pack_h2(ph[2], ph[3]);
                pa_h[kk][2] = pack_h2(ph[4], ph[5]);
                pa_h[kk][3] = pack_h2(ph[6], ph[7]);
                pa_l[kk][0] = pack_h2(pr[0], pr[1]);
                pa_l[kk][1] = pack_h2(pr[2], pr[3]);
                pa_l[kk][2] = pack_h2(pr[4], pr[5]);
                pa_l[kk][3] = pack_h2(pr[6], pr[7]);
            }

            // ---- O += P @ V, kk-outer: 16 accumulators round-robin ----
#pragma unroll
            for (int kk = 0; kk < 4; ++kk) {
                uint32_t vb_[8][4];
#pragma unroll
                for (int g = 0; g < 8; ++g)
                    LDSM4T(vb_[g], vt_s + (uint32_t)(kk * 16) * AROWSTR + g * 32 + vb_off);
#pragma unroll
                for (int g = 0; g < 8; ++g) {
                    MMA_F16(o[2 * g],     pa_h[kk], vb_[g][0], vb_[g][1]);
                    MMA_F16(o[2 * g + 1], pa_h[kk], vb_[g][2], vb_[g][3]);
                }
#pragma unroll
                for (int g = 0; g < 8; ++g) {
                    MMA_F16(o[2 * g],     pa_l[kk], vb_[g][0], vb_[g][1]);
                    MMA_F16(o[2 * g + 1], pa_l[kk], vb_[g][2], vb_[g][3]);
                }
            }
        }
    }
#undef LOAD_KV

    const float inv0 = 1.0f / l_i[0];
    const float inv1 = 1.0f / l_i[1];
    const int rg0 = b * LL + q0 + wr + (lane >> 2);
    const int rg1 = rg0 + 8;
#pragma unroll
    for (int nt = 0; nt < 16; ++nt) {
        const int col = h * HDIM + nt * 8 + (lane & 3) * 2;
        {
            float vx = o[nt][0] * inv0, vy = o[nt][1] * inv0;
            __half hx = __float2half_rn(vx), hy = __float2half_rn(vy);
            float rx = vx - __half2float(hx), ry = vy - __half2float(hy);
            __half2 hp; hp.x = hx; hp.y = hy;
            size_t idx = (size_t)rg0 * DD + col;
            *(uint32_t*)(cth + idx) = *(uint32_t*)&hp;
            *(uint32_t*)(ctl + idx) = pack_h2(rx, ry);
        }
        {
            float vx = o[nt][2] * inv1, vy = o[nt][3] * inv1;
            __half hx = __float2half_rn(vx), hy = __float2half_rn(vy);
            float rx = vx - __half2float(hx), ry = vy - __half2float(hy);
            __half2 hp; hp.x = hx; hp.y = hy;
            size_t idx = (size_t)rg1 * DD + col;
            *(uint32_t*)(cth + idx) = *(uint32_t*)&hp;
            *(uint32_t*)(ctl + idx) = pack_h2(rx, ry);
        }
    }
}

// ---------------------------------------------------------------------------
// Launch.  d_out layout: [ out (B*L*D) | k (B*H*L*d) | v (B*H*L*d) ]
// ---------------------------------------------------------------------------
extern "C" void kernel_launch(void* const* d_in, const int* in_sizes, int n_in,
                              void* d_out, int out_size)
{
    const float* x  = (const float*)d_in[0];
    const float* Wq = (const float*)d_in[2];
    const float* bq = (const float*)d_in[3];
    const float* Wk = (const float*)d_in[4];
    const float* bk = (const float*)d_in[5];
    const float* Wv = (const float*)d_in[6];
    const float* bv = (const float*)d_in[7];
    const float* Wo = (const float*)d_in[8];
    const float* bo = (const float*)d_in[9];

    float* out_p = (float*)d_out;
    float* k_out = out_p + (size_t)BB * LL * DD;
    float* v_out = k_out + (size_t)BB * HH * LL * HDIM;

    __half *ah, *al, *btq, *btk, *btv, *bto, *qh, *ql, *kh, *vh;
    cudaGetSymbolAddress((void**)&ah, g_ah);
    cudaGetSymbolAddress((void**)&al, g_al);
    cudaGetSymbolAddress((void**)&btq, g_bq);
    cudaGetSymbolAddress((void**)&btk, g_bk);
    cudaGetSymbolAddress((void**)&btv, g_bv);
    cudaGetSymbolAddress((void**)&bto, g_bo);
    cudaGetSymbolAddress((void**)&qh, g_qh);
    cudaGetSymbolAddress((void**)&ql, g_ql);
    cudaGetSymbolAddress((void**)&kh, g_kh);
    cudaGetSymbolAddress((void**)&vh, g_vh);

    cudaFuncSetAttribute(gemm_mma_kernel, cudaFuncAttributeMaxDynamicSharedMemorySize, GEMM_SMEM);
    cudaFuncSetAttribute(attn_mma_kernel, cudaFuncAttributeMaxDynamicSharedMemorySize, ATT_SMEM);

    const int n4 = MM * DD / 4;
    const int cs_blocks = n4 / 256;
    dim3 tr_grid(DD / 32, DD / 32, 4);
    dim3 tr_block(32, 8);
    const int gemm_blocks = (MM / 128) * (DD / 128);   // 1024

    // upfront conversions
    conv_split_kernel<<<cs_blocks, 256>>>((const float4*)x, (h16x4*)ah, (h16x4*)al, n4);
    conv_tr4_kernel<<<tr_grid, tr_block>>>(Wq, Wk, Wv, Wo, btq, btk, btv, bto);

    // projections (separate launches — R10 fused variant regressed via L2 thrash)
    gemm_mma_kernel<<<gemm_blocks, 128, GEMM_SMEM>>>(ah, al, btq, bq, nullptr, qh, ql, ATT_SCALE, 1);
    gemm_mma_kernel<<<gemm_blocks, 128, GEMM_SMEM>>>(ah, al, btk, bk, k_out, kh, nullptr, 1.0f, 2);
    gemm_mma_kernel<<<gemm_blocks, 128, GEMM_SMEM>>>(ah, al, btv, bv, v_out, vh, nullptr, 1.0f, 2);

    // attention -> ctx fp16 split into ah/al
    dim3 ag(LL / 128, HH, BB);
    attn_mma_kernel<<<ag, 256, ATT_SMEM>>>(qh, ql, kh, vh, ah, al);

    // output projection
    gemm_mma_kernel<<<gemm_blocks, 128, GEMM_SMEM>>>(ah, al, bto, bo, out_p, nullptr, nullptr, 1.0f, 0);
}

// round 12
// speedup vs baseline: 1.1105x; 1.0649x over previous
#include <cuda_runtime.h>
#include <cuda_fp16.h>
#include <math.h>
#include <stdint.h>

// Problem constants
#define BB 2
#define LL 2048
#define DD 4096
#define HH 32
#define HDIM 128
#define MM (BB*LL)          // 4096 rows
#define ATT_SCALE 0.08838834764831845f

// ---------------------------------------------------------------------------
// Scratch (allocation-free rule: __device__ globals)
// ---------------------------------------------------------------------------
__device__ __half g_ah[(size_t)MM*DD];       // A hi (x or ctx)
__device__ __half g_al[(size_t)MM*DD];       // A lo
__device__ __half g_bq[(size_t)DD*DD];       // Wq^T fp16 [N,K]
__device__ __half g_bk[(size_t)DD*DD];
__device__ __half g_bv[(size_t)DD*DD];
__device__ __half g_bo[(size_t)DD*DD];
__device__ __half g_qh[(size_t)MM*DD];       // q hi (scaled) [B,H,L,d]
__device__ __half g_ql[(size_t)MM*DD];       // q lo
__device__ __half g_kh[(size_t)MM*DD];       // k fp16
__device__ __half g_vh[(size_t)MM*DD];       // v fp16

__device__ __forceinline__ uint32_t smem_u32(const void* p) {
    uint32_t a;
    asm("{ .reg .u64 t; cvta.to.shared.u64 t, %1; cvt.u32.u64 %0, t; }"
        : "=r"(a) : "l"(p));
    return a;
}

#define LDSM4(r, addr) \
    asm volatile("ldmatrix.sync.aligned.m8n8.x4.shared.b16 {%0,%1,%2,%3}, [%4];" \
        : "=r"((r)[0]), "=r"((r)[1]), "=r"((r)[2]), "=r"((r)[3]) : "r"(addr))
#define LDSM4T(r, addr) \
    asm volatile("ldmatrix.sync.aligned.m8n8.x4.trans.shared.b16 {%0,%1,%2,%3}, [%4];" \
        : "=r"((r)[0]), "=r"((r)[1]), "=r"((r)[2]), "=r"((r)[3]) : "r"(addr))

#define MMA_F16(d, a, b0, b1) \
    asm volatile("mma.sync.aligned.m16n8k16.row.col.f32.f16.f16.f32 " \
        "{%0,%1,%2,%3}, {%4,%5,%6,%7}, {%8,%9}, {%0,%1,%2,%3};" \
        : "+f"((d)[0]), "+f"((d)[1]), "+f"((d)[2]), "+f"((d)[3]) \
        : "r"((a)[0]), "r"((a)[1]), "r"((a)[2]), "r"((a)[3]), "r"(b0), "r"(b1))

#define CP_ASYNC16(dst, src) \
    asm volatile("cp.async.cg.shared.global [%0], [%1], 16;" \
        :: "r"(dst), "l"(src) : "memory")
#define CP_COMMIT() asm volatile("cp.async.commit_group;" ::: "memory")
#define CP_WAIT1() asm volatile("cp.async.wait_group 1;" ::: "memory")
#define CP_WAIT0() asm volatile("cp.async.wait_group 0;" ::: "memory")

__device__ __forceinline__ uint32_t pack_h2(float x, float y) {
    __half2 t = __floats2half2_rn(x, y);
    return *(uint32_t*)&t;
}

// ---------------------------------------------------------------------------
// Conversion kernels
// ---------------------------------------------------------------------------
struct __align__(8) h16x4 { __half v[4]; };

__global__ __launch_bounds__(256) void conv_split_kernel(
    const float4* __restrict__ in, h16x4* __restrict__ oh, h16x4* __restrict__ ol, int n4)
{
    int i = blockIdx.x * 256 + threadIdx.x;
    if (i >= n4) return;
    float4 x = in[i];
    h16x4 h, l;
    h.v[0] = __float2half_rn(x.x); l.v[0] = __float2half_rn(x.x - __half2float(h.v[0]));
    h.v[1] = __float2half_rn(x.y); l.v[1] = __float2half_rn(x.y - __half2float(h.v[1]));
    h.v[2] = __float2half_rn(x.z); l.v[2] = __float2half_rn(x.z - __half2float(h.v[2]));
    h.v[3] = __float2half_rn(x.w); l.v[3] = __float2half_rn(x.w - __half2float(h.v[3]));
    oh[i] = h;
    ol[i] = l;
}

// 4 weight transposes fused: W [K,N] f32 -> Wt fp16 [N,K], blockIdx.z picks W.
__global__ __launch_bounds__(256) void conv_tr4_kernel(
    const float* __restrict__ W0, const float* __restrict__ W1,
    const float* __restrict__ W2, const float* __restrict__ W3,
    __half* __restrict__ T0, __half* __restrict__ T1,
    __half* __restrict__ T2, __half* __restrict__ T3)
{
    const float* W = (blockIdx.z == 0) ? W0 : (blockIdx.z == 1) ? W1
                    : (blockIdx.z == 2) ? W2 : W3;
    __half* Th = (blockIdx.z == 0) ? T0 : (blockIdx.z == 1) ? T1
                : (blockIdx.z == 2) ? T2 : T3;
    __shared__ float sm[32][33];
    const int k0 = blockIdx.x * 32, n0 = blockIdx.y * 32;
    const int tx = threadIdx.x, ty = threadIdx.y;     // (32, 8)
#pragma unroll
    for (int i = 0; i < 4; i++)
        sm[ty + 8 * i][tx] = W[(size_t)(k0 + ty + 8 * i) * DD + n0 + tx];
    __syncthreads();
#pragma unroll
    for (int i = 0; i < 4; i++) {
        float v = sm[tx][ty + 8 * i];
        Th[(size_t)(n0 + ty + 8 * i) * DD + k0 + tx] = __float2half_rn(v);
    }
}

// ---------------------------------------------------------------------------
// HMMA GEMM (R9-proven core): CTA 128x128, 4 warps 2x2, warp tile 64x64,
// K-chunk 64, XOR-swizzled smem, 2 stages, 2 CTAs/SM.
// Al == nullptr -> single-term A (skips lo tile loads + lo MMAs).
// out_mode 0: fp32 row-major; 1: fp16 hi/lo scaled head-split (Q);
// 2: fp32 head-split + fp16 head-split (K,V)
// ---------------------------------------------------------------------------
#define KCH 64
#define TILE_SZ 16384                     // 128 rows x 128 B
#define STAGE_BYTES (3 * TILE_SZ)         // 49152  (Ah, Al, B)
#define GEMM_SMEM (2 * STAGE_BYTES)       // 98304
#define NCHUNK (DD / KCH)                 // 64

__global__ __launch_bounds__(128, 2) void gemm_mma_kernel(
    const __half* __restrict__ Ah, const __half* __restrict__ Al,
    const __half* __restrict__ B,
    const float* __restrict__ bias, float* __restrict__ out,
    __half* __restrict__ oh, __half* __restrict__ ol,
    float scale, int out_mode)
{
    extern __shared__ __align__(16) char smem[];
    const uint32_t sb = smem_u32(smem);
    const int tid = threadIdx.x, lane = tid & 31, wid = tid >> 5;
    const int wm = wid >> 1;              // 0..1
    const int wn = wid & 1;               // 0..1
    const bool has_lo = (Al != nullptr);
    // swizzled block mapping: groups of (32 m x 8 n)
    const int gid = blockIdx.x;
    const int m0 = (((gid & 255) >> 3)) * 128;
    const int n0 = (((gid >> 8) << 3) | (gid & 7)) * 128;

    const __half* gsrc[3];
    gsrc[0] = Ah + (size_t)m0 * DD;
    gsrc[1] = has_lo ? (Al + (size_t)m0 * DD) : gsrc[0];
    gsrc[2] = B + (size_t)n0 * DD;

    float acc[4][8][4];
#pragma unroll
    for (int i = 0; i < 4; i++)
#pragma unroll
        for (int j = 0; j < 8; j++)
#pragma unroll
            for (int e = 0; e < 4; e++) acc[i][j][e] = 0.f;

    // per-lane LDSM addressing (swizzled): row stride 128B, granule ^= (row&7)
    const int rowA = wm * 64 + (lane & 15);       // +16*i
    const int a_half = lane >> 4;
    const int s_a = lane & 7;
    const int rowB = wn * 64 + ((lane >> 4) << 3) + (lane & 7);   // +16*j
    const int b_half = (lane >> 3) & 1;
    const int s_b = lane & 7;

#define LOAD_CHUNK(cc, st) do {                                                \
    const uint32_t stage_ = sb + (uint32_t)(st) * STAGE_BYTES;                 \
    _Pragma("unroll")                                                          \
    for (int t_ = 0; t_ < 3; ++t_) {                                           \
        if (t_ == 1 && !has_lo) continue;                                      \
        const __half* gp_ = gsrc[t_] + (size_t)(cc) * KCH;                     \
        _Pragma("unroll")                                                      \
        for (int i_ = 0; i_ < 8; ++i_) {                                       \
            int f_ = tid + i_ * 128;              /* 0..1023 */                \
            int r_ = f_ >> 3, g_ = f_ & 7;                                     \
            const void* src_ = gp_ + (size_t)r_ * DD + g_ * 8;                 \
            uint32_t dst_ = stage_ + t_ * TILE_SZ + r_ * 128                   \
                            + ((g_ ^ (r_ & 7)) << 4);                          \
            CP_ASYNC16(dst_, src_);                                            \
        }                                                                      \
    }                                                                          \
    CP_COMMIT();                                                               \
} while (0)

    LOAD_CHUNK(0, 0);

#pragma unroll 1
    for (int c = 0; c < NCHUNK; ++c) {
        if (c + 1 < NCHUNK) {
            LOAD_CHUNK(c + 1, (c + 1) & 1);
            CP_WAIT1();
        } else {
            CP_WAIT0();
        }
        __syncthreads();

        const uint32_t stage = sb + (uint32_t)(c & 1) * STAGE_BYTES;

#pragma unroll
        for (int kk = 0; kk < 4; ++kk) {
            const uint32_t ga = (uint32_t)(((2 * kk + a_half) ^ s_a) << 4);
            const uint32_t gb = (uint32_t)(((2 * kk + b_half) ^ s_b) << 4);
            uint32_t ah_[4][4], bf_[4][4];
#pragma unroll
            for (int i = 0; i < 4; ++i) {
                const uint32_t ra = (uint32_t)(rowA + i * 16) * 128 + ga;
                LDSM4(ah_[i], stage + ra);
            }
#pragma unroll
            for (int j = 0; j < 4; ++j)
                LDSM4(bf_[j], stage + 2 * TILE_SZ
                              + (uint32_t)(rowB + j * 16) * 128 + gb);
#pragma unroll
            for (int i = 0; i < 4; ++i)
#pragma unroll
                for (int jn = 0; jn < 8; ++jn)
                    MMA_F16(acc[i][jn], ah_[i], bf_[jn >> 1][(jn & 1) * 2],
                            bf_[jn >> 1][(jn & 1) * 2 + 1]);
            if (has_lo) {
                uint32_t al_[4][4];
#pragma unroll
                for (int i = 0; i < 4; ++i) {
                    const uint32_t ra = (uint32_t)(rowA + i * 16) * 128 + ga;
                    LDSM4(al_[i], stage + TILE_SZ + ra);
                }
#pragma unroll
                for (int i = 0; i < 4; ++i)
#pragma unroll
                    for (int jn = 0; jn < 8; ++jn)
                        MMA_F16(acc[i][jn], al_[i], bf_[jn >> 1][(jn & 1) * 2],
                                bf_[jn >> 1][(jn & 1) * 2 + 1]);
            }
        }
        __syncthreads();
    }
#undef LOAD_CHUNK

    // epilogue
#pragma unroll
    for (int i = 0; i < 4; ++i) {
        const int r_lo = m0 + wm * 64 + i * 16 + (lane >> 2);
#pragma unroll
        for (int jn = 0; jn < 8; ++jn) {
            const int colg = n0 + wn * 64 + jn * 8 + (lane & 3) * 2;
            const float bv0 = bias[colg], bv1 = bias[colg + 1];
#pragma unroll
            for (int half_ = 0; half_ < 2; ++half_) {
                const int row = r_lo + half_ * 8;
                float vx = acc[i][jn][half_ * 2 + 0] + bv0;
                float vy = acc[i][jn][half_ * 2 + 1] + bv1;
                if (out_mode == 0) {
                    float2 v; v.x = vx; v.y = vy;
                    *(float2*)(out + (size_t)row * DD + colg) = v;
                } else {
                    int b_ = row >> 11, l_ = row & 2047, h_ = colg >> 7, dd = colg & 127;
                    size_t idx = ((((size_t)b_ * HH + h_) * LL + l_) * HDIM) + dd;
                    if (out_mode == 2) {
                        float2 v; v.x = vx; v.y = vy;
                        *(float2*)(out + idx) = v;
                        *(uint32_t*)(oh + idx) = pack_h2(vx, vy);
                    } else {
                        float sx = vx * scale, sy = vy * scale;
                        __half hx = __float2half_rn(sx), hy = __float2half_rn(sy);
                        float rx = sx - __half2float(hx), ry = sy - __half2float(hy);
                        __half2 hp; hp.x = hx; hp.y = hy;
                        *(uint32_t*)(oh + idx) = *(uint32_t*)&hp;
                        *(uint32_t*)(ol + idx) = pack_h2(rx, ry);
                    }
                }
            }
        }
    }
}

// ---------------------------------------------------------------------------
// Flash attention (causal), HMMA fp16 2-term — R11 structure (PV kk-outer).
// Grid (L/128, H, B), 256 threads (8 warps x 16 q-rows).
// ---------------------------------------------------------------------------
#define AROWSTR 272                        // 128 fp16 = 256 B + 16 pad
#define ATILE_Q (128 * AROWSTR)            // 34816
#define ATILE_KV (64 * AROWSTR)            // 17408
#define ATT_SMEM (2 * ATILE_Q + 4 * ATILE_KV)   // 139264

__global__ __launch_bounds__(256, 1) void attn_mma_kernel(
    const __half* __restrict__ qh, const __half* __restrict__ ql,
    const __half* __restrict__ kh, const __half* __restrict__ vh,
    __half* __restrict__ cth, __half* __restrict__ ctl)
{
    extern __shared__ __align__(16) char smem[];
    const uint32_t sb = smem_u32(smem);
    const int tid = threadIdx.x, lane = tid & 31, wid = tid >> 5;
    const int wr = wid * 16;

    const int qt = blockIdx.x, h = blockIdx.y, b = blockIdx.z;
    const int q0 = qt * 128;
    const size_t hb = ((size_t)b * HH + h) * LL * HDIM;

    {
        const __half* srcs[2] = { qh + hb, ql + hb };
#pragma unroll
        for (int t = 0; t < 2; ++t)
#pragma unroll
            for (int i = 0; i < 8; ++i) {
                int f = tid + i * 256;
                int r = f >> 4, s = f & 15;
                CP_ASYNC16(sb + t * ATILE_Q + r * AROWSTR + s * 16,
                           srcs[t] + (size_t)(q0 + r) * HDIM + s * 8);
            }
        CP_COMMIT();
    }

#define LOAD_KV(kt_, buf_) do {                                                \
    const int k0_ = (kt_) * 64;                                                \
    const __half* srcs_[2] = { kh + hb, vh + hb };                             \
    _Pragma("unroll")                                                          \
    for (int t_ = 0; t_ < 2; ++t_)                                             \
        _Pragma("unroll")                                                      \
        for (int i_ = 0; i_ < 4; ++i_) {                                       \
            int f_ = tid + i_ * 256;                                           \
            int r_ = f_ >> 4, s_ = f_ & 15;                                    \
            CP_ASYNC16(sb + 2 * ATILE_Q + (2 * (buf_) + t_) * ATILE_KV         \
                          + r_ * AROWSTR + s_ * 16,                            \
                       srcs_[t_] + (size_t)(k0_ + r_) * HDIM + s_ * 8);        \
        }                                                                      \
    CP_COMMIT();                                                               \
} while (0)

    LOAD_KV(0, 0);

    float o[16][4];
#pragma unroll
    for (int i = 0; i < 16; ++i)
#pragma unroll
        for (int e = 0; e < 4; ++e) o[i][e] = 0.f;
    float m_i[2] = { -1e30f, -1e30f };
    float l_i[2] = { 0.f, 0.f };

    const uint32_t qa_off = (uint32_t)(wr + (lane & 15)) * AROWSTR + ((lane >> 4) << 4);
    const uint32_t kb_off = (uint32_t)(((lane >> 4) << 3) + (lane & 7)) * AROWSTR
                            + (((lane >> 3) & 1) << 4);
    const uint32_t vb_off = (uint32_t)(((lane >> 3) & 1) * 8 + (lane & 7)) * AROWSTR
                            + ((lane >> 4) << 4);

    const int ktmax = 2 * qt + 1;

#pragma unroll 1
    for (int kt = 0; kt <= ktmax; ++kt) {
        const int k0 = kt * 64;
        __syncthreads();
        if (kt + 1 <= ktmax) {
            LOAD_KV(kt + 1, (kt + 1) & 1);
            CP_WAIT1();
        } else {
            CP_WAIT0();
        }
        __syncthreads();

        const bool active = (k0 <= q0 + wr + 15);
        if (active) {
            const uint32_t kt_s = sb + 2 * ATILE_Q + (2 * (kt & 1)) * ATILE_KV;
            const uint32_t vt_s = kt_s + ATILE_KV;

            float s[8][4];
#pragma unroll
            for (int i = 0; i < 8; ++i)
#pragma unroll
                for (int e = 0; e < 4; ++e) s[i][e] = 0.f;

#pragma unroll
            for (int kk = 0; kk < 8; ++kk) {
                uint32_t qa_h[4], qa_l[4], kb_[4][4];
                LDSM4(qa_h, sb + 0 * ATILE_Q + qa_off + kk * 32);
                LDSM4(qa_l, sb + 1 * ATILE_Q + qa_off + kk * 32);
#pragma unroll
                for (int g = 0; g < 4; ++g)
                    LDSM4(kb_[g], kt_s + g * 16 * AROWSTR + kb_off + kk * 32);
#pragma unroll
                for (int g = 0; g < 4; ++g)
#pragma unroll
                    for (int jj = 0; jj < 2; ++jj)
                        MMA_F16(s[2 * g + jj], qa_h, kb_[g][jj * 2], kb_[g][jj * 2 + 1]);
#pragma unroll
                for (int g = 0; g < 4; ++g)
#pragma unroll
                    for (int jj = 0; jj < 2; ++jj)
                        MMA_F16(s[2 * g + jj], qa_l, kb_[g][jj * 2], kb_[g][jj * 2 + 1]);
            }

            const int r0g = q0 + wr + (lane >> 2);
            if (k0 + 63 > q0 + wr) {
#pragma unroll
                for (int nt = 0; nt < 8; ++nt) {
                    const int cg = k0 + nt * 8 + (lane & 3) * 2;
#pragma unroll
                    for (int e = 0; e < 4; ++e) {
                        const int rr = r0g + (e >> 1) * 8;
                        const int cc = cg + (e & 1);
                        if (cc > rr) s[nt][e] = -1e30f;
                    }
                }
            }

            float scl[2];
#pragma unroll
            for (int rh = 0; rh < 2; ++rh) {
                float mx = -1e30f;
#pragma unroll
                for (int nt = 0; nt < 8; ++nt)
                    mx = fmaxf(mx, fmaxf(s[nt][rh * 2], s[nt][rh * 2 + 1]));
                mx = fmaxf(mx, __shfl_xor_sync(0xffffffffu, mx, 1));
                mx = fmaxf(mx, __shfl_xor_sync(0xffffffffu, mx, 2));
                const float m_new = fmaxf(m_i[rh], mx);
                scl[rh] = __expf(m_i[rh] - m_new);
                float rs = 0.f;
#pragma unroll
                for (int nt = 0; nt < 8; ++nt) {
                    float p0 = __expf(s[nt][rh * 2] - m_new);
                    float p1 = __expf(s[nt][rh * 2 + 1] - m_new);
                    s[nt][rh * 2] = p0;
                    s[nt][rh * 2 + 1] = p1;
                    rs += p0 + p1;
                }
                rs += __shfl_xor_sync(0xffffffffu, rs, 1);
                rs += __shfl_xor_sync(0xffffffffu, rs, 2);
                l_i[rh] = l_i[rh] * scl[rh] + rs;
                m_i[rh] = m_new;
            }
#pragma unroll
            for (int i = 0; i < 16; ++i) {
                o[i][0] *= scl[0]; o[i][1] *= scl[0];
                o[i][2] *= scl[1]; o[i][3] *= scl[1];
            }

            uint32_t pa_h[4][4], pa_l[4][4];
#pragma unroll
            for (int kk = 0; kk < 4; ++kk) {
                const int t0 = 2 * kk, t1 = 2 * kk + 1;
                const float pv[8] = { s[t0][0], s[t0][1], s[t0][2], s[t0][3],
                                      s[t1][0], s[t1][1], s[t1][2], s[t1][3] };
                float ph[8], pr[8];
#pragma unroll
                for (int e = 0; e < 8; ++e) {
                    __half hh = __float2half_rn(pv[e]);
                    ph[e] = __half2float(hh);
                    pr[e] = pv[e] - ph[e];
                }
                pa_h[kk][0] = pack_h2(ph[0], ph[1]);
                pa_h[kk][1] = pack_h2(ph[2], ph[3]);
                pa_h[kk][2] = pack_h2(ph[4], ph[5]);
                pa_h[kk][3] = pack_h2(ph[6], ph[7]);
                pa_l[kk][0] = pack_h2(pr[0], pr[1]);
                pa_l[kk][1] = pack_h2(pr[2], pr[3]);
                pa_l[kk][2] = pack_h2(pr[4], pr[5]);
                pa_l[kk][3] = pack_h2(pr[6], pr[7]);
            }

            // ---- O += P @ V, kk-outer: 16 accumulators round-robin ----
#pragma unroll
            for (int kk = 0; kk < 4; ++kk) {
                uint32_t vb_[8][4];
#pragma unroll
                for (int g = 0; g < 8; ++g)
                    LDSM4T(vb_[g], vt_s + (uint32_t)(kk * 16) * AROWSTR + g * 32 + vb_off);
#pragma unroll
                for (int g = 0; g < 8; ++g) {
                    MMA_F16(o[2 * g],     pa_h[kk], vb_[g][0], vb_[g][1]);
                    MMA_F16(o[2 * g + 1], pa_h[kk], vb_[g][2], vb_[g][3]);
                }
#pragma unroll
                for (int g = 0; g < 8; ++g) {
                    MMA_F16(o[2 * g],     pa_l[kk], vb_[g][0], vb_[g][1]);
                    MMA_F16(o[2 * g + 1], pa_l[kk], vb_[g][2], vb_[g][3]);
                }
            }
        }
    }
#undef LOAD_KV

    const float inv0 = 1.0f / l_i[0];
    const float inv1 = 1.0f / l_i[1];
    const int rg0 = b * LL + q0 + wr + (lane >> 2);
    const int rg1 = rg0 + 8;
#pragma unroll
    for (int nt = 0; nt < 16; ++nt) {
        const int col = h * HDIM + nt * 8 + (lane & 3) * 2;
        {
            float vx = o[nt][0] * inv0, vy = o[nt][1] * inv0;
            __half hx = __float2half_rn(vx), hy = __float2half_rn(vy);
            float rx = vx - __half2float(hx), ry = vy - __half2float(hy);
            __half2 hp; hp.x = hx; hp.y = hy;
            size_t idx = (size_t)rg0 * DD + col;
            *(uint32_t*)(cth + idx) = *(uint32_t*)&hp;
            *(uint32_t*)(ctl + idx) = pack_h2(rx, ry);
        }
        {
            float vx = o[nt][2] * inv1, vy = o[nt][3] * inv1;
            __half hx = __float2half_rn(vx), hy = __float2half_rn(vy);
            float rx = vx - __half2float(hx), ry = vy - __half2float(hy);
            __half2 hp; hp.x = hx; hp.y = hy;
            size_t idx = (size_t)rg1 * DD + col;
            *(uint32_t*)(cth + idx) = *(uint32_t*)&hp;
            *(uint32_t*)(ctl + idx) = pack_h2(rx, ry);
        }
    }
}

// ---------------------------------------------------------------------------
// Launch.  d_out layout: [ out (B*L*D) | k (B*H*L*d) | v (B*H*L*d) ]
// ---------------------------------------------------------------------------
extern "C" void kernel_launch(void* const* d_in, const int* in_sizes, int n_in,
                              void* d_out, int out_size)
{
    const float* x  = (const float*)d_in[0];
    const float* Wq = (const float*)d_in[2];
    const float* bq = (const float*)d_in[3];
    const float* Wk = (const float*)d_in[4];
    const float* bk = (const float*)d_in[5];
    const float* Wv = (const float*)d_in[6];
    const float* bv = (const float*)d_in[7];
    const float* Wo = (const float*)d_in[8];
    const float* bo = (const float*)d_in[9];

    float* out_p = (float*)d_out;
    float* k_out = out_p + (size_t)BB * LL * DD;
    float* v_out = k_out + (size_t)BB * HH * LL * HDIM;

    __half *ah, *al, *btq, *btk, *btv, *bto, *qh, *ql, *kh, *vh;
    cudaGetSymbolAddress((void**)&ah, g_ah);
    cudaGetSymbolAddress((void**)&al, g_al);
    cudaGetSymbolAddress((void**)&btq, g_bq);
    cudaGetSymbolAddress((void**)&btk, g_bk);
    cudaGetSymbolAddress((void**)&btv, g_bv);
    cudaGetSymbolAddress((void**)&bto, g_bo);
    cudaGetSymbolAddress((void**)&qh, g_qh);
    cudaGetSymbolAddress((void**)&ql, g_ql);
    cudaGetSymbolAddress((void**)&kh, g_kh);
    cudaGetSymbolAddress((void**)&vh, g_vh);

    cudaFuncSetAttribute(gemm_mma_kernel, cudaFuncAttributeMaxDynamicSharedMemorySize, GEMM_SMEM);
    cudaFuncSetAttribute(attn_mma_kernel, cudaFuncAttributeMaxDynamicSharedMemorySize, ATT_SMEM);

    const int n4 = MM * DD / 4;
    const int cs_blocks = n4 / 256;
    dim3 tr_grid(DD / 32, DD / 32, 4);
    dim3 tr_block(32, 8);
    const int gemm_blocks = (MM / 128) * (DD / 128);   // 1024

    // upfront conversions
    conv_split_kernel<<<cs_blocks, 256>>>((const float4*)x, (h16x4*)ah, (h16x4*)al, n4);
    conv_tr4_kernel<<<tr_grid, tr_block>>>(Wq, Wk, Wv, Wo, btq, btk, btv, bto);

    // projections: Q full 2-term (accuracy-critical); K,V single-term
    // (attention consumes fp16 kh/vh regardless; k_out/v_out error ~4e-4).
    gemm_mma_kernel<<<gemm_blocks, 128, GEMM_SMEM>>>(ah, al, btq, bq, nullptr, qh, ql, ATT_SCALE, 1);
    gemm_mma_kernel<<<gemm_blocks, 128, GEMM_SMEM>>>(ah, nullptr, btk, bk, k_out, kh, nullptr, 1.0f, 2);
    gemm_mma_kernel<<<gemm_blocks, 128, GEMM_SMEM>>>(ah, nullptr, btv, bv, v_out, vh, nullptr, 1.0f, 2);

    // attention -> ctx fp16 split into ah/al
    dim3 ag(LL / 128, HH, BB);
    attn_mma_kernel<<<ag, 256, ATT_SMEM>>>(qh, ql, kh, vh, ah, al);

    // output projection (full 2-term)
    gemm_mma_kernel<<<gemm_blocks, 128, GEMM_SMEM>>>(ah, al, bto, bo, out_p, nullptr, nullptr, 1.0f, 0);
}

// round 13
// speedup vs baseline: 1.1144x; 1.0035x over previous
#include <cuda_runtime.h>
#include <cuda_fp16.h>
#include <math.h>
#include <stdint.h>

// Problem constants
#define BB 2
#define LL 2048
#define DD 4096
#define HH 32
#define HDIM 128
#define MM (BB*LL)          // 4096 rows
#define ATT_SCALE 0.08838834764831845f

// ---------------------------------------------------------------------------
// Scratch (allocation-free rule: __device__ globals)
// ---------------------------------------------------------------------------
__device__ __half g_ah[(size_t)MM*DD];       // A hi (x or ctx)
__device__ __half g_al[(size_t)MM*DD];       // A lo
__device__ __half g_bq[(size_t)DD*DD];       // Wq^T fp16 [N,K]
__device__ __half g_bk[(size_t)DD*DD];
__device__ __half g_bv[(size_t)DD*DD];
__device__ __half g_bo[(size_t)DD*DD];
__device__ __half g_qh[(size_t)MM*DD];       // q hi (scaled) [B,H,L,d]
__device__ __half g_ql[(size_t)MM*DD];       // q lo
__device__ __half g_kh[(size_t)MM*DD];       // k fp16
__device__ __half g_vh[(size_t)MM*DD];       // v fp16

__device__ __forceinline__ uint32_t smem_u32(const void* p) {
    uint32_t a;
    asm("{ .reg .u64 t; cvta.to.shared.u64 t, %1; cvt.u32.u64 %0, t; }"
        : "=r"(a) : "l"(p));
    return a;
}

#define LDSM4(r, addr) \
    asm volatile("ldmatrix.sync.aligned.m8n8.x4.shared.b16 {%0,%1,%2,%3}, [%4];" \
        : "=r"((r)[0]), "=r"((r)[1]), "=r"((r)[2]), "=r"((r)[3]) : "r"(addr))
#define LDSM4T(r, addr) \
    asm volatile("ldmatrix.sync.aligned.m8n8.x4.trans.shared.b16 {%0,%1,%2,%3}, [%4];" \
        : "=r"((r)[0]), "=r"((r)[1]), "=r"((r)[2]), "=r"((r)[3]) : "r"(addr))

#define MMA_F16(d, a, b0, b1) \
    asm volatile("mma.sync.aligned.m16n8k16.row.col.f32.f16.f16.f32 " \
        "{%0,%1,%2,%3}, {%4,%5,%6,%7}, {%8,%9}, {%0,%1,%2,%3};" \
        : "+f"((d)[0]), "+f"((d)[1]), "+f"((d)[2]), "+f"((d)[3]) \
        : "r"((a)[0]), "r"((a)[1]), "r"((a)[2]), "r"((a)[3]), "r"(b0), "r"(b1))

#define CP_ASYNC16(dst, src) \
    asm volatile("cp.async.cg.shared.global [%0], [%1], 16;" \
        :: "r"(dst), "l"(src) : "memory")
#define CP_COMMIT() asm volatile("cp.async.commit_group;" ::: "memory")
#define CP_WAIT1() asm volatile("cp.async.wait_group 1;" ::: "memory")
#define CP_WAIT0() asm volatile("cp.async.wait_group 0;" ::: "memory")

__device__ __forceinline__ uint32_t pack_h2(float x, float y) {
    __half2 t = __floats2half2_rn(x, y);
    return *(uint32_t*)&t;
}

// ---------------------------------------------------------------------------
// Conversion kernels
// ---------------------------------------------------------------------------
struct __align__(8) h16x4 { __half v[4]; };

__global__ __launch_bounds__(256) void conv_split_kernel(
    const float4* __restrict__ in, h16x4* __restrict__ oh, h16x4* __restrict__ ol, int n4)
{
    int i = blockIdx.x * 256 + threadIdx.x;
    if (i >= n4) return;
    float4 x = in[i];
    h16x4 h, l;
    h.v[0] = __float2half_rn(x.x); l.v[0] = __float2half_rn(x.x - __half2float(h.v[0]));
    h.v[1] = __float2half_rn(x.y); l.v[1] = __float2half_rn(x.y - __half2float(h.v[1]));
    h.v[2] = __float2half_rn(x.z); l.v[2] = __float2half_rn(x.z - __half2float(h.v[2]));
    h.v[3] = __float2half_rn(x.w); l.v[3] = __float2half_rn(x.w - __half2float(h.v[3]));
    oh[i] = h;
    ol[i] = l;
}

// 4 weight transposes fused: W [K,N] f32 -> Wt fp16 [N,K], blockIdx.z picks W.
__global__ __launch_bounds__(256) void conv_tr4_kernel(
    const float* __restrict__ W0, const float* __restrict__ W1,
    const float* __restrict__ W2, const float* __restrict__ W3,
    __half* __restrict__ T0, __half* __restrict__ T1,
    __half* __restrict__ T2, __half* __restrict__ T3)
{
    const float* W = (blockIdx.z == 0) ? W0 : (blockIdx.z == 1) ? W1
                    : (blockIdx.z == 2) ? W2 : W3;
    __half* Th = (blockIdx.z == 0) ? T0 : (blockIdx.z == 1) ? T1
                : (blockIdx.z == 2) ? T2 : T3;
    __shared__ float sm[32][33];
    const int k0 = blockIdx.x * 32, n0 = blockIdx.y * 32;
    const int tx = threadIdx.x, ty = threadIdx.y;     // (32, 8)
#pragma unroll
    for (int i = 0; i < 4; i++)
        sm[ty + 8 * i][tx] = W[(size_t)(k0 + ty + 8 * i) * DD + n0 + tx];
    __syncthreads();
#pragma unroll
    for (int i = 0; i < 4; i++) {
        float v = sm[tx][ty + 8 * i];
        Th[(size_t)(n0 + ty + 8 * i) * DD + k0 + tx] = __float2half_rn(v);
    }
}

// ---------------------------------------------------------------------------
// HMMA GEMM (R9-proven core): CTA 128x128, 4 warps 2x2, warp tile 64x64,
// K-chunk 64, XOR-swizzled smem, 2 stages, 2 CTAs/SM.
// Al == nullptr -> single-term A.
// out_mode 0: fp32 row-major; 1: fp16 hi/lo scaled head-split (Q);
// 2: fp32 head-split + fp16 head-split (K,V)
// ---------------------------------------------------------------------------
#define KCH 64
#define TILE_SZ 16384                     // 128 rows x 128 B
#define STAGE_BYTES (3 * TILE_SZ)         // 49152  (Ah, Al, B)
#define GEMM_SMEM (2 * STAGE_BYTES)       // 98304
#define NCHUNK (DD / KCH)                 // 64

__global__ __launch_bounds__(128, 2) void gemm_mma_kernel(
    const __half* __restrict__ Ah, const __half* __restrict__ Al,
    const __half* __restrict__ B,
    const float* __restrict__ bias, float* __restrict__ out,
    __half* __restrict__ oh, __half* __restrict__ ol,
    float scale, int out_mode)
{
    extern __shared__ __align__(16) char smem[];
    const uint32_t sb = smem_u32(smem);
    const int tid = threadIdx.x, lane = tid & 31, wid = tid >> 5;
    const int wm = wid >> 1;              // 0..1
    const int wn = wid & 1;               // 0..1
    const bool has_lo = (Al != nullptr);
    // swizzled block mapping: groups of (32 m x 8 n)
    const int gid = blockIdx.x;
    const int m0 = (((gid & 255) >> 3)) * 128;
    const int n0 = (((gid >> 8) << 3) | (gid & 7)) * 128;

    const __half* gsrc[3];
    gsrc[0] = Ah + (size_t)m0 * DD;
    gsrc[1] = has_lo ? (Al + (size_t)m0 * DD) : gsrc[0];
    gsrc[2] = B + (size_t)n0 * DD;

    float acc[4][8][4];
#pragma unroll
    for (int i = 0; i < 4; i++)
#pragma unroll
        for (int j = 0; j < 8; j++)
#pragma unroll
            for (int e = 0; e < 4; e++) acc[i][j][e] = 0.f;

    const int rowA = wm * 64 + (lane & 15);
    const int a_half = lane >> 4;
    const int s_a = lane & 7;
    const int rowB = wn * 64 + ((lane >> 4) << 3) + (lane & 7);
    const int b_half = (lane >> 3) & 1;
    const int s_b = lane & 7;

#define LOAD_CHUNK(cc, st) do {                                                \
    const uint32_t stage_ = sb + (uint32_t)(st) * STAGE_BYTES;                 \
    _Pragma("unroll")                                                          \
    for (int t_ = 0; t_ < 3; ++t_) {                                           \
        if (t_ == 1 && !has_lo) continue;                                      \
        const __half* gp_ = gsrc[t_] + (size_t)(cc) * KCH;                     \
        _Pragma("unroll")                                                      \
        for (int i_ = 0; i_ < 8; ++i_) {                                       \
            int f_ = tid + i_ * 128;              /* 0..1023 */                \
            int r_ = f_ >> 3, g_ = f_ & 7;                                     \
            const void* src_ = gp_ + (size_t)r_ * DD + g_ * 8;                 \
            uint32_t dst_ = stage_ + t_ * TILE_SZ + r_ * 128                   \
                            + ((g_ ^ (r_ & 7)) << 4);                          \
            CP_ASYNC16(dst_, src_);                                            \
        }                                                                      \
    }                                                                          \
    CP_COMMIT();                                                               \
} while (0)

    LOAD_CHUNK(0, 0);

#pragma unroll 1
    for (int c = 0; c < NCHUNK; ++c) {
        if (c + 1 < NCHUNK) {
            LOAD_CHUNK(c + 1, (c + 1) & 1);
            CP_WAIT1();
        } else {
            CP_WAIT0();
        }
        __syncthreads();

        const uint32_t stage = sb + (uint32_t)(c & 1) * STAGE_BYTES;

#pragma unroll
        for (int kk = 0; kk < 4; ++kk) {
            const uint32_t ga = (uint32_t)(((2 * kk + a_half) ^ s_a) << 4);
            const uint32_t gb = (uint32_t)(((2 * kk + b_half) ^ s_b) << 4);
            uint32_t ah_[4][4], bf_[4][4];
#pragma unroll
            for (int i = 0; i < 4; ++i) {
                const uint32_t ra = (uint32_t)(rowA + i * 16) * 128 + ga;
                LDSM4(ah_[i], stage + ra);
            }
#pragma unroll
            for (int j = 0; j < 4; ++j)
                LDSM4(bf_[j], stage + 2 * TILE_SZ
                              + (uint32_t)(rowB + j * 16) * 128 + gb);
#pragma unroll
            for (int i = 0; i < 4; ++i)
#pragma unroll
                for (int jn = 0; jn < 8; ++jn)
                    MMA_F16(acc[i][jn], ah_[i], bf_[jn >> 1][(jn & 1) * 2],
                            bf_[jn >> 1][(jn & 1) * 2 + 1]);
            if (has_lo) {
                uint32_t al_[4][4];
#pragma unroll
                for (int i = 0; i < 4; ++i) {
                    const uint32_t ra = (uint32_t)(rowA + i * 16) * 128 + ga;
                    LDSM4(al_[i], stage + TILE_SZ + ra);
                }
#pragma unroll
                for (int i = 0; i < 4; ++i)
#pragma unroll
                    for (int jn = 0; jn < 8; ++jn)
                        MMA_F16(acc[i][jn], al_[i], bf_[jn >> 1][(jn & 1) * 2],
                                bf_[jn >> 1][(jn & 1) * 2 + 1]);
            }
        }
        __syncthreads();
    }
#undef LOAD_CHUNK

    // epilogue
#pragma unroll
    for (int i = 0; i < 4; ++i) {
        const int r_lo = m0 + wm * 64 + i * 16 + (lane >> 2);
#pragma unroll
        for (int jn = 0; jn < 8; ++jn) {
            const int colg = n0 + wn * 64 + jn * 8 + (lane & 3) * 2;
            const float bv0 = bias[colg], bv1 = bias[colg + 1];
#pragma unroll
            for (int half_ = 0; half_ < 2; ++half_) {
                const int row = r_lo + half_ * 8;
                float vx = acc[i][jn][half_ * 2 + 0] + bv0;
                float vy = acc[i][jn][half_ * 2 + 1] + bv1;
                if (out_mode == 0) {
                    float2 v; v.x = vx; v.y = vy;
                    *(float2*)(out + (size_t)row * DD + colg) = v;
                } else {
                    int b_ = row >> 11, l_ = row & 2047, h_ = colg >> 7, dd = colg & 127;
                    size_t idx = ((((size_t)b_ * HH + h_) * LL + l_) * HDIM) + dd;
                    if (out_mode == 2) {
                        float2 v; v.x = vx; v.y = vy;
                        *(float2*)(out + idx) = v;
                        *(uint32_t*)(oh + idx) = pack_h2(vx, vy);
                    } else {
                        float sx = vx * scale, sy = vy * scale;
                        __half hx = __float2half_rn(sx), hy = __float2half_rn(sy);
                        float rx = sx - __half2float(hx), ry = sy - __half2float(hy);
                        __half2 hp; hp.x = hx; hp.y = hy;
                        *(uint32_t*)(oh + idx) = *(uint32_t*)&hp;
                        *(uint32_t*)(ol + idx) = pack_h2(rx, ry);
                    }
                }
            }
        }
    }
}

// ---------------------------------------------------------------------------
// Flash attention (causal), HMMA fp16 2-term.
// KV processed in PAIRS of 64-row tiles (128 cols/iter): halves barriers,
// softmax passes, and o-rescales. Double-buffered pairs (8 KV tiles).
// Grid (L/128, H, B), 256 threads (8 warps x 16 q-rows).
// ---------------------------------------------------------------------------
#define AROWSTR 272                        // 128 fp16 = 256 B + 16 pad
#define ATILE_Q (128 * AROWSTR)            // 34816
#define ATILE_KV (64 * AROWSTR)            // 17408
#define ATT_SMEM (2 * ATILE_Q + 8 * ATILE_KV)   // 208896

__global__ __launch_bounds__(256, 1) void attn_mma_kernel(
    const __half* __restrict__ qh, const __half* __restrict__ ql,
    const __half* __restrict__ kh, const __half* __restrict__ vh,
    __half* __restrict__ cth, __half* __restrict__ ctl)
{
    extern __shared__ __align__(16) char smem[];
    const uint32_t sb = smem_u32(smem);
    const int tid = threadIdx.x, lane = tid & 31, wid = tid >> 5;
    const int wr = wid * 16;

    const int qt = blockIdx.x, h = blockIdx.y, b = blockIdx.z;
    const int q0 = qt * 128;
    const size_t hb = ((size_t)b * HH + h) * LL * HDIM;

    {
        const __half* srcs[2] = { qh + hb, ql + hb };
#pragma unroll
        for (int t = 0; t < 2; ++t)
#pragma unroll
            for (int i = 0; i < 8; ++i) {
                int f = tid + i * 256;
                int r = f >> 4, s = f & 15;
                CP_ASYNC16(sb + t * ATILE_Q + r * AROWSTR + s * 16,
                           srcs[t] + (size_t)(q0 + r) * HDIM + s * 8);
            }
        CP_COMMIT();
    }

    // Pair buffers: pair p at 2*ATILE_Q + p*4*ATILE_KV: [K0, V0, K1, V1]
#define LOAD_KVPAIR(it_, p_) do {                                              \
    _Pragma("unroll")                                                          \
    for (int t_ = 0; t_ < 4; ++t_) {                                           \
        const __half* src_ = (t_ & 1) ? (vh + hb) : (kh + hb);                 \
        const int k0_ = ((it_) * 2 + (t_ >> 1)) * 64;                          \
        const uint32_t base_ = sb + 2 * ATILE_Q + (p_) * 4 * ATILE_KV          \
                               + t_ * ATILE_KV;                                \
        _Pragma("unroll")                                                      \
        for (int i_ = 0; i_ < 4; ++i_) {                                       \
            int f_ = tid + i_ * 256;                                           \
            int r_ = f_ >> 4, s_ = f_ & 15;                                    \
            CP_ASYNC16(base_ + r_ * AROWSTR + s_ * 16,                         \
                       src_ + (size_t)(k0_ + r_) * HDIM + s_ * 8);             \
        }                                                                      \
    }                                                                          \
    CP_COMMIT();                                                               \
} while (0)

    LOAD_KVPAIR(0, 0);

    float o[16][4];
#pragma unroll
    for (int i = 0; i < 16; ++i)
#pragma unroll
        for (int e = 0; e < 4; ++e) o[i][e] = 0.f;
    float m_i[2] = { -1e30f, -1e30f };
    float l_i[2] = { 0.f, 0.f };

    const uint32_t qa_off = (uint32_t)(wr + (lane & 15)) * AROWSTR + ((lane >> 4) << 4);
    const uint32_t kb_off = (uint32_t)(((lane >> 4) << 3) + (lane & 7)) * AROWSTR
                            + (((lane >> 3) & 1) << 4);
    const uint32_t vb_off = (uint32_t)(((lane >> 3) & 1) * 8 + (lane & 7)) * AROWSTR
                            + ((lane >> 4) << 4);

    const int nit = qt + 1;               // pairs of 64-tiles (always even count)

#pragma unroll 1
    for (int it = 0; it < nit; ++it) {
        const int k0 = it * 128;
        __syncthreads();
        if (it + 1 < nit) {
            LOAD_KVPAIR(it + 1, (it + 1) & 1);
            CP_WAIT1();
        } else {
            CP_WAIT0();
        }
        __syncthreads();

        const bool active = (k0 <= q0 + wr + 15);
        if (active) {
            const uint32_t pairb = sb + 2 * ATILE_Q + (uint32_t)(it & 1) * 4 * ATILE_KV;
            const uint32_t k_s0 = pairb;
            const uint32_t v_s0 = pairb + ATILE_KV;
            const uint32_t k_s1 = pairb + 2 * ATILE_KV;
            const uint32_t v_s1 = pairb + 3 * ATILE_KV;

            float s[16][4];
#pragma unroll
            for (int i = 0; i < 16; ++i)
#pragma unroll
                for (int e = 0; e < 4; ++e) s[i][e] = 0.f;

            // ---- S = Q @ K^T over 128 cols (2-term) ----
#pragma unroll
            for (int kk = 0; kk < 8; ++kk) {
                uint32_t qa_h[4], qa_l[4], kb_[8][4];
                LDSM4(qa_h, sb + 0 * ATILE_Q + qa_off + kk * 32);
                LDSM4(qa_l, sb + 1 * ATILE_Q + qa_off + kk * 32);
#pragma unroll
                for (int g = 0; g < 4; ++g) {
                    LDSM4(kb_[g],     k_s0 + g * 16 * AROWSTR + kb_off + kk * 32);
                    LDSM4(kb_[4 + g], k_s1 + g * 16 * AROWSTR + kb_off + kk * 32);
                }
#pragma unroll
                for (int g = 0; g < 8; ++g)
#pragma unroll
                    for (int jj = 0; jj < 2; ++jj)
                        MMA_F16(s[2 * g + jj], qa_h, kb_[g][jj * 2], kb_[g][jj * 2 + 1]);
#pragma unroll
                for (int g = 0; g < 8; ++g)
#pragma unroll
                    for (int jj = 0; jj < 2; ++jj)
                        MMA_F16(s[2 * g + jj], qa_l, kb_[g][jj * 2], kb_[g][jj * 2 + 1]);
            }

            // ---- causal mask ----
            const int r0g = q0 + wr + (lane >> 2);
            if (k0 + 127 > q0 + wr) {
#pragma unroll
                for (int nt = 0; nt < 16; ++nt) {
                    const int cg = k0 + nt * 8 + (lane & 3) * 2;
#pragma unroll
                    for (int e = 0; e < 4; ++e) {
                        const int rr = r0g + (e >> 1) * 8;
                        const int cc = cg + (e & 1);
                        if (cc > rr) s[nt][e] = -1e30f;
                    }
                }
            }

            // ---- online softmax over 128 cols ----
            float scl[2];
#pragma unroll
            for (int rh = 0; rh < 2; ++rh) {
                float mx = -1e30f;
#pragma unroll
                for (int nt = 0; nt < 16; ++nt)
                    mx = fmaxf(mx, fmaxf(s[nt][rh * 2], s[nt][rh * 2 + 1]));
                mx = fmaxf(mx, __shfl_xor_sync(0xffffffffu, mx, 1));
                mx = fmaxf(mx, __shfl_xor_sync(0xffffffffu, mx, 2));
                const float m_new = fmaxf(m_i[rh], mx);
                scl[rh] = __expf(m_i[rh] - m_new);
                float rs = 0.f;
#pragma unroll
                for (int nt = 0; nt < 16; ++nt) {
                    float p0 = __expf(s[nt][rh * 2] - m_new);
                    float p1 = __expf(s[nt][rh * 2 + 1] - m_new);
                    s[nt][rh * 2] = p0;
                    s[nt][rh * 2 + 1] = p1;
                    rs += p0 + p1;
                }
                rs += __shfl_xor_sync(0xffffffffu, rs, 1);
                rs += __shfl_xor_sync(0xffffffffu, rs, 2);
                l_i[rh] = l_i[rh] * scl[rh] + rs;
                m_i[rh] = m_new;
            }
#pragma unroll
            for (int i = 0; i < 16; ++i) {
                o[i][0] *= scl[0]; o[i][1] *= scl[0];
                o[i][2] *= scl[1]; o[i][3] *= scl[1];
            }

            // ---- split P into fp16 hi/lo A-fragments (8 k16 groups) ----
            uint32_t pa_h[8][4], pa_l[8][4];
#pragma unroll
            for (int kk = 0; kk < 8; ++kk) {
                const int t0 = 2 * kk, t1 = 2 * kk + 1;
                const float pv[8] = { s[t0][0], s[t0][1], s[t0][2], s[t0][3],
                                      s[t1][0], s[t1][1], s[t1][2], s[t1][3] };
                float ph[8], pr[8];
#pragma unroll
                for (int e = 0; e < 8; ++e) {
                    __half hh = __float2half_rn(pv[e]);
                    ph[e] = __half2float(hh);
                    pr[e] = pv[e] - ph[e];
                }
                pa_h[kk][0] = pack_h2(ph[0], ph[1]);
                pa_h[kk][1] = pack_h2(ph[2], ph[3]);
                pa_h[kk][2] = pack_h2(ph[4], ph[5]);
                pa_h[kk][3] = pack_h2(ph[6], ph[7]);
                pa_l[kk][0] = pack_h2(pr[0], pr[1]);
                pa_l[kk][1] = pack_h2(pr[2], pr[3]);
                pa_l[kk][2] = pack_h2(pr[4], pr[5]);
                pa_l[kk][3] = pack_h2(pr[6], pr[7]);
            }

            // ---- O += P @ V over 128 contraction cols, kk-outer ----
#pragma unroll
            for (int kk = 0; kk < 8; ++kk) {
                const uint32_t vsrc = (kk < 4) ? v_s0 : v_s1;
                const uint32_t vrow = (uint32_t)((kk & 3) * 16) * AROWSTR;
                uint32_t vb_[8][4];
#pragma unroll
                for (int g = 0; g < 8; ++g)
                    LDSM4T(vb_[g], vsrc + vrow + g * 32 + vb_off);
#pragma unroll
                for (int g = 0; g < 8; ++g) {
                    MMA_F16(o[2 * g],     pa_h[kk], vb_[g][0], vb_[g][1]);
                    MMA_F16(o[2 * g + 1], pa_h[kk], vb_[g][2], vb_[g][3]);
                }
#pragma unroll
                for (int g = 0; g < 8; ++g) {
                    MMA_F16(o[2 * g],     pa_l[kk], vb_[g][0], vb_[g][1]);
                    MMA_F16(o[2 * g + 1], pa_l[kk], vb_[g][2], vb_[g][3]);
                }
            }
        }
    }
#undef LOAD_KVPAIR

    const float inv0 = 1.0f / l_i[0];
    const float inv1 = 1.0f / l_i[1];
    const int rg0 = b * LL + q0 + wr + (lane >> 2);
    const int rg1 = rg0 + 8;
#pragma unroll
    for (int nt = 0; nt < 16; ++nt) {
        const int col = h * HDIM + nt * 8 + (lane & 3) * 2;
        {
            float vx = o[nt][0] * inv0, vy = o[nt][1] * inv0;
            __half hx = __float2half_rn(vx), hy = __float2half_rn(vy);
            float rx = vx - __half2float(hx), ry = vy - __half2float(hy);
            __half2 hp; hp.x = hx; hp.y = hy;
            size_t idx = (size_t)rg0 * DD + col;
            *(uint32_t*)(cth + idx) = *(uint32_t*)&hp;
            *(uint32_t*)(ctl + idx) = pack_h2(rx, ry);
        }
        {
            float vx = o[nt][2] * inv1, vy = o[nt][3] * inv1;
            __half hx = __float2half_rn(vx), hy = __float2half_rn(vy);
            float rx = vx - __half2float(hx), ry = vy - __half2float(hy);
            __half2 hp; hp.x = hx; hp.y = hy;
            size_t idx = (size_t)rg1 * DD + col;
            *(uint32_t*)(cth + idx) = *(uint32_t*)&hp;
            *(uint32_t*)(ctl + idx) = pack_h2(rx, ry);
        }
    }
}

// ---------------------------------------------------------------------------
// Launch.  d_out layout: [ out (B*L*D) | k (B*H*L*d) | v (B*H*L*d) ]
// ---------------------------------------------------------------------------
extern "C" void kernel_launch(void* const* d_in, const int* in_sizes, int n_in,
                              void* d_out, int out_size)
{
    const float* x  = (const float*)d_in[0];
    const float* Wq = (const float*)d_in[2];
    const float* bq = (const float*)d_in[3];
    const float* Wk = (const float*)d_in[4];
    const float* bk = (const float*)d_in[5];
    const float* Wv = (const float*)d_in[6];
    const float* bv = (const float*)d_in[7];
    const float* Wo = (const float*)d_in[8];
    const float* bo = (const float*)d_in[9];

    float* out_p = (float*)d_out;
    float* k_out = out_p + (size_t)BB * LL * DD;
    float* v_out = k_out + (size_t)BB * HH * LL * HDIM;

    __half *ah, *al, *btq, *btk, *btv, *bto, *qh, *ql, *kh, *vh;
    cudaGetSymbolAddress((void**)&ah, g_ah);
    cudaGetSymbolAddress((void**)&al, g_al);
    cudaGetSymbolAddress((void**)&btq, g_bq);
    cudaGetSymbolAddress((void**)&btk, g_bk);
    cudaGetSymbolAddress((void**)&btv, g_bv);
    cudaGetSymbolAddress((void**)&bto, g_bo);
    cudaGetSymbolAddress((void**)&qh, g_qh);
    cudaGetSymbolAddress((void**)&ql, g_ql);
    cudaGetSymbolAddress((void**)&kh, g_kh);
    cudaGetSymbolAddress((void**)&vh, g_vh);

    cudaFuncSetAttribute(gemm_mma_kernel, cudaFuncAttributeMaxDynamicSharedMemorySize, GEMM_SMEM);
    cudaFuncSetAttribute(attn_mma_kernel, cudaFuncAttributeMaxDynamicSharedMemorySize, ATT_SMEM);

    const int n4 = MM * DD / 4;
    const int cs_blocks = n4 / 256;
    dim3 tr_grid(DD / 32, DD / 32, 4);
    dim3 tr_block(32, 8);
    const int gemm_blocks = (MM / 128) * (DD / 128);   // 1024

    // upfront conversions
    conv_split_kernel<<<cs_blocks, 256>>>((const float4*)x, (h16x4*)ah, (h16x4*)al, n4);
    conv_tr4_kernel<<<tr_grid, tr_block>>>(Wq, Wk, Wv, Wo, btq, btk, btv, bto);

    // projections: Q full 2-term; K,V single-term
    gemm_mma_kernel<<<gemm_blocks, 128, GEMM_SMEM>>>(ah, al, btq, bq, nullptr, qh, ql, ATT_SCALE, 1);
    gemm_mma_kernel<<<gemm_blocks, 128, GEMM_SMEM>>>(ah, nullptr, btk, bk, k_out, kh, nullptr, 1.0f, 2);
    gemm_mma_kernel<<<gemm_blocks, 128, GEMM_SMEM>>>(ah, nullptr, btv, bv, v_out, vh, nullptr, 1.0f, 2);

    // attention -> ctx fp16 split into ah/al
    dim3 ag(LL / 128, HH, BB);
    attn_mma_kernel<<<ag, 256, ATT_SMEM>>>(qh, ql, kh, vh, ah, al);

    // output projection (full 2-term)
    gemm_mma_kernel<<<gemm_blocks, 128, GEMM_SMEM>>>(ah, al, bto, bo, out_p, nullptr, nullptr, 1.0f, 0);
}

// round 14
// speedup vs baseline: 1.2224x; 1.0969x over previous
#include <cuda_runtime.h>
#include <cuda_fp16.h>
#include <math.h>
#include <stdint.h>

// Problem constants
#define BB 2
#define LL 2048
#define DD 4096
#define HH 32
#define HDIM 128
#define MM (BB*LL)          // 4096 rows
#define ATT_SCALE 0.08838834764831845f

// ---------------------------------------------------------------------------
// Scratch (allocation-free rule: __device__ globals)
// ---------------------------------------------------------------------------
__device__ __half g_ah[(size_t)MM*DD];       // A hi (x or ctx)
__device__ __half g_al[(size_t)MM*DD];       // A lo
__device__ __half g_bq[(size_t)DD*DD];       // Wq^T fp16 [N,K]
__device__ __half g_bk[(size_t)DD*DD];
__device__ __half g_bv[(size_t)DD*DD];
__device__ __half g_bo[(size_t)DD*DD];
__device__ __half g_qh[(size_t)MM*DD];       // q hi (scaled) [B,H,L,d]
__device__ __half g_ql[(size_t)MM*DD];       // q lo
__device__ __half g_kh[(size_t)MM*DD];       // k fp16
__device__ __half g_vh[(size_t)MM*DD];       // v fp16

__device__ __forceinline__ uint32_t smem_u32(const void* p) {
    uint32_t a;
    asm("{ .reg .u64 t; cvta.to.shared.u64 t, %1; cvt.u32.u64 %0, t; }"
        : "=r"(a) : "l"(p));
    return a;
}

#define LDSM4(r, addr) \
    asm volatile("ldmatrix.sync.aligned.m8n8.x4.shared.b16 {%0,%1,%2,%3}, [%4];" \
        : "=r"((r)[0]), "=r"((r)[1]), "=r"((r)[2]), "=r"((r)[3]) : "r"(addr))
#define LDSM4T(r, addr) \
    asm volatile("ldmatrix.sync.aligned.m8n8.x4.trans.shared.b16 {%0,%1,%2,%3}, [%4];" \
        : "=r"((r)[0]), "=r"((r)[1]), "=r"((r)[2]), "=r"((r)[3]) : "r"(addr))

#define MMA_F16(d, a, b0, b1) \
    asm volatile("mma.sync.aligned.m16n8k16.row.col.f32.f16.f16.f32 " \
        "{%0,%1,%2,%3}, {%4,%5,%6,%7}, {%8,%9}, {%0,%1,%2,%3};" \
        : "+f"((d)[0]), "+f"((d)[1]), "+f"((d)[2]), "+f"((d)[3]) \
        : "r"((a)[0]), "r"((a)[1]), "r"((a)[2]), "r"((a)[3]), "r"(b0), "r"(b1))

#define CP_ASYNC16(dst, src) \
    asm volatile("cp.async.cg.shared.global [%0], [%1], 16;" \
        :: "r"(dst), "l"(src) : "memory")
#define CP_COMMIT() asm volatile("cp.async.commit_group;" ::: "memory")
#define CP_WAIT1() asm volatile("cp.async.wait_group 1;" ::: "memory")
#define CP_WAIT0() asm volatile("cp.async.wait_group 0;" ::: "memory")

__device__ __forceinline__ uint32_t pack_h2(float x, float y) {
    __half2 t = __floats2half2_rn(x, y);
    return *(uint32_t*)&t;
}

// ---------------------------------------------------------------------------
// Conversion kernels
// ---------------------------------------------------------------------------
struct __align__(8) h16x4 { __half v[4]; };

__global__ __launch_bounds__(256) void conv_split_kernel(
    const float4* __restrict__ in, h16x4* __restrict__ oh, h16x4* __restrict__ ol, int n4)
{
    int i = blockIdx.x * 256 + threadIdx.x;
    if (i >= n4) return;
    float4 x = in[i];
    h16x4 h, l;
    h.v[0] = __float2half_rn(x.x); l.v[0] = __float2half_rn(x.x - __half2float(h.v[0]));
    h.v[1] = __float2half_rn(x.y); l.v[1] = __float2half_rn(x.y - __half2float(h.v[1]));
    h.v[2] = __float2half_rn(x.z); l.v[2] = __float2half_rn(x.z - __half2float(h.v[2]));
    h.v[3] = __float2half_rn(x.w); l.v[3] = __float2half_rn(x.w - __half2float(h.v[3]));
    oh[i] = h;
    ol[i] = l;
}

// 4 weight transposes fused: W [K,N] f32 -> Wt fp16 [N,K], blockIdx.z picks W.
__global__ __launch_bounds__(256) void conv_tr4_kernel(
    const float* __restrict__ W0, const float* __restrict__ W1,
    const float* __restrict__ W2, const float* __restrict__ W3,
    __half* __restrict__ T0, __half* __restrict__ T1,
    __half* __restrict__ T2, __half* __restrict__ T3)
{
    const float* W = (blockIdx.z == 0) ? W0 : (blockIdx.z == 1) ? W1
                    : (blockIdx.z == 2) ? W2 : W3;
    __half* Th = (blockIdx.z == 0) ? T0 : (blockIdx.z == 1) ? T1
                : (blockIdx.z == 2) ? T2 : T3;
    __shared__ float sm[32][33];
    const int k0 = blockIdx.x * 32, n0 = blockIdx.y * 32;
    const int tx = threadIdx.x, ty = threadIdx.y;     // (32, 8)
#pragma unroll
    for (int i = 0; i < 4; i++)
        sm[ty + 8 * i][tx] = W[(size_t)(k0 + ty + 8 * i) * DD + n0 + tx];
    __syncthreads();
#pragma unroll
    for (int i = 0; i < 4; i++) {
        float v = sm[tx][ty + 8 * i];
        Th[(size_t)(n0 + ty + 8 * i) * DD + k0 + tx] = __float2half_rn(v);
    }
}

// ---------------------------------------------------------------------------
// Persistent HMMA GEMM: CTA 128x128, 4 warps 2x2, warp tile 64x64,
// K-chunk 64, XOR-swizzled smem, 2 stages, 2 CTAs/SM.
// Grid-stride over 1024 tiles (grid = 2*SMs) -> no wave quantization.
// Al == nullptr -> single-term A.
// out_mode 0: fp32 row-major; 1: fp16 hi/lo scaled head-split (Q);
// 2: fp32 head-split + fp16 head-split (K,V)
// ---------------------------------------------------------------------------
#define KCH 64
#define TILE_SZ 16384                     // 128 rows x 128 B
#define STAGE_BYTES (3 * TILE_SZ)         // 49152  (Ah, Al, B)
#define GEMM_SMEM (2 * STAGE_BYTES)       // 98304
#define NCHUNK (DD / KCH)                 // 64
#define NTILES ((MM / 128) * (DD / 128))  // 1024

__global__ __launch_bounds__(128, 2) void gemm_mma_kernel(
    const __half* __restrict__ Ah, const __half* __restrict__ Al,
    const __half* __restrict__ B,
    const float* __restrict__ bias, float* __restrict__ out,
    __half* __restrict__ oh, __half* __restrict__ ol,
    float scale, int out_mode)
{
    extern __shared__ __align__(16) char smem[];
    const uint32_t sb = smem_u32(smem);
    const int tid = threadIdx.x, lane = tid & 31, wid = tid >> 5;
    const int wm = wid >> 1;              // 0..1
    const int wn = wid & 1;               // 0..1
    const bool has_lo = (Al != nullptr);

    // per-lane LDSM addressing (swizzled): row stride 128B, granule ^= (row&7)
    const int rowA = wm * 64 + (lane & 15);
    const int a_half = lane >> 4;
    const int s_a = lane & 7;
    const int rowB = wn * 64 + ((lane >> 4) << 3) + (lane & 7);
    const int b_half = (lane >> 3) & 1;
    const int s_b = lane & 7;

#pragma unroll 1
    for (int gid = blockIdx.x; gid < NTILES; gid += gridDim.x) {
        // swizzled block mapping: groups of (32 m x 8 n)
        const int m0 = (((gid & 255) >> 3)) * 128;
        const int n0 = (((gid >> 8) << 3) | (gid & 7)) * 128;

        const __half* gsrc[3];
        gsrc[0] = Ah + (size_t)m0 * DD;
        gsrc[1] = has_lo ? (Al + (size_t)m0 * DD) : gsrc[0];
        gsrc[2] = B + (size_t)n0 * DD;

        float acc[4][8][4];
#pragma unroll
        for (int i = 0; i < 4; i++)
#pragma unroll
            for (int j = 0; j < 8; j++)
#pragma unroll
                for (int e = 0; e < 4; e++) acc[i][j][e] = 0.f;

#define LOAD_CHUNK(cc, st) do {                                                \
    const uint32_t stage_ = sb + (uint32_t)(st) * STAGE_BYTES;                 \
    _Pragma("unroll")                                                          \
    for (int t_ = 0; t_ < 3; ++t_) {                                           \
        if (t_ == 1 && !has_lo) continue;                                      \
        const __half* gp_ = gsrc[t_] + (size_t)(cc) * KCH;                     \
        _Pragma("unroll")                                                      \
        for (int i_ = 0; i_ < 8; ++i_) {                                       \
            int f_ = tid + i_ * 128;              /* 0..1023 */                \
            int r_ = f_ >> 3, g_ = f_ & 7;                                     \
            const void* src_ = gp_ + (size_t)r_ * DD + g_ * 8;                 \
            uint32_t dst_ = stage_ + t_ * TILE_SZ + r_ * 128                   \
                            + ((g_ ^ (r_ & 7)) << 4);                          \
            CP_ASYNC16(dst_, src_);                                            \
        }                                                                      \
    }                                                                          \
    CP_COMMIT();                                                               \
} while (0)

        LOAD_CHUNK(0, 0);

#pragma unroll 1
        for (int c = 0; c < NCHUNK; ++c) {
            if (c + 1 < NCHUNK) {
                LOAD_CHUNK(c + 1, (c + 1) & 1);
                CP_WAIT1();
            } else {
                CP_WAIT0();
            }
            __syncthreads();

            const uint32_t stage = sb + (uint32_t)(c & 1) * STAGE_BYTES;

#pragma unroll
            for (int kk = 0; kk < 4; ++kk) {
                const uint32_t ga = (uint32_t)(((2 * kk + a_half) ^ s_a) << 4);
                const uint32_t gb = (uint32_t)(((2 * kk + b_half) ^ s_b) << 4);
                uint32_t ah_[4][4], bf_[4][4];
#pragma unroll
                for (int i = 0; i < 4; ++i) {
                    const uint32_t ra = (uint32_t)(rowA + i * 16) * 128 + ga;
                    LDSM4(ah_[i], stage + ra);
                }
#pragma unroll
                for (int j = 0; j < 4; ++j)
                    LDSM4(bf_[j], stage + 2 * TILE_SZ
                                  + (uint32_t)(rowB + j * 16) * 128 + gb);
#pragma unroll
                for (int i = 0; i < 4; ++i)
#pragma unroll
                    for (int jn = 0; jn < 8; ++jn)
                        MMA_F16(acc[i][jn], ah_[i], bf_[jn >> 1][(jn & 1) * 2],
                                bf_[jn >> 1][(jn & 1) * 2 + 1]);
                if (has_lo) {
                    uint32_t al_[4][4];
#pragma unroll
                    for (int i = 0; i < 4; ++i) {
                        const uint32_t ra = (uint32_t)(rowA + i * 16) * 128 + ga;
                        LDSM4(al_[i], stage + TILE_SZ + ra);
                    }
#pragma unroll
                    for (int i = 0; i < 4; ++i)
#pragma unroll
                        for (int jn = 0; jn < 8; ++jn)
                            MMA_F16(acc[i][jn], al_[i], bf_[jn >> 1][(jn & 1) * 2],
                                    bf_[jn >> 1][(jn & 1) * 2 + 1]);
                }
            }
            __syncthreads();
        }
#undef LOAD_CHUNK

        // epilogue
#pragma unroll
        for (int i = 0; i < 4; ++i) {
            const int r_lo = m0 + wm * 64 + i * 16 + (lane >> 2);
#pragma unroll
            for (int jn = 0; jn < 8; ++jn) {
                const int colg = n0 + wn * 64 + jn * 8 + (lane & 3) * 2;
                const float bv0 = bias[colg], bv1 = bias[colg + 1];
#pragma unroll
                for (int half_ = 0; half_ < 2; ++half_) {
                    const int row = r_lo + half_ * 8;
                    float vx = acc[i][jn][half_ * 2 + 0] + bv0;
                    float vy = acc[i][jn][half_ * 2 + 1] + bv1;
                    if (out_mode == 0) {
                        float2 v; v.x = vx; v.y = vy;
                        *(float2*)(out + (size_t)row * DD + colg) = v;
                    } else {
                        int b_ = row >> 11, l_ = row & 2047, h_ = colg >> 7, dd = colg & 127;
                        size_t idx = ((((size_t)b_ * HH + h_) * LL + l_) * HDIM) + dd;
                        if (out_mode == 2) {
                            float2 v; v.x = vx; v.y = vy;
                            *(float2*)(out + idx) = v;
                            *(uint32_t*)(oh + idx) = pack_h2(vx, vy);
                        } else {
                            float sx = vx * scale, sy = vy * scale;
                            __half hx = __float2half_rn(sx), hy = __float2half_rn(sy);
                            float rx = sx - __half2float(hx), ry = sy - __half2float(hy);
                            __half2 hp; hp.x = hx; hp.y = hy;
                            *(uint32_t*)(oh + idx) = *(uint32_t*)&hp;
                            *(uint32_t*)(ol + idx) = pack_h2(rx, ry);
                        }
                    }
                }
            }
        }
    }
}

// ---------------------------------------------------------------------------
// Flash attention (causal), HMMA fp16 2-term.
// KV in pairs of 64-row tiles (128 cols/iter), double-buffered pairs.
// Longest-first: qt = gridDim.x-1-blockIdx.x (big CTAs scheduled first).
// Grid (L/128, H, B), 256 threads (8 warps x 16 q-rows).
// ---------------------------------------------------------------------------
#define AROWSTR 272                        // 128 fp16 = 256 B + 16 pad
#define ATILE_Q (128 * AROWSTR)            // 34816
#define ATILE_KV (64 * AROWSTR)            // 17408
#define ATT_SMEM (2 * ATILE_Q + 8 * ATILE_KV)   // 208896

__global__ __launch_bounds__(256, 1) void attn_mma_kernel(
    const __half* __restrict__ qh, const __half* __restrict__ ql,
    const __half* __restrict__ kh, const __half* __restrict__ vh,
    __half* __restrict__ cth, __half* __restrict__ ctl)
{
    extern __shared__ __align__(16) char smem[];
    const uint32_t sb = smem_u32(smem);
    const int tid = threadIdx.x, lane = tid & 31, wid = tid >> 5;
    const int wr = wid * 16;

    const int qt = gridDim.x - 1 - blockIdx.x;   // longest-first scheduling
    const int h = blockIdx.y, b = blockIdx.z;
    const int q0 = qt * 128;
    const size_t hb = ((size_t)b * HH + h) * LL * HDIM;

    {
        const __half* srcs[2] = { qh + hb, ql + hb };
#pragma unroll
        for (int t = 0; t < 2; ++t)
#pragma unroll
            for (int i = 0; i < 8; ++i) {
                int f = tid + i * 256;
                int r = f >> 4, s = f & 15;
                CP_ASYNC16(sb + t * ATILE_Q + r * AROWSTR + s * 16,
                           srcs[t] + (size_t)(q0 + r) * HDIM + s * 8);
            }
        CP_COMMIT();
    }

    // Pair buffers: pair p at 2*ATILE_Q + p*4*ATILE_KV: [K0, V0, K1, V1]
#define LOAD_KVPAIR(it_, p_) do {                                              \
    _Pragma("unroll")                                                          \
    for (int t_ = 0; t_ < 4; ++t_) {                                           \
        const __half* src_ = (t_ & 1) ? (vh + hb) : (kh + hb);                 \
        const int k0_ = ((it_) * 2 + (t_ >> 1)) * 64;                          \
        const uint32_t base_ = sb + 2 * ATILE_Q + (p_) * 4 * ATILE_KV          \
                               + t_ * ATILE_KV;                                \
        _Pragma("unroll")                                                      \
        for (int i_ = 0; i_ < 4; ++i_) {                                       \
            int f_ = tid + i_ * 256;                                           \
            int r_ = f_ >> 4, s_ = f_ & 15;                                    \
            CP_ASYNC16(base_ + r_ * AROWSTR + s_ * 16,                         \
                       src_ + (size_t)(k0_ + r_) * HDIM + s_ * 8);             \
        }                                                                      \
    }                                                                          \
    CP_COMMIT();                                                               \
} while (0)

    LOAD_KVPAIR(0, 0);

    float o[16][4];
#pragma unroll
    for (int i = 0; i < 16; ++i)
#pragma unroll
        for (int e = 0; e < 4; ++e) o[i][e] = 0.f;
    float m_i[2] = { -1e30f, -1e30f };
    float l_i[2] = { 0.f, 0.f };

    const uint32_t qa_off = (uint32_t)(wr + (lane & 15)) * AROWSTR + ((lane >> 4) << 4);
    const uint32_t kb_off = (uint32_t)(((lane >> 4) << 3) + (lane & 7)) * AROWSTR
                            + (((lane >> 3) & 1) << 4);
    const uint32_t vb_off = (uint32_t)(((lane >> 3) & 1) * 8 + (lane & 7)) * AROWSTR
                            + ((lane >> 4) << 4);

    const int nit = qt + 1;               // pairs of 64-tiles

#pragma unroll 1
    for (int it = 0; it < nit; ++it) {
        const int k0 = it * 128;
        __syncthreads();
        if (it + 1 < nit) {
            LOAD_KVPAIR(it + 1, (it + 1) & 1);
            CP_WAIT1();
        } else {
            CP_WAIT0();
        }
        __syncthreads();

        const bool active = (k0 <= q0 + wr + 15);
        if (active) {
            const uint32_t pairb = sb + 2 * ATILE_Q + (uint32_t)(it & 1) * 4 * ATILE_KV;
            const uint32_t k_s0 = pairb;
            const uint32_t v_s0 = pairb + ATILE_KV;
            const uint32_t k_s1 = pairb + 2 * ATILE_KV;
            const uint32_t v_s1 = pairb + 3 * ATILE_KV;

            float s[16][4];
#pragma unroll
            for (int i = 0; i < 16; ++i)
#pragma unroll
                for (int e = 0; e < 4; ++e) s[i][e] = 0.f;

            // ---- S = Q @ K^T over 128 cols (2-term) ----
#pragma unroll
            for (int kk = 0; kk < 8; ++kk) {
                uint32_t qa_h[4], qa_l[4], kb_[8][4];
                LDSM4(qa_h, sb + 0 * ATILE_Q + qa_off + kk * 32);
                LDSM4(qa_l, sb + 1 * ATILE_Q + qa_off + kk * 32);
#pragma unroll
                for (int g = 0; g < 4; ++g) {
                    LDSM4(kb_[g],     k_s0 + g * 16 * AROWSTR + kb_off + kk * 32);
                    LDSM4(kb_[4 + g], k_s1 + g * 16 * AROWSTR + kb_off + kk * 32);
                }
#pragma unroll
                for (int g = 0; g < 8; ++g)
#pragma unroll
                    for (int jj = 0; jj < 2; ++jj)
                        MMA_F16(s[2 * g + jj], qa_h, kb_[g][jj * 2], kb_[g][jj * 2 + 1]);
#pragma unroll
                for (int g = 0; g < 8; ++g)
#pragma unroll
                    for (int jj = 0; jj < 2; ++jj)
                        MMA_F16(s[2 * g + jj], qa_l, kb_[g][jj * 2], kb_[g][jj * 2 + 1]);
            }

            // ---- causal mask ----
            const int r0g = q0 + wr + (lane >> 2);
            if (k0 + 127 > q0 + wr) {
#pragma unroll
                for (int nt = 0; nt < 16; ++nt) {
                    const int cg = k0 + nt * 8 + (lane & 3) * 2;
#pragma unroll
                    for (int e = 0; e < 4; ++e) {
                        const int rr = r0g + (e >> 1) * 8;
                        const int cc = cg + (e & 1);
                        if (cc > rr) s[nt][e] = -1e30f;
                    }
                }
            }

            // ---- online softmax over 128 cols ----
            float scl[2];
#pragma unroll
            for (int rh = 0; rh < 2; ++rh) {
                float mx = -1e30f;
#pragma unroll
                for (int nt = 0; nt < 16; ++nt)
                    mx = fmaxf(mx, fmaxf(s[nt][rh * 2], s[nt][rh * 2 + 1]));
                mx = fmaxf(mx, __shfl_xor_sync(0xffffffffu, mx, 1));
                mx = fmaxf(mx, __shfl_xor_sync(0xffffffffu, mx, 2));
                const float m_new = fmaxf(m_i[rh], mx);
                scl[rh] = __expf(m_i[rh] - m_new);
                float rs = 0.f;
#pragma unroll
                for (int nt = 0; nt < 16; ++nt) {
                    float p0 = __expf(s[nt][rh * 2] - m_new);
                    float p1 = __expf(s[nt][rh * 2 + 1] - m_new);
                    s[nt][rh * 2] = p0;
                    s[nt][rh * 2 + 1] = p1;
                    rs += p0 + p1;
                }
                rs += __shfl_xor_sync(0xffffffffu, rs, 1);
                rs += __shfl_xor_sync(0xffffffffu, rs, 2);
                l_i[rh] = l_i[rh] * scl[rh] + rs;
                m_i[rh] = m_new;
            }
#pragma unroll
            for (int i = 0; i < 16; ++i) {
                o[i][0] *= scl[0]; o[i][1] *= scl[0];
                o[i][2] *= scl[1]; o[i][3] *= scl[1];
            }

            // ---- split P into fp16 hi/lo A-fragments (8 k16 groups) ----
            uint32_t pa_h[8][4], pa_l[8][4];
#pragma unroll
            for (int kk = 0; kk < 8; ++kk) {
                const int t0 = 2 * kk, t1 = 2 * kk + 1;
                const float pv[8] = { s[t0][0], s[t0][1], s[t0][2], s[t0][3],
                                      s[t1][0], s[t1][1], s[t1][2], s[t1][3] };
                float ph[8], pr[8];
#pragma unroll
                for (int e = 0; e < 8; ++e) {
                    __half hh = __float2half_rn(pv[e]);
                    ph[e] = __half2float(hh);
                    pr[e] = pv[e] - ph[e];
                }
                pa_h[kk][0] = pack_h2(ph[0], ph[1]);
                pa_h[kk][1] = pack_h2(ph[2], ph[3]);
                pa_h[kk][2] = pack_h2(ph[4], ph[5]);
                pa_h[kk][3] = pack_h2(ph[6], ph[7]);
                pa_l[kk][0] = pack_h2(pr[0], pr[1]);
                pa_l[kk][1] = pack_h2(pr[2], pr[3]);
                pa_l[kk][2] = pack_h2(pr[4], pr[5]);
                pa_l[kk][3] = pack_h2(pr[6], pr[7]);
            }

            // ---- O += P @ V over 128 contraction cols, kk-outer ----
#pragma unroll
            for (int kk = 0; kk < 8; ++kk) {
                const uint32_t vsrc = (kk < 4) ? v_s0 : v_s1;
                const uint32_t vrow = (uint32_t)((kk & 3) * 16) * AROWSTR;
                uint32_t vb_[8][4];
#pragma unroll
                for (int g = 0; g < 8; ++g)
                    LDSM4T(vb_[g], vsrc + vrow + g * 32 + vb_off);
#pragma unroll
                for (int g = 0; g < 8; ++g) {
                    MMA_F16(o[2 * g],     pa_h[kk], vb_[g][0], vb_[g][1]);
                    MMA_F16(o[2 * g + 1], pa_h[kk], vb_[g][2], vb_[g][3]);
                }
#pragma unroll
                for (int g = 0; g < 8; ++g) {
                    MMA_F16(o[2 * g],     pa_l[kk], vb_[g][0], vb_[g][1]);
                    MMA_F16(o[2 * g + 1], pa_l[kk], vb_[g][2], vb_[g][3]);
                }
            }
        }
    }
#undef LOAD_KVPAIR

    const float inv0 = 1.0f / l_i[0];
    const float inv1 = 1.0f / l_i[1];
    const int rg0 = b * LL + q0 + wr + (lane >> 2);
    const int rg1 = rg0 + 8;
#pragma unroll
    for (int nt = 0; nt < 16; ++nt) {
        const int col = h * HDIM + nt * 8 + (lane & 3) * 2;
        {
            float vx = o[nt][0] * inv0, vy = o[nt][1] * inv0;
            __half hx = __float2half_rn(vx), hy = __float2half_rn(vy);
            float rx = vx - __half2float(hx), ry = vy - __half2float(hy);
            __half2 hp; hp.x = hx; hp.y = hy;
            size_t idx = (size_t)rg0 * DD + col;
            *(uint32_t*)(cth + idx) = *(uint32_t*)&hp;
            *(uint32_t*)(ctl + idx) = pack_h2(rx, ry);
        }
        {
            float vx = o[nt][2] * inv1, vy = o[nt][3] * inv1;
            __half hx = __float2half_rn(vx), hy = __float2half_rn(vy);
            float rx = vx - __half2float(hx), ry = vy - __half2float(hy);
            __half2 hp; hp.x = hx; hp.y = hy;
            size_t idx = (size_t)rg1 * DD + col;
            *(uint32_t*)(cth + idx) = *(uint32_t*)&hp;
            *(uint32_t*)(ctl + idx) = pack_h2(rx, ry);
        }
    }
}

// ---------------------------------------------------------------------------
// Launch.  d_out layout: [ out (B*L*D) | k (B*H*L*d) | v (B*H*L*d) ]
// ---------------------------------------------------------------------------
extern "C" void kernel_launch(void* const* d_in, const int* in_sizes, int n_in,
                              void* d_out, int out_size)
{
    const float* x  = (const float*)d_in[0];
    const float* Wq = (const float*)d_in[2];
    const float* bq = (const float*)d_in[3];
    const float* Wk = (const float*)d_in[4];
    const float* bk = (const float*)d_in[5];
    const float* Wv = (const float*)d_in[6];
    const float* bv = (const float*)d_in[7];
    const float* Wo = (const float*)d_in[8];
    const float* bo = (const float*)d_in[9];

    float* out_p = (float*)d_out;
    float* k_out = out_p + (size_t)BB * LL * DD;
    float* v_out = k_out + (size_t)BB * HH * LL * HDIM;

    __half *ah, *al, *btq, *btk, *btv, *bto, *qh, *ql, *kh, *vh;
    cudaGetSymbolAddress((void**)&ah, g_ah);
    cudaGetSymbolAddress((void**)&al, g_al);
    cudaGetSymbolAddress((void**)&btq, g_bq);
    cudaGetSymbolAddress((void**)&btk, g_bk);
    cudaGetSymbolAddress((void**)&btv, g_bv);
    cudaGetSymbolAddress((void**)&bto, g_bo);
    cudaGetSymbolAddress((void**)&qh, g_qh);
    cudaGetSymbolAddress((void**)&ql, g_ql);
    cudaGetSymbolAddress((void**)&kh, g_kh);
    cudaGetSymbolAddress((void**)&vh, g_vh);

    cudaFuncSetAttribute(gemm_mma_kernel, cudaFuncAttributeMaxDynamicSharedMemorySize, GEMM_SMEM);
    cudaFuncSetAttribute(attn_mma_kernel, cudaFuncAttributeMaxDynamicSharedMemorySize, ATT_SMEM);

    // persistent grid: 2 CTAs per SM
    int n_sm = 148;
    cudaDeviceGetAttribute(&n_sm, cudaDevAttrMultiProcessorCount, 0);
    const int pgrid = 2 * n_sm;

    const int n4 = MM * DD / 4;
    const int cs_blocks = n4 / 256;
    dim3 tr_grid(DD / 32, DD / 32, 4);
    dim3 tr_block(32, 8);

    // upfront conversions
    conv_split_kernel<<<cs_blocks, 256>>>((const float4*)x, (h16x4*)ah, (h16x4*)al, n4);
    conv_tr4_kernel<<<tr_grid, tr_block>>>(Wq, Wk, Wv, Wo, btq, btk, btv, bto);

    // projections: Q full 2-term; K,V single-term — persistent grids
    gemm_mma_kernel<<<pgrid, 128, GEMM_SMEM>>>(ah, al, btq, bq, nullptr, qh, ql, ATT_SCALE, 1);
    gemm_mma_kernel<<<pgrid, 128, GEMM_SMEM>>>(ah, nullptr, btk, bk, k_out, kh, nullptr, 1.0f, 2);
    gemm_mma_kernel<<<pgrid, 128, GEMM_SMEM>>>(ah, nullptr, btv, bv, v_out, vh, nullptr, 1.0f, 2);

    // attention -> ctx fp16 split into ah/al
    dim3 ag(LL / 128, HH, BB);
    attn_mma_kernel<<<ag, 256, ATT_SMEM>>>(qh, ql, kh, vh, ah, al);

    // output projection (full 2-term), persistent
    gemm_mma_kernel<<<pgrid, 128, GEMM_SMEM>>>(ah, al, bto, bo, out_p, nullptr, nullptr, 1.0f, 0);
}

// round 15
// speedup vs baseline: 1.3715x; 1.1219x over previous
#include <cuda_runtime.h>
#include <cuda_fp16.h>
#include <math.h>
#include <stdint.h>

// Problem constants
#define BB 2
#define LL 2048
#define DD 4096
#define HH 32
#define HDIM 128
#define MM (BB*LL)          // 4096 rows
#define ATT_SCALE 0.08838834764831845f

// ---------------------------------------------------------------------------
// Scratch (allocation-free rule: __device__ globals)
// ---------------------------------------------------------------------------
__device__ __half g_ah[(size_t)MM*DD];       // A hi (x or ctx)
__device__ __half g_al[(size_t)MM*DD];       // A lo
__device__ __half g_bq[(size_t)DD*DD];       // Wq^T fp16 [N,K]
__device__ __half g_bk[(size_t)DD*DD];
__device__ __half g_bv[(size_t)DD*DD];
__device__ __half g_bo[(size_t)DD*DD];
__device__ __half g_qh[(size_t)MM*DD];       // q hi (scaled) [B,H,L,d]
__device__ __half g_ql[(size_t)MM*DD];       // q lo
__device__ __half g_kh[(size_t)MM*DD];       // k fp16
__device__ __half g_vh[(size_t)MM*DD];       // v fp16

__device__ __forceinline__ uint32_t smem_u32(const void* p) {
    uint32_t a;
    asm("{ .reg .u64 t; cvta.to.shared.u64 t, %1; cvt.u32.u64 %0, t; }"
        : "=r"(a) : "l"(p));
    return a;
}

#define LDSM4(r, addr) \
    asm volatile("ldmatrix.sync.aligned.m8n8.x4.shared.b16 {%0,%1,%2,%3}, [%4];" \
        : "=r"((r)[0]), "=r"((r)[1]), "=r"((r)[2]), "=r"((r)[3]) : "r"(addr))
#define LDSM4T(r, addr) \
    asm volatile("ldmatrix.sync.aligned.m8n8.x4.trans.shared.b16 {%0,%1,%2,%3}, [%4];" \
        : "=r"((r)[0]), "=r"((r)[1]), "=r"((r)[2]), "=r"((r)[3]) : "r"(addr))

#define MMA_F16(d, a, b0, b1) \
    asm volatile("mma.sync.aligned.m16n8k16.row.col.f32.f16.f16.f32 " \
        "{%0,%1,%2,%3}, {%4,%5,%6,%7}, {%8,%9}, {%0,%1,%2,%3};" \
        : "+f"((d)[0]), "+f"((d)[1]), "+f"((d)[2]), "+f"((d)[3]) \
        : "r"((a)[0]), "r"((a)[1]), "r"((a)[2]), "r"((a)[3]), "r"(b0), "r"(b1))

#define CP_ASYNC16(dst, src) \
    asm volatile("cp.async.cg.shared.global [%0], [%1], 16;" \
        :: "r"(dst), "l"(src) : "memory")
#define CP_COMMIT() asm volatile("cp.async.commit_group;" ::: "memory")
#define CP_WAIT1() asm volatile("cp.async.wait_group 1;" ::: "memory")
#define CP_WAIT0() asm volatile("cp.async.wait_group 0;" ::: "memory")

__device__ __forceinline__ uint32_t pack_h2(float x, float y) {
    __half2 t = __floats2half2_rn(x, y);
    return *(uint32_t*)&t;
}

// ---------------------------------------------------------------------------
// Conversion kernels
// ---------------------------------------------------------------------------
struct __align__(8) h16x4 { __half v[4]; };

__global__ __launch_bounds__(256) void conv_split_kernel(
    const float4* __restrict__ in, h16x4* __restrict__ oh, h16x4* __restrict__ ol, int n4)
{
    int i = blockIdx.x * 256 + threadIdx.x;
    if (i >= n4) return;
    float4 x = in[i];
    h16x4 h, l;
    h.v[0] = __float2half_rn(x.x); l.v[0] = __float2half_rn(x.x - __half2float(h.v[0]));
    h.v[1] = __float2half_rn(x.y); l.v[1] = __float2half_rn(x.y - __half2float(h.v[1]));
    h.v[2] = __float2half_rn(x.z); l.v[2] = __float2half_rn(x.z - __half2float(h.v[2]));
    h.v[3] = __float2half_rn(x.w); l.v[3] = __float2half_rn(x.w - __half2float(h.v[3]));
    oh[i] = h;
    ol[i] = l;
}

// 4 weight transposes fused: W [K,N] f32 -> Wt fp16 [N,K], blockIdx.z picks W.
__global__ __launch_bounds__(256) void conv_tr4_kernel(
    const float* __restrict__ W0, const float* __restrict__ W1,
    const float* __restrict__ W2, const float* __restrict__ W3,
    __half* __restrict__ T0, __half* __restrict__ T1,
    __half* __restrict__ T2, __half* __restrict__ T3)
{
    const float* W = (blockIdx.z == 0) ? W0 : (blockIdx.z == 1) ? W1
                    : (blockIdx.z == 2) ? W2 : W3;
    __half* Th = (blockIdx.z == 0) ? T0 : (blockIdx.z == 1) ? T1
                : (blockIdx.z == 2) ? T2 : T3;
    __shared__ float sm[32][33];
    const int k0 = blockIdx.x * 32, n0 = blockIdx.y * 32;
    const int tx = threadIdx.x, ty = threadIdx.y;     // (32, 8)
#pragma unroll
    for (int i = 0; i < 4; i++)
        sm[ty + 8 * i][tx] = W[(size_t)(k0 + ty + 8 * i) * DD + n0 + tx];
    __syncthreads();
#pragma unroll
    for (int i = 0; i < 4; i++) {
        float v = sm[tx][ty + 8 * i];
        Th[(size_t)(n0 + ty + 8 * i) * DD + k0 + tx] = __float2half_rn(v);
    }
}

// ---------------------------------------------------------------------------
// Persistent HMMA GEMM: CTA 128x128, 4 warps 2x2, warp tile 64x64,
// K-chunk 64, XOR-swizzled smem, 2 stages, 2 CTAs/SM.
// Grid-stride over ntotal tiles; tiles >= NTILES use the second job
// (B2/bias2/out2/oh2) -- used to fuse the K and V projections into one
// launch. Grid-stride keeps resident CTAs on consecutive gids, so only one
// weight matrix is hot in L2 at a time.
// Al == nullptr -> single-term A.
// out_mode 0: fp32 row-major; 1: fp16 hi/lo scaled head-split (Q);
// 2: fp32 head-split + fp16 head-split (K,V)
// ---------------------------------------------------------------------------
#define KCH 64
#define TILE_SZ 16384                     // 128 rows x 128 B
#define STAGE_BYTES (3 * TILE_SZ)         // 49152  (Ah, Al, B)
#define GEMM_SMEM (2 * STAGE_BYTES)       // 98304
#define NCHUNK (DD / KCH)                 // 64
#define NTILES ((MM / 128) * (DD / 128))  // 1024

__global__ __launch_bounds__(128, 2) void gemm_mma_kernel(
    const __half* __restrict__ Ah, const __half* __restrict__ Al,
    const __half* __restrict__ B,
    const float* __restrict__ bias, float* __restrict__ out,
    __half* __restrict__ oh, __half* __restrict__ ol,
    float scale, int out_mode,
    const __half* __restrict__ B2, const float* __restrict__ bias2,
    float* __restrict__ out2, __half* __restrict__ oh2,
    int ntotal)
{
    extern __shared__ __align__(16) char smem[];
    const uint32_t sb = smem_u32(smem);
    const int tid = threadIdx.x, lane = tid & 31, wid = tid >> 5;
    const int wm = wid >> 1;              // 0..1
    const int wn = wid & 1;               // 0..1
    const bool has_lo = (Al != nullptr);

    // per-lane LDSM addressing (swizzled): row stride 128B, granule ^= (row&7)
    const int rowA = wm * 64 + (lane & 15);
    const int a_half = lane >> 4;
    const int s_a = lane & 7;
    const int rowB = wn * 64 + ((lane >> 4) << 3) + (lane & 7);
    const int b_half = (lane >> 3) & 1;
    const int s_b = lane & 7;

#pragma unroll 1
    for (int gid = blockIdx.x; gid < ntotal; gid += gridDim.x) {
        const bool second = (gid >= NTILES);
        const int tg = second ? gid - NTILES : gid;
        const __half* Bx = second ? B2 : B;
        const float* biasx = second ? bias2 : bias;
        float* outx = second ? out2 : out;
        __half* ohx = second ? oh2 : oh;

        // swizzled block mapping: groups of (32 m x 8 n)
        const int m0 = (((tg & 255) >> 3)) * 128;
        const int n0 = (((tg >> 8) << 3) | (tg & 7)) * 128;

        const __half* gsrc[3];
        gsrc[0] = Ah + (size_t)m0 * DD;
        gsrc[1] = has_lo ? (Al + (size_t)m0 * DD) : gsrc[0];
        gsrc[2] = Bx + (size_t)n0 * DD;

        float acc[4][8][4];
#pragma unroll
        for (int i = 0; i < 4; i++)
#pragma unroll
            for (int j = 0; j < 8; j++)
#pragma unroll
                for (int e = 0; e < 4; e++) acc[i][j][e] = 0.f;

#define LOAD_CHUNK(cc, st) do {                                                \
    const uint32_t stage_ = sb + (uint32_t)(st) * STAGE_BYTES;                 \
    _Pragma("unroll")                                                          \
    for (int t_ = 0; t_ < 3; ++t_) {                                           \
        if (t_ == 1 && !has_lo) continue;                                      \
        const __half* gp_ = gsrc[t_] + (size_t)(cc) * KCH;                     \
        _Pragma("unroll")                                                      \
        for (int i_ = 0; i_ < 8; ++i_) {                                       \
            int f_ = tid + i_ * 128;              /* 0..1023 */                \
            int r_ = f_ >> 3, g_ = f_ & 7;                                     \
            const void* src_ = gp_ + (size_t)r_ * DD + g_ * 8;                 \
            uint32_t dst_ = stage_ + t_ * TILE_SZ + r_ * 128                   \
                            + ((g_ ^ (r_ & 7)) << 4);                          \
            CP_ASYNC16(dst_, src_);                                            \
        }                                                                      \
    }                                                                          \
    CP_COMMIT();                                                               \
} while (0)

        LOAD_CHUNK(0, 0);

#pragma unroll 1
        for (int c = 0; c < NCHUNK; ++c) {
            if (c + 1 < NCHUNK) {
                LOAD_CHUNK(c + 1, (c + 1) & 1);
                CP_WAIT1();
            } else {
                CP_WAIT0();
            }
            __syncthreads();

            const uint32_t stage = sb + (uint32_t)(c & 1) * STAGE_BYTES;

#pragma unroll
            for (int kk = 0; kk < 4; ++kk) {
                const uint32_t ga = (uint32_t)(((2 * kk + a_half) ^ s_a) << 4);
                const uint32_t gb = (uint32_t)(((2 * kk + b_half) ^ s_b) << 4);
                uint32_t ah_[4][4], bf_[4][4];
#pragma unroll
                for (int i = 0; i < 4; ++i) {
                    const uint32_t ra = (uint32_t)(rowA + i * 16) * 128 + ga;
                    LDSM4(ah_[i], stage + ra);
                }
#pragma unroll
                for (int j = 0; j < 4; ++j)
                    LDSM4(bf_[j], stage + 2 * TILE_SZ
                                  + (uint32_t)(rowB + j * 16) * 128 + gb);
#pragma unroll
                for (int i = 0; i < 4; ++i)
#pragma unroll
                    for (int jn = 0; jn < 8; ++jn)
                        MMA_F16(acc[i][jn], ah_[i], bf_[jn >> 1][(jn & 1) * 2],
                                bf_[jn >> 1][(jn & 1) * 2 + 1]);
                if (has_lo) {
                    uint32_t al_[4][4];
#pragma unroll
                    for (int i = 0; i < 4; ++i) {
                        const uint32_t ra = (uint32_t)(rowA + i * 16) * 128 + ga;
                        LDSM4(al_[i], stage + TILE_SZ + ra);
                    }
#pragma unroll
                    for (int i = 0; i < 4; ++i)
#pragma unroll
                        for (int jn = 0; jn < 8; ++jn)
                            MMA_F16(acc[i][jn], al_[i], bf_[jn >> 1][(jn & 1) * 2],
                                    bf_[jn >> 1][(jn & 1) * 2 + 1]);
                }
            }
            __syncthreads();
        }
#undef LOAD_CHUNK

        // epilogue
#pragma unroll
        for (int i = 0; i < 4; ++i) {
            const int r_lo = m0 + wm * 64 + i * 16 + (lane >> 2);
#pragma unroll
            for (int jn = 0; jn < 8; ++jn) {
                const int colg = n0 + wn * 64 + jn * 8 + (lane & 3) * 2;
                const float bv0 = biasx[colg], bv1 = biasx[colg + 1];
#pragma unroll
                for (int half_ = 0; half_ < 2; ++half_) {
                    const int row = r_lo + half_ * 8;
                    float vx = acc[i][jn][half_ * 2 + 0] + bv0;
                    float vy = acc[i][jn][half_ * 2 + 1] + bv1;
                    if (out_mode == 0) {
                        float2 v; v.x = vx; v.y = vy;
                        *(float2*)(outx + (size_t)row * DD + colg) = v;
                    } else {
                        int b_ = row >> 11, l_ = row & 2047, h_ = colg >> 7, dd = colg & 127;
                        size_t idx = ((((size_t)b_ * HH + h_) * LL + l_) * HDIM) + dd;
                        if (out_mode == 2) {
                            float2 v; v.x = vx; v.y = vy;
                            *(float2*)(outx + idx) = v;
                            *(uint32_t*)(ohx + idx) = pack_h2(vx, vy);
                        } else {
                            float sx = vx * scale, sy = vy * scale;
                            __half hx = __float2half_rn(sx), hy = __float2half_rn(sy);
                            float rx = sx - __half2float(hx), ry = sy - __half2float(hy);
                            __half2 hp; hp.x = hx; hp.y = hy;
                            *(uint32_t*)(ohx + idx) = *(uint32_t*)&hp;
                            *(uint32_t*)(ol + idx) = pack_h2(rx, ry);
                        }
                    }
                }
            }
        }
    }
}

// ---------------------------------------------------------------------------
// Flash attention (causal), HMMA fp16 2-term.
// KV in pairs of 64-row tiles (128 cols/iter), double-buffered pairs.
// Longest-first: qt = gridDim.x-1-blockIdx.x.
// Grid (L/128, H, B), 256 threads (8 warps x 16 q-rows).
// ---------------------------------------------------------------------------
#define AROWSTR 272                        // 128 fp16 = 256 B + 16 pad
#define ATILE_Q (128 * AROWSTR)            // 34816
#define ATILE_KV (64 * AROWSTR)            // 17408
#define ATT_SMEM (2 * ATILE_Q + 8 * ATILE_KV)   // 208896

__global__ __launch_bounds__(256, 1) void attn_mma_kernel(
    const __half* __restrict__ qh, const __half* __restrict__ ql,
    const __half* __restrict__ kh, const __half* __restrict__ vh,
    __half* __restrict__ cth, __half* __restrict__ ctl)
{
    extern __shared__ __align__(16) char smem[];
    const uint32_t sb = smem_u32(smem);
    const int tid = threadIdx.x, lane = tid & 31, wid = tid >> 5;
    const int wr = wid * 16;

    const int qt = gridDim.x - 1 - blockIdx.x;   // longest-first scheduling
    const int h = blockIdx.y, b = blockIdx.z;
    const int q0 = qt * 128;
    const size_t hb = ((size_t)b * HH + h) * LL * HDIM;

    {
        const __half* srcs[2] = { qh + hb, ql + hb };
#pragma unroll
        for (int t = 0; t < 2; ++t)
#pragma unroll
            for (int i = 0; i < 8; ++i) {
                int f = tid + i * 256;
                int r = f >> 4, s = f & 15;
                CP_ASYNC16(sb + t * ATILE_Q + r * AROWSTR + s * 16,
                           srcs[t] + (size_t)(q0 + r) * HDIM + s * 8);
            }
        CP_COMMIT();
    }

    // Pair buffers: pair p at 2*ATILE_Q + p*4*ATILE_KV: [K0, V0, K1, V1]
#define LOAD_KVPAIR(it_, p_) do {                                              \
    _Pragma("unroll")                                                          \
    for (int t_ = 0; t_ < 4; ++t_) {                                           \
        const __half* src_ = (t_ & 1) ? (vh + hb) : (kh + hb);                 \
        const int k0_ = ((it_) * 2 + (t_ >> 1)) * 64;                          \
        const uint32_t base_ = sb + 2 * ATILE_Q + (p_) * 4 * ATILE_KV          \
                               + t_ * ATILE_KV;                                \
        _Pragma("unroll")                                                      \
        for (int i_ = 0; i_ < 4; ++i_) {                                       \
            int f_ = tid + i_ * 256;                                           \
            int r_ = f_ >> 4, s_ = f_ & 15;                                    \
            CP_ASYNC16(base_ + r_ * AROWSTR + s_ * 16,                         \
                       src_ + (size_t)(k0_ + r_) * HDIM + s_ * 8);             \
        }                                                                      \
    }                                                                          \
    CP_COMMIT();                                                               \
} while (0)

    LOAD_KVPAIR(0, 0);

    float o[16][4];
#pragma unroll
    for (int i = 0; i < 16; ++i)
#pragma unroll
        for (int e = 0; e < 4; ++e) o[i][e] = 0.f;
    float m_i[2] = { -1e30f, -1e30f };
    float l_i[2] = { 0.f, 0.f };

    const uint32_t qa_off = (uint32_t)(wr + (lane & 15)) * AROWSTR + ((lane >> 4) << 4);
    const uint32_t kb_off = (uint32_t)(((lane >> 4) << 3) + (lane & 7)) * AROWSTR
                            + (((lane >> 3) & 1) << 4);
    const uint32_t vb_off = (uint32_t)(((lane >> 3) & 1) * 8 + (lane & 7)) * AROWSTR
                            + ((lane >> 4) << 4);

    const int nit = qt + 1;               // pairs of 64-tiles

#pragma unroll 1
    for (int it = 0; it < nit; ++it) {
        const int k0 = it * 128;
        __syncthreads();
        if (it + 1 < nit) {
            LOAD_KVPAIR(it + 1, (it + 1) & 1);
            CP_WAIT1();
        } else {
            CP_WAIT0();
        }
        __syncthreads();

        const bool active = (k0 <= q0 + wr + 15);
        if (active) {
            const uint32_t pairb = sb + 2 * ATILE_Q + (uint32_t)(it & 1) * 4 * ATILE_KV;
            const uint32_t k_s0 = pairb;
            const uint32_t v_s0 = pairb + ATILE_KV;
            const uint32_t k_s1 = pairb + 2 * ATILE_KV;
            const uint32_t v_s1 = pairb + 3 * ATILE_KV;

            float s[16][4];
#pragma unroll
            for (int i = 0; i < 16; ++i)
#pragma unroll
                for (int e = 0; e < 4; ++e) s[i][e] = 0.f;

            // ---- S = Q @ K^T over 128 cols (2-term) ----
#pragma unroll
            for (int kk = 0; kk < 8; ++kk) {
                uint32_t qa_h[4], qa_l[4], kb_[8][4];
                LDSM4(qa_h, sb + 0 * ATILE_Q + qa_off + kk * 32);
                LDSM4(qa_l, sb + 1 * ATILE_Q + qa_off + kk * 32);
#pragma unroll
                for (int g = 0; g < 4; ++g) {
                    LDSM4(kb_[g],     k_s0 + g * 16 * AROWSTR + kb_off + kk * 32);
                    LDSM4(kb_[4 + g], k_s1 + g * 16 * AROWSTR + kb_off + kk * 32);
                }
#pragma unroll
                for (int g = 0; g < 8; ++g)
#pragma unroll
                    for (int jj = 0; jj < 2; ++jj)
                        MMA_F16(s[2 * g + jj], qa_h, kb_[g][jj * 2], kb_[g][jj * 2 + 1]);
#pragma unroll
                for (int g = 0; g < 8; ++g)
#pragma unroll
                    for (int jj = 0; jj < 2; ++jj)
                        MMA_F16(s[2 * g + jj], qa_l, kb_[g][jj * 2], kb_[g][jj * 2 + 1]);
            }

            // ---- causal mask ----
            const int r0g = q0 + wr + (lane >> 2);
            if (k0 + 127 > q0 + wr) {
#pragma unroll
                for (int nt = 0; nt < 16; ++nt) {
                    const int cg = k0 + nt * 8 + (lane & 3) * 2;
#pragma unroll
                    for (int e = 0; e < 4; ++e) {
                        const int rr = r0g + (e >> 1) * 8;
                        const int cc = cg + (e & 1);
                        if (cc > rr) s[nt][e] = -1e30f;
                    }
                }
            }

            // ---- online softmax over 128 cols ----
            float scl[2];
#pragma unroll
            for (int rh = 0; rh < 2; ++rh) {
                float mx = -1e30f;
#pragma unroll
                for (int nt = 0; nt < 16; ++nt)
                    mx = fmaxf(mx, fmaxf(s[nt][rh * 2], s[nt][rh * 2 + 1]));
                mx = fmaxf(mx, __shfl_xor_sync(0xffffffffu, mx, 1));
                mx = fmaxf(mx, __shfl_xor_sync(0xffffffffu, mx, 2));
                const float m_new = fmaxf(m_i[rh], mx);
                scl[rh] = __expf(m_i[rh] - m_new);
                float rs = 0.f;
#pragma unroll
                for (int nt = 0; nt < 16; ++nt) {
                    float p0 = __expf(s[nt][rh * 2] - m_new);
                    float p1 = __expf(s[nt][rh * 2 + 1] - m_new);
                    s[nt][rh * 2] = p0;
                    s[nt][rh * 2 + 1] = p1;
                    rs += p0 + p1;
                }
                rs += __shfl_xor_sync(0xffffffffu, rs, 1);
                rs += __shfl_xor_sync(0xffffffffu, rs, 2);
                l_i[rh] = l_i[rh] * scl[rh] + rs;
                m_i[rh] = m_new;
            }
#pragma unroll
            for (int i = 0; i < 16; ++i) {
                o[i][0] *= scl[0]; o[i][1] *= scl[0];
                o[i][2] *= scl[1]; o[i][3] *= scl[1];
            }

            // ---- split P into fp16 hi/lo A-fragments (8 k16 groups) ----
            uint32_t pa_h[8][4], pa_l[8][4];
#pragma unroll
            for (int kk = 0; kk < 8; ++kk) {
                const int t0 = 2 * kk, t1 = 2 * kk + 1;
                const float pv[8] = { s[t0][0], s[t0][1], s[t0][2], s[t0][3],
                                      s[t1][0], s[t1][1], s[t1][2], s[t1][3] };
                float ph[8], pr[8];
#pragma unroll
                for (int e = 0; e < 8; ++e) {
                    __half hh = __float2half_rn(pv[e]);
                    ph[e] = __half2float(hh);
                    pr[e] = pv[e] - ph[e];
                }
                pa_h[kk][0] = pack_h2(ph[0], ph[1]);
                pa_h[kk][1] = pack_h2(ph[2], ph[3]);
                pa_h[kk][2] = pack_h2(ph[4], ph[5]);
                pa_h[kk][3] = pack_h2(ph[6], ph[7]);
                pa_l[kk][0] = pack_h2(pr[0], pr[1]);
                pa_l[kk][1] = pack_h2(pr[2], pr[3]);
                pa_l[kk][2] = pack_h2(pr[4], pr[5]);
                pa_l[kk][3] = pack_h2(pr[6], pr[7]);
            }

            // ---- O += P @ V over 128 contraction cols, kk-outer ----
#pragma unroll
            for (int kk = 0; kk < 8; ++kk) {
                const uint32_t vsrc = (kk < 4) ? v_s0 : v_s1;
                const uint32_t vrow = (uint32_t)((kk & 3) * 16) * AROWSTR;
                uint32_t vb_[8][4];
#pragma unroll
                for (int g = 0; g < 8; ++g)
                    LDSM4T(vb_[g], vsrc + vrow + g * 32 + vb_off);
#pragma unroll
                for (int g = 0; g < 8; ++g) {
                    MMA_F16(o[2 * g],     pa_h[kk], vb_[g][0], vb_[g][1]);
                    MMA_F16(o[2 * g + 1], pa_h[kk], vb_[g][2], vb_[g][3]);
                }
#pragma unroll
                for (int g = 0; g < 8; ++g) {
                    MMA_F16(o[2 * g],     pa_l[kk], vb_[g][0], vb_[g][1]);
                    MMA_F16(o[2 * g + 1], pa_l[kk], vb_[g][2], vb_[g][3]);
                }
            }
        }
    }
#undef LOAD_KVPAIR

    const float inv0 = 1.0f / l_i[0];
    const float inv1 = 1.0f / l_i[1];
    const int rg0 = b * LL + q0 + wr + (lane >> 2);
    const int rg1 = rg0 + 8;
#pragma unroll
    for (int nt = 0; nt < 16; ++nt) {
        const int col = h * HDIM + nt * 8 + (lane & 3) * 2;
        {
            float vx = o[nt][0] * inv0, vy = o[nt][1] * inv0;
            __half hx = __float2half_rn(vx), hy = __float2half_rn(vy);
            float rx = vx - __half2float(hx), ry = vy - __half2float(hy);
            __half2 hp; hp.x = hx; hp.y = hy;
            size_t idx = (size_t)rg0 * DD + col;
            *(uint32_t*)(cth + idx) = *(uint32_t*)&hp;
            *(uint32_t*)(ctl + idx) = pack_h2(rx, ry);
        }
        {
            float vx = o[nt][2] * inv1, vy = o[nt][3] * inv1;
            __half hx = __float2half_rn(vx), hy = __float2half_rn(vy);
            float rx = vx - __half2float(hx), ry = vy - __half2float(hy);
            __half2 hp; hp.x = hx; hp.y = hy;
            size_t idx = (size_t)rg1 * DD + col;
            *(uint32_t*)(cth + idx) = *(uint32_t*)&hp;
            *(uint32_t*)(ctl + idx) = pack_h2(rx, ry);
        }
    }
}

// ---------------------------------------------------------------------------
// Launch.  d_out layout: [ out (B*L*D) | k (B*H*L*d) | v (B*H*L*d) ]
// ---------------------------------------------------------------------------
extern "C" void kernel_launch(void* const* d_in, const int* in_sizes, int n_in,
                              void* d_out, int out_size)
{
    const float* x  = (const float*)d_in[0];
    const float* Wq = (const float*)d_in[2];
    const float* bq = (const float*)d_in[3];
    const float* Wk = (const float*)d_in[4];
    const float* bk = (const float*)d_in[5];
    const float* Wv = (const float*)d_in[6];
    const float* bv = (const float*)d_in[7];
    const float* Wo = (const float*)d_in[8];
    const float* bo = (const float*)d_in[9];

    float* out_p = (float*)d_out;
    float* k_out = out_p + (size_t)BB * LL * DD;
    float* v_out = k_out + (size_t)BB * HH * LL * HDIM;

    __half *ah, *al, *btq, *btk, *btv, *bto, *qh, *ql, *kh, *vh;
    cudaGetSymbolAddress((void**)&ah, g_ah);
    cudaGetSymbolAddress((void**)&al, g_al);
    cudaGetSymbolAddress((void**)&btq, g_bq);
    cudaGetSymbolAddress((void**)&btk, g_bk);
    cudaGetSymbolAddress((void**)&btv, g_bv);
    cudaGetSymbolAddress((void**)&bto, g_bo);
    cudaGetSymbolAddress((void**)&qh, g_qh);
    cudaGetSymbolAddress((void**)&ql, g_ql);
    cudaGetSymbolAddress((void**)&kh, g_kh);
    cudaGetSymbolAddress((void**)&vh, g_vh);

    cudaFuncSetAttribute(gemm_mma_kernel, cudaFuncAttributeMaxDynamicSharedMemorySize, GEMM_SMEM);
    cudaFuncSetAttribute(attn_mma_kernel, cudaFuncAttributeMaxDynamicSharedMemorySize, ATT_SMEM);

    // persistent grid: 2 CTAs per SM
    int n_sm = 148;
    cudaDeviceGetAttribute(&n_sm, cudaDevAttrMultiProcessorCount, 0);
    const int pgrid = 2 * n_sm;

    const int n4 = MM * DD / 4;
    const int cs_blocks = n4 / 256;
    dim3 tr_grid(DD / 32, DD / 32, 4);
    dim3 tr_block(32, 8);

    // upfront conversions
    conv_split_kernel<<<cs_blocks, 256>>>((const float4*)x, (h16x4*)ah, (h16x4*)al, n4);
    conv_tr4_kernel<<<tr_grid, tr_block>>>(Wq, Wk, Wv, Wo, btq, btk, btv, bto);

    // Q projection: 1-term A (score-path only; error audit in commit msg)
    gemm_mma_kernel<<<pgrid, 128, GEMM_SMEM>>>(
        ah, nullptr, btq, bq, nullptr, qh, ql, ATT_SCALE, 1,
        btq, bq, nullptr, qh, NTILES);

    // K+V projections fused into one persistent launch (2048 tiles)
    gemm_mma_kernel<<<pgrid, 128, GEMM_SMEM>>>(
        ah, nullptr, btk, bk, k_out, kh, nullptr, 1.0f, 2,
        btv, bv, v_out, vh, 2 * NTILES);

    // attention -> ctx fp16 split into ah/al
    dim3 ag(LL / 128, HH, BB);
    attn_mma_kernel<<<ag, 256, ATT_SMEM>>>(qh, ql, kh, vh, ah, al);

    // output projection (full 2-term), persistent
    gemm_mma_kernel<<<pgrid, 128, GEMM_SMEM>>>(
        ah, al, bto, bo, out_p, nullptr, nullptr, 1.0f, 0,
        bto, bo, out_p, nullptr, NTILES);
}

// round 16
// speedup vs baseline: 1.5845x; 1.1553x over previous
#include <cuda_runtime.h>
#include <cuda_fp16.h>
#include <math.h>
#include <stdint.h>

// Problem constants
#define BB 2
#define LL 2048
#define DD 4096
#define HH 32
#define HDIM 128
#define MM (BB*LL)          // 4096 rows
#define ATT_SCALE 0.08838834764831845f

// ---------------------------------------------------------------------------
// Scratch (allocation-free rule: __device__ globals)
// ---------------------------------------------------------------------------
__device__ __half g_ah[(size_t)MM*DD];       // A hi (x or ctx)
__device__ __half g_al[(size_t)MM*DD];       // A lo (unused; kept for safety)
__device__ __half g_bq[(size_t)DD*DD];       // Wq^T fp16 [N,K]
__device__ __half g_bk[(size_t)DD*DD];
__device__ __half g_bv[(size_t)DD*DD];
__device__ __half g_bo[(size_t)DD*DD];
__device__ __half g_qh[(size_t)MM*DD];       // q hi (scaled) [B,H,L,d]
__device__ __half g_ql[(size_t)MM*DD];       // q lo
__device__ __half g_kh[(size_t)MM*DD];       // k fp16
__device__ __half g_vh[(size_t)MM*DD];       // v fp16

__device__ __forceinline__ uint32_t smem_u32(const void* p) {
    uint32_t a;
    asm("{ .reg .u64 t; cvta.to.shared.u64 t, %1; cvt.u32.u64 %0, t; }"
        : "=r"(a) : "l"(p));
    return a;
}

#define LDSM4(r, addr) \
    asm volatile("ldmatrix.sync.aligned.m8n8.x4.shared.b16 {%0,%1,%2,%3}, [%4];" \
        : "=r"((r)[0]), "=r"((r)[1]), "=r"((r)[2]), "=r"((r)[3]) : "r"(addr))
#define LDSM4T(r, addr) \
    asm volatile("ldmatrix.sync.aligned.m8n8.x4.trans.shared.b16 {%0,%1,%2,%3}, [%4];" \
        : "=r"((r)[0]), "=r"((r)[1]), "=r"((r)[2]), "=r"((r)[3]) : "r"(addr))

#define MMA_F16(d, a, b0, b1) \
    asm volatile("mma.sync.aligned.m16n8k16.row.col.f32.f16.f16.f32 " \
        "{%0,%1,%2,%3}, {%4,%5,%6,%7}, {%8,%9}, {%0,%1,%2,%3};" \
        : "+f"((d)[0]), "+f"((d)[1]), "+f"((d)[2]), "+f"((d)[3]) \
        : "r"((a)[0]), "r"((a)[1]), "r"((a)[2]), "r"((a)[3]), "r"(b0), "r"(b1))

#define CP_ASYNC16(dst, src) \
    asm volatile("cp.async.cg.shared.global [%0], [%1], 16;" \
        :: "r"(dst), "l"(src) : "memory")
#define CP_COMMIT() asm volatile("cp.async.commit_group;" ::: "memory")
#define CP_WAIT1() asm volatile("cp.async.wait_group 1;" ::: "memory")
#define CP_WAIT0() asm volatile("cp.async.wait_group 0;" ::: "memory")

__device__ __forceinline__ uint32_t pack_h2(float x, float y) {
    __half2 t = __floats2half2_rn(x, y);
    return *(uint32_t*)&t;
}

// ---------------------------------------------------------------------------
// Conversion kernels
// ---------------------------------------------------------------------------
struct __align__(8) h16x4 { __half v[4]; };

// fp32 -> fp16 (hi only; no GEMM consumes the x-lo term anymore)
__global__ __launch_bounds__(256) void conv_h_kernel(
    const float4* __restrict__ in, h16x4* __restrict__ oh, int n4)
{
    int i = blockIdx.x * 256 + threadIdx.x;
    if (i >= n4) return;
    float4 x = in[i];
    h16x4 h;
    h.v[0] = __float2half_rn(x.x);
    h.v[1] = __float2half_rn(x.y);
    h.v[2] = __float2half_rn(x.z);
    h.v[3] = __float2half_rn(x.w);
    oh[i] = h;
}

// 4 weight transposes fused: W [K,N] f32 -> Wt fp16 [N,K], blockIdx.z picks W.
__global__ __launch_bounds__(256) void conv_tr4_kernel(
    const float* __restrict__ W0, const float* __restrict__ W1,
    const float* __restrict__ W2, const float* __restrict__ W3,
    __half* __restrict__ T0, __half* __restrict__ T1,
    __half* __restrict__ T2, __half* __restrict__ T3)
{
    const float* W = (blockIdx.z == 0) ? W0 : (blockIdx.z == 1) ? W1
                    : (blockIdx.z == 2) ? W2 : W3;
    __half* Th = (blockIdx.z == 0) ? T0 : (blockIdx.z == 1) ? T1
                : (blockIdx.z == 2) ? T2 : T3;
    __shared__ float sm[32][33];
    const int k0 = blockIdx.x * 32, n0 = blockIdx.y * 32;
    const int tx = threadIdx.x, ty = threadIdx.y;     // (32, 8)
#pragma unroll
    for (int i = 0; i < 4; i++)
        sm[ty + 8 * i][tx] = W[(size_t)(k0 + ty + 8 * i) * DD + n0 + tx];
    __syncthreads();
#pragma unroll
    for (int i = 0; i < 4; i++) {
        float v = sm[tx][ty + 8 * i];
        Th[(size_t)(n0 + ty + 8 * i) * DD + k0 + tx] = __float2half_rn(v);
    }
}

// ---------------------------------------------------------------------------
// Persistent HMMA GEMM: CTA 128x128, 4 warps 2x2, warp tile 64x64,
// K-chunk 64, XOR-swizzled smem, 2 stages, 2 CTAs/SM.
// Grid-stride over ntotal tiles; tiles >= NTILES use the second job.
// Al == nullptr -> single-term A.
// out_mode 0: fp32 row-major; 1: fp16 hi/lo scaled head-split (Q);
// 2: fp32 head-split + fp16 head-split (K,V)
// ---------------------------------------------------------------------------
#define KCH 64
#define TILE_SZ 16384                     // 128 rows x 128 B
#define STAGE_BYTES (3 * TILE_SZ)         // 49152  (Ah, Al, B)
#define GEMM_SMEM (2 * STAGE_BYTES)       // 98304
#define NCHUNK (DD / KCH)                 // 64
#define NTILES ((MM / 128) * (DD / 128))  // 1024

__global__ __launch_bounds__(128, 2) void gemm_mma_kernel(
    const __half* __restrict__ Ah, const __half* __restrict__ Al,
    const __half* __restrict__ B,
    const float* __restrict__ bias, float* __restrict__ out,
    __half* __restrict__ oh, __half* __restrict__ ol,
    float scale, int out_mode,
    const __half* __restrict__ B2, const float* __restrict__ bias2,
    float* __restrict__ out2, __half* __restrict__ oh2,
    int ntotal)
{
    extern __shared__ __align__(16) char smem[];
    const uint32_t sb = smem_u32(smem);
    const int tid = threadIdx.x, lane = tid & 31, wid = tid >> 5;
    const int wm = wid >> 1;              // 0..1
    const int wn = wid & 1;               // 0..1
    const bool has_lo = (Al != nullptr);

    // per-lane LDSM addressing (swizzled): row stride 128B, granule ^= (row&7)
    const int rowA = wm * 64 + (lane & 15);
    const int a_half = lane >> 4;
    const int s_a = lane & 7;
    const int rowB = wn * 64 + ((lane >> 4) << 3) + (lane & 7);
    const int b_half = (lane >> 3) & 1;
    const int s_b = lane & 7;

#pragma unroll 1
    for (int gid = blockIdx.x; gid < ntotal; gid += gridDim.x) {
        const bool second = (gid >= NTILES);
        const int tg = second ? gid - NTILES : gid;
        const __half* Bx = second ? B2 : B;
        const float* biasx = second ? bias2 : bias;
        float* outx = second ? out2 : out;
        __half* ohx = second ? oh2 : oh;

        // swizzled block mapping: groups of (32 m x 8 n)
        const int m0 = (((tg & 255) >> 3)) * 128;
        const int n0 = (((tg >> 8) << 3) | (tg & 7)) * 128;

        const __half* gsrc[3];
        gsrc[0] = Ah + (size_t)m0 * DD;
        gsrc[1] = has_lo ? (Al + (size_t)m0 * DD) : gsrc[0];
        gsrc[2] = Bx + (size_t)n0 * DD;

        float acc[4][8][4];
#pragma unroll
        for (int i = 0; i < 4; i++)
#pragma unroll
            for (int j = 0; j < 8; j++)
#pragma unroll
                for (int e = 0; e < 4; e++) acc[i][j][e] = 0.f;

#define LOAD_CHUNK(cc, st) do {                                                \
    const uint32_t stage_ = sb + (uint32_t)(st) * STAGE_BYTES;                 \
    _Pragma("unroll")                                                          \
    for (int t_ = 0; t_ < 3; ++t_) {                                           \
        if (t_ == 1 && !has_lo) continue;                                      \
        const __half* gp_ = gsrc[t_] + (size_t)(cc) * KCH;                     \
        _Pragma("unroll")                                                      \
        for (int i_ = 0; i_ < 8; ++i_) {                                       \
            int f_ = tid + i_ * 128;              /* 0..1023 */                \
            int r_ = f_ >> 3, g_ = f_ & 7;                                     \
            const void* src_ = gp_ + (size_t)r_ * DD + g_ * 8;                 \
            uint32_t dst_ = stage_ + t_ * TILE_SZ + r_ * 128                   \
                            + ((g_ ^ (r_ & 7)) << 4);                          \
            CP_ASYNC16(dst_, src_);                                            \
        }                                                                      \
    }                                                                          \
    CP_COMMIT();                                                               \
} while (0)

        LOAD_CHUNK(0, 0);

#pragma unroll 1
        for (int c = 0; c < NCHUNK; ++c) {
            if (c + 1 < NCHUNK) {
                LOAD_CHUNK(c + 1, (c + 1) & 1);
                CP_WAIT1();
            } else {
                CP_WAIT0();
            }
            __syncthreads();

            const uint32_t stage = sb + (uint32_t)(c & 1) * STAGE_BYTES;

#pragma unroll
            for (int kk = 0; kk < 4; ++kk) {
                const uint32_t ga = (uint32_t)(((2 * kk + a_half) ^ s_a) << 4);
                const uint32_t gb = (uint32_t)(((2 * kk + b_half) ^ s_b) << 4);
                uint32_t ah_[4][4], bf_[4][4];
#pragma unroll
                for (int i = 0; i < 4; ++i) {
                    const uint32_t ra = (uint32_t)(rowA + i * 16) * 128 + ga;
                    LDSM4(ah_[i], stage + ra);
                }
#pragma unroll
                for (int j = 0; j < 4; ++j)
                    LDSM4(bf_[j], stage + 2 * TILE_SZ
                                  + (uint32_t)(rowB + j * 16) * 128 + gb);
#pragma unroll
                for (int i = 0; i < 4; ++i)
#pragma unroll
                    for (int jn = 0; jn < 8; ++jn)
                        MMA_F16(acc[i][jn], ah_[i], bf_[jn >> 1][(jn & 1) * 2],
                                bf_[jn >> 1][(jn & 1) * 2 + 1]);
                if (has_lo) {
                    uint32_t al_[4][4];
#pragma unroll
                    for (int i = 0; i < 4; ++i) {
                        const uint32_t ra = (uint32_t)(rowA + i * 16) * 128 + ga;
                        LDSM4(al_[i], stage + TILE_SZ + ra);
                    }
#pragma unroll
                    for (int i = 0; i < 4; ++i)
#pragma unroll
                        for (int jn = 0; jn < 8; ++jn)
                            MMA_F16(acc[i][jn], al_[i], bf_[jn >> 1][(jn & 1) * 2],
                                    bf_[jn >> 1][(jn & 1) * 2 + 1]);
                }
            }
            __syncthreads();
        }
#undef LOAD_CHUNK

        // epilogue
#pragma unroll
        for (int i = 0; i < 4; ++i) {
            const int r_lo = m0 + wm * 64 + i * 16 + (lane >> 2);
#pragma unroll
            for (int jn = 0; jn < 8; ++jn) {
                const int colg = n0 + wn * 64 + jn * 8 + (lane & 3) * 2;
                const float bv0 = biasx[colg], bv1 = biasx[colg + 1];
#pragma unroll
                for (int half_ = 0; half_ < 2; ++half_) {
                    const int row = r_lo + half_ * 8;
                    float vx = acc[i][jn][half_ * 2 + 0] + bv0;
                    float vy = acc[i][jn][half_ * 2 + 1] + bv1;
                    if (out_mode == 0) {
                        float2 v; v.x = vx; v.y = vy;
                        *(float2*)(outx + (size_t)row * DD + colg) = v;
                    } else {
                        int b_ = row >> 11, l_ = row & 2047, h_ = colg >> 7, dd = colg & 127;
                        size_t idx = ((((size_t)b_ * HH + h_) * LL + l_) * HDIM) + dd;
                        if (out_mode == 2) {
                            float2 v; v.x = vx; v.y = vy;
                            *(float2*)(outx + idx) = v;
                            *(uint32_t*)(ohx + idx) = pack_h2(vx, vy);
                        } else {
                            float sx = vx * scale, sy = vy * scale;
                            __half hx = __float2half_rn(sx), hy = __float2half_rn(sy);
                            float rx = sx - __half2float(hx), ry = sy - __half2float(hy);
                            __half2 hp; hp.x = hx; hp.y = hy;
                            *(uint32_t*)(ohx + idx) = *(uint32_t*)&hp;
                            *(uint32_t*)(ol + idx) = pack_h2(rx, ry);
                        }
                    }
                }
            }
        }
    }
}

// ---------------------------------------------------------------------------
// Flash attention (causal), HMMA fp16 2-term.
// KV in pairs of 64-row tiles (128 cols/iter), double-buffered pairs.
// Longest-first: qt = gridDim.x-1-blockIdx.x.
// ctl == nullptr -> skip lo-split of ctx output (Wo consumes hi only).
// Grid (L/128, H, B), 256 threads (8 warps x 16 q-rows).
// ---------------------------------------------------------------------------
#define AROWSTR 272                        // 128 fp16 = 256 B + 16 pad
#define ATILE_Q (128 * AROWSTR)            // 34816
#define ATILE_KV (64 * AROWSTR)            // 17408
#define ATT_SMEM (2 * ATILE_Q + 8 * ATILE_KV)   // 208896

__global__ __launch_bounds__(256, 1) void attn_mma_kernel(
    const __half* __restrict__ qh, const __half* __restrict__ ql,
    const __half* __restrict__ kh, const __half* __restrict__ vh,
    __half* __restrict__ cth, __half* __restrict__ ctl)
{
    extern __shared__ __align__(16) char smem[];
    const uint32_t sb = smem_u32(smem);
    const int tid = threadIdx.x, lane = tid & 31, wid = tid >> 5;
    const int wr = wid * 16;

    const int qt = gridDim.x - 1 - blockIdx.x;   // longest-first scheduling
    const int h = blockIdx.y, b = blockIdx.z;
    const int q0 = qt * 128;
    const size_t hb = ((size_t)b * HH + h) * LL * HDIM;

    {
        const __half* srcs[2] = { qh + hb, ql + hb };
#pragma unroll
        for (int t = 0; t < 2; ++t)
#pragma unroll
            for (int i = 0; i < 8; ++i) {
                int f = tid + i * 256;
                int r = f >> 4, s = f & 15;
                CP_ASYNC16(sb + t * ATILE_Q + r * AROWSTR + s * 16,
                           srcs[t] + (size_t)(q0 + r) * HDIM + s * 8);
            }
        CP_COMMIT();
    }

    // Pair buffers: pair p at 2*ATILE_Q + p*4*ATILE_KV: [K0, V0, K1, V1]
#define LOAD_KVPAIR(it_, p_) do {                                              \
    _Pragma("unroll")                                                          \
    for (int t_ = 0; t_ < 4; ++t_) {                                           \
        const __half* src_ = (t_ & 1) ? (vh + hb) : (kh + hb);                 \
        const int k0_ = ((it_) * 2 + (t_ >> 1)) * 64;                          \
        const uint32_t base_ = sb + 2 * ATILE_Q + (p_) * 4 * ATILE_KV          \
                               + t_ * ATILE_KV;                                \
        _Pragma("unroll")                                                      \
        for (int i_ = 0; i_ < 4; ++i_) {                                       \
            int f_ = tid + i_ * 256;                                           \
            int r_ = f_ >> 4, s_ = f_ & 15;                                    \
            CP_ASYNC16(base_ + r_ * AROWSTR + s_ * 16,                         \
                       src_ + (size_t)(k0_ + r_) * HDIM + s_ * 8);             \
        }                                                                      \
    }                                                                          \
    CP_COMMIT();                                                               \
} while (0)

    LOAD_KVPAIR(0, 0);

    float o[16][4];
#pragma unroll
    for (int i = 0; i < 16; ++i)
#pragma unroll
        for (int e = 0; e < 4; ++e) o[i][e] = 0.f;
    float m_i[2] = { -1e30f, -1e30f };
    float l_i[2] = { 0.f, 0.f };

    const uint32_t qa_off = (uint32_t)(wr + (lane & 15)) * AROWSTR + ((lane >> 4) << 4);
    const uint32_t kb_off = (uint32_t)(((lane >> 4) << 3) + (lane & 7)) * AROWSTR
                            + (((lane >> 3) & 1) << 4);
    const uint32_t vb_off = (uint32_t)(((lane >> 3) & 1) * 8 + (lane & 7)) * AROWSTR
                            + ((lane >> 4) << 4);

    const int nit = qt + 1;               // pairs of 64-tiles

#pragma unroll 1
    for (int it = 0; it < nit; ++it) {
        const int k0 = it * 128;
        __syncthreads();
        if (it + 1 < nit) {
            LOAD_KVPAIR(it + 1, (it + 1) & 1);
            CP_WAIT1();
        } else {
            CP_WAIT0();
        }
        __syncthreads();

        const bool active = (k0 <= q0 + wr + 15);
        if (active) {
            const uint32_t pairb = sb + 2 * ATILE_Q + (uint32_t)(it & 1) * 4 * ATILE_KV;
            const uint32_t k_s0 = pairb;
            const uint32_t v_s0 = pairb + ATILE_KV;
            const uint32_t k_s1 = pairb + 2 * ATILE_KV;
            const uint32_t v_s1 = pairb + 3 * ATILE_KV;

            float s[16][4];
#pragma unroll
            for (int i = 0; i < 16; ++i)
#pragma unroll
                for (int e = 0; e < 4; ++e) s[i][e] = 0.f;

            // ---- S = Q @ K^T over 128 cols (2-term) ----
#pragma unroll
            for (int kk = 0; kk < 8; ++kk) {
                uint32_t qa_h[4], qa_l[4], kb_[8][4];
                LDSM4(qa_h, sb + 0 * ATILE_Q + qa_off + kk * 32);
                LDSM4(qa_l, sb + 1 * ATILE_Q + qa_off + kk * 32);
#pragma unroll
                for (int g = 0; g < 4; ++g) {
                    LDSM4(kb_[g],     k_s0 + g * 16 * AROWSTR + kb_off + kk * 32);
                    LDSM4(kb_[4 + g], k_s1 + g * 16 * AROWSTR + kb_off + kk * 32);
                }
#pragma unroll
                for (int g = 0; g < 8; ++g)
#pragma unroll
                    for (int jj = 0; jj < 2; ++jj)
                        MMA_F16(s[2 * g + jj], qa_h, kb_[g][jj * 2], kb_[g][jj * 2 + 1]);
#pragma unroll
                for (int g = 0; g < 8; ++g)
#pragma unroll
                    for (int jj = 0; jj < 2; ++jj)
                        MMA_F16(s[2 * g + jj], qa_l, kb_[g][jj * 2], kb_[g][jj * 2 + 1]);
            }

            // ---- causal mask ----
            const int r0g = q0 + wr + (lane >> 2);
            if (k0 + 127 > q0 + wr) {
#pragma unroll
                for (int nt = 0; nt < 16; ++nt) {
                    const int cg = k0 + nt * 8 + (lane & 3) * 2;
#pragma unroll
                    for (int e = 0; e < 4; ++e) {
                        const int rr = r0g + (e >> 1) * 8;
                        const int cc = cg + (e & 1);
                        if (cc > rr) s[nt][e] = -1e30f;
                    }
                }
            }

            // ---- online softmax over 128 cols ----
            float scl[2];
#pragma unroll
            for (int rh = 0; rh < 2; ++rh) {
                float mx = -1e30f;
#pragma unroll
                for (int nt = 0; nt < 16; ++nt)
                    mx = fmaxf(mx, fmaxf(s[nt][rh * 2], s[nt][rh * 2 + 1]));
                mx = fmaxf(mx, __shfl_xor_sync(0xffffffffu, mx, 1));
                mx = fmaxf(mx, __shfl_xor_sync(0xffffffffu, mx, 2));
                const float m_new = fmaxf(m_i[rh], mx);
                scl[rh] = __expf(m_i[rh] - m_new);
                float rs = 0.f;
#pragma unroll
                for (int nt = 0; nt < 16; ++nt) {
                    float p0 = __expf(s[nt][rh * 2] - m_new);
                    float p1 = __expf(s[nt][rh * 2 + 1] - m_new);
                    s[nt][rh * 2] = p0;
                    s[nt][rh * 2 + 1] = p1;
                    rs += p0 + p1;
                }
                rs += __shfl_xor_sync(0xffffffffu, rs, 1);
                rs += __shfl_xor_sync(0xffffffffu, rs, 2);
                l_i[rh] = l_i[rh] * scl[rh] + rs;
                m_i[rh] = m_new;
            }
#pragma unroll
            for (int i = 0; i < 16; ++i) {
                o[i][0] *= scl[0]; o[i][1] *= scl[0];
                o[i][2] *= scl[1]; o[i][3] *= scl[1];
            }

            // ---- split P into fp16 hi/lo A-fragments (8 k16 groups) ----
            uint32_t pa_h[8][4], pa_l[8][4];
#pragma unroll
            for (int kk = 0; kk < 8; ++kk) {
                const int t0 = 2 * kk, t1 = 2 * kk + 1;
                const float pv[8] = { s[t0][0], s[t0][1], s[t0][2], s[t0][3],
                                      s[t1][0], s[t1][1], s[t1][2], s[t1][3] };
                float ph[8], pr[8];
#pragma unroll
                for (int e = 0; e < 8; ++e) {
                    __half hh = __float2half_rn(pv[e]);
                    ph[e] = __half2float(hh);
                    pr[e] = pv[e] - ph[e];
                }
                pa_h[kk][0] = pack_h2(ph[0], ph[1]);
                pa_h[kk][1] = pack_h2(ph[2], ph[3]);
                pa_h[kk][2] = pack_h2(ph[4], ph[5]);
                pa_h[kk][3] = pack_h2(ph[6], ph[7]);
                pa_l[kk][0] = pack_h2(pr[0], pr[1]);
                pa_l[kk][1] = pack_h2(pr[2], pr[3]);
                pa_l[kk][2] = pack_h2(pr[4], pr[5]);
                pa_l[kk][3] = pack_h2(pr[6], pr[7]);
            }

            // ---- O += P @ V over 128 contraction cols, kk-outer ----
#pragma unroll
            for (int kk = 0; kk < 8; ++kk) {
                const uint32_t vsrc = (kk < 4) ? v_s0 : v_s1;
                const uint32_t vrow = (uint32_t)((kk & 3) * 16) * AROWSTR;
                uint32_t vb_[8][4];
#pragma unroll
                for (int g = 0; g < 8; ++g)
                    LDSM4T(vb_[g], vsrc + vrow + g * 32 + vb_off);
#pragma unroll
                for (int g = 0; g < 8; ++g) {
                    MMA_F16(o[2 * g],     pa_h[kk], vb_[g][0], vb_[g][1]);
                    MMA_F16(o[2 * g + 1], pa_h[kk], vb_[g][2], vb_[g][3]);
                }
#pragma unroll
                for (int g = 0; g < 8; ++g) {
                    MMA_F16(o[2 * g],     pa_l[kk], vb_[g][0], vb_[g][1]);
                    MMA_F16(o[2 * g + 1], pa_l[kk], vb_[g][2], vb_[g][3]);
                }
            }
        }
    }
#undef LOAD_KVPAIR

    const float inv0 = 1.0f / l_i[0];
    const float inv1 = 1.0f / l_i[1];
    const int rg0 = b * LL + q0 + wr + (lane >> 2);
    const int rg1 = rg0 + 8;
    const bool wlo = (ctl != nullptr);
#pragma unroll
    for (int nt = 0; nt < 16; ++nt) {
        const int col = h * HDIM + nt * 8 + (lane & 3) * 2;
        {
            float vx = o[nt][0] * inv0, vy = o[nt][1] * inv0;
            __half hx = __float2half_rn(vx), hy = __float2half_rn(vy);
            __half2 hp; hp.x = hx; hp.y = hy;
            size_t idx = (size_t)rg0 * DD + col;
            *(uint32_t*)(cth + idx) = *(uint32_t*)&hp;
            if (wlo) {
                float rx = vx - __half2float(hx), ry = vy - __half2float(hy);
                *(uint32_t*)(ctl + idx) = pack_h2(rx, ry);
            }
        }
        {
            float vx = o[nt][2] * inv1, vy = o[nt][3] * inv1;
            __half hx = __float2half_rn(vx), hy = __float2half_rn(vy);
            __half2 hp; hp.x = hx; hp.y = hy;
            size_t idx = (size_t)rg1 * DD + col;
            *(uint32_t*)(cth + idx) = *(uint32_t*)&hp;
            if (wlo) {
                float rx = vx - __half2float(hx), ry = vy - __half2float(hy);
                *(uint32_t*)(ctl + idx) = pack_h2(rx, ry);
            }
        }
    }
}

// ---------------------------------------------------------------------------
// Launch.  d_out layout: [ out (B*L*D) | k (B*H*L*d) | v (B*H*L*d) ]
// ---------------------------------------------------------------------------
extern "C" void kernel_launch(void* const* d_in, const int* in_sizes, int n_in,
                              void* d_out, int out_size)
{
    const float* x  = (const float*)d_in[0];
    const float* Wq = (const float*)d_in[2];
    const float* bq = (const float*)d_in[3];
    const float* Wk = (const float*)d_in[4];
    const float* bk = (const float*)d_in[5];
    const float* Wv = (const float*)d_in[6];
    const float* bv = (const float*)d_in[7];
    const float* Wo = (const float*)d_in[8];
    const float* bo = (const float*)d_in[9];

    float* out_p = (float*)d_out;
    float* k_out = out_p + (size_t)BB * LL * DD;
    float* v_out = k_out + (size_t)BB * HH * LL * HDIM;

    __half *ah, *btq, *btk, *btv, *bto, *qh, *ql, *kh, *vh;
    cudaGetSymbolAddress((void**)&ah, g_ah);
    cudaGetSymbolAddress((void**)&btq, g_bq);
    cudaGetSymbolAddress((void**)&btk, g_bk);
    cudaGetSymbolAddress((void**)&btv, g_bv);
    cudaGetSymbolAddress((void**)&bto, g_bo);
    cudaGetSymbolAddress((void**)&qh, g_qh);
    cudaGetSymbolAddress((void**)&ql, g_ql);
    cudaGetSymbolAddress((void**)&kh, g_kh);
    cudaGetSymbolAddress((void**)&vh, g_vh);

    cudaFuncSetAttribute(gemm_mma_kernel, cudaFuncAttributeMaxDynamicSharedMemorySize, GEMM_SMEM);
    cudaFuncSetAttribute(attn_mma_kernel, cudaFuncAttributeMaxDynamicSharedMemorySize, ATT_SMEM);

    // persistent grid: 2 CTAs per SM
    int n_sm = 148;
    cudaDeviceGetAttribute(&n_sm, cudaDevAttrMultiProcessorCount, 0);
    const int pgrid = 2 * n_sm;

    const int n4 = MM * DD / 4;
    const int cs_blocks = n4 / 256;
    dim3 tr_grid(DD / 32, DD / 32, 4);
    dim3 tr_block(32, 8);

    // upfront conversions (x -> fp16 hi only; no consumer of x-lo remains)
    conv_h_kernel<<<cs_blocks, 256>>>((const float4*)x, (h16x4*)ah, n4);
    conv_tr4_kernel<<<tr_grid, tr_block>>>(Wq, Wk, Wv, Wo, btq, btk, btv, bto);

    // Q projection: 1-term A, outputs scaled fp16 hi/lo split
    gemm_mma_kernel<<<pgrid, 128, GEMM_SMEM>>>(
        ah, nullptr, btq, bq, nullptr, qh, ql, ATT_SCALE, 1,
        btq, bq, nullptr, qh, NTILES);

    // K+V projections fused into one persistent launch (2048 tiles)
    gemm_mma_kernel<<<pgrid, 128, GEMM_SMEM>>>(
        ah, nullptr, btk, bk, k_out, kh, nullptr, 1.0f, 2,
        btv, bv, v_out, vh, 2 * NTILES);

    // attention -> ctx fp16 (hi only) into ah
    dim3 ag(LL / 128, HH, BB);
    attn_mma_kernel<<<ag, 256, ATT_SMEM>>>(qh, ql, kh, vh, ah, nullptr);

    // output projection: 1-term A (ctx hi), persistent
    gemm_mma_kernel<<<pgrid, 128, GEMM_SMEM>>>(
        ah, nullptr, bto, bo, out_p, nullptr, nullptr, 1.0f, 0,
        bto, bo, out_p, nullptr, NTILES);
}

// round 17
// speedup vs baseline: 1.6681x; 1.0528x over previous
#include <cuda_runtime.h>
#include <cuda_fp16.h>
#include <math.h>
#include <stdint.h>

// Problem constants
#define BB 2
#define LL 2048
#define DD 4096
#define HH 32
#define HDIM 128
#define MM (BB*LL)          // 4096 rows
#define ATT_SCALE 0.08838834764831845f

// ---------------------------------------------------------------------------
// Scratch (allocation-free rule: __device__ globals)
// ---------------------------------------------------------------------------
__device__ __half g_ah[(size_t)MM*DD];       // A hi (x or ctx)
__device__ __half g_bq[(size_t)DD*DD];       // Wq^T fp16 [N,K]
__device__ __half g_bk[(size_t)DD*DD];
__device__ __half g_bv[(size_t)DD*DD];
__device__ __half g_bo[(size_t)DD*DD];
__device__ __half g_qh[(size_t)MM*DD];       // q hi (scaled) [B,H,L,d]
__device__ __half g_ql[(size_t)MM*DD];       // q lo
__device__ __half g_kh[(size_t)MM*DD];       // k fp16
__device__ __half g_vh[(size_t)MM*DD];       // v fp16

__device__ __forceinline__ uint32_t smem_u32(const void* p) {
    uint32_t a;
    asm("{ .reg .u64 t; cvta.to.shared.u64 t, %1; cvt.u32.u64 %0, t; }"
        : "=r"(a) : "l"(p));
    return a;
}

#define LDSM4(r, addr) \
    asm volatile("ldmatrix.sync.aligned.m8n8.x4.shared.b16 {%0,%1,%2,%3}, [%4];" \
        : "=r"((r)[0]), "=r"((r)[1]), "=r"((r)[2]), "=r"((r)[3]) : "r"(addr))
#define LDSM4T(r, addr) \
    asm volatile("ldmatrix.sync.aligned.m8n8.x4.trans.shared.b16 {%0,%1,%2,%3}, [%4];" \
        : "=r"((r)[0]), "=r"((r)[1]), "=r"((r)[2]), "=r"((r)[3]) : "r"(addr))

#define MMA_F16(d, a, b0, b1) \
    asm volatile("mma.sync.aligned.m16n8k16.row.col.f32.f16.f16.f32 " \
        "{%0,%1,%2,%3}, {%4,%5,%6,%7}, {%8,%9}, {%0,%1,%2,%3};" \
        : "+f"((d)[0]), "+f"((d)[1]), "+f"((d)[2]), "+f"((d)[3]) \
        : "r"((a)[0]), "r"((a)[1]), "r"((a)[2]), "r"((a)[3]), "r"(b0), "r"(b1))

#define CP_ASYNC16(dst, src) \
    asm volatile("cp.async.cg.shared.global [%0], [%1], 16;" \
        :: "r"(dst), "l"(src) : "memory")
#define CP_COMMIT() asm volatile("cp.async.commit_group;" ::: "memory")
#define CP_WAIT1() asm volatile("cp.async.wait_group 1;" ::: "memory")
#define CP_WAIT0() asm volatile("cp.async.wait_group 0;" ::: "memory")

__device__ __forceinline__ uint32_t pack_h2(float x, float y) {
    __half2 t = __floats2half2_rn(x, y);
    return *(uint32_t*)&t;
}

// ---------------------------------------------------------------------------
// Conversion kernels
// ---------------------------------------------------------------------------
struct __align__(8) h16x4 { __half v[4]; };

// fp32 -> fp16 (hi only)
__global__ __launch_bounds__(256) void conv_h_kernel(
    const float4* __restrict__ in, h16x4* __restrict__ oh, int n4)
{
    int i = blockIdx.x * 256 + threadIdx.x;
    if (i >= n4) return;
    float4 x = in[i];
    h16x4 h;
    h.v[0] = __float2half_rn(x.x);
    h.v[1] = __float2half_rn(x.y);
    h.v[2] = __float2half_rn(x.z);
    h.v[3] = __float2half_rn(x.w);
    oh[i] = h;
}

// 4 weight transposes fused: W [K,N] f32 -> Wt fp16 [N,K], blockIdx.z picks W.
__global__ __launch_bounds__(256) void conv_tr4_kernel(
    const float* __restrict__ W0, const float* __restrict__ W1,
    const float* __restrict__ W2, const float* __restrict__ W3,
    __half* __restrict__ T0, __half* __restrict__ T1,
    __half* __restrict__ T2, __half* __restrict__ T3)
{
    const float* W = (blockIdx.z == 0) ? W0 : (blockIdx.z == 1) ? W1
                    : (blockIdx.z == 2) ? W2 : W3;
    __half* Th = (blockIdx.z == 0) ? T0 : (blockIdx.z == 1) ? T1
                : (blockIdx.z == 2) ? T2 : T3;
    __shared__ float sm[32][33];
    const int k0 = blockIdx.x * 32, n0 = blockIdx.y * 32;
    const int tx = threadIdx.x, ty = threadIdx.y;     // (32, 8)
#pragma unroll
    for (int i = 0; i < 4; i++)
        sm[ty + 8 * i][tx] = W[(size_t)(k0 + ty + 8 * i) * DD + n0 + tx];
    __syncthreads();
#pragma unroll
    for (int i = 0; i < 4; i++) {
        float v = sm[tx][ty + 8 * i];
        Th[(size_t)(n0 + ty + 8 * i) * DD + k0 + tx] = __float2half_rn(v);
    }
}

// ---------------------------------------------------------------------------
// Persistent HMMA GEMM (R16-proven): CTA 128x128, 4 warps 2x2, warp 64x64,
// K-chunk 64, XOR-swizzled smem, 2 stages, 2 CTAs/SM, 1-term A.
// Grid-stride over ntotal tiles; tiles >= NTILES use the second job.
// out_mode 0: fp32 row-major; 1: fp16 hi/lo scaled head-split (Q);
// 2: fp32 head-split + fp16 head-split (K,V)
// ---------------------------------------------------------------------------
#define KCH 64
#define TILE_SZ 16384                     // 128 rows x 128 B
#define STAGE_BYTES (3 * TILE_SZ)         // 49152
#define GEMM_SMEM (2 * STAGE_BYTES)       // 98304
#define NCHUNK (DD / KCH)                 // 64
#define NTILES ((MM / 128) * (DD / 128))  // 1024

__global__ __launch_bounds__(128, 2) void gemm_mma_kernel(
    const __half* __restrict__ Ah,
    const __half* __restrict__ B,
    const float* __restrict__ bias, float* __restrict__ out,
    __half* __restrict__ oh, __half* __restrict__ ol,
    float scale, int out_mode,
    const __half* __restrict__ B2, const float* __restrict__ bias2,
    float* __restrict__ out2, __half* __restrict__ oh2,
    int ntotal)
{
    extern __shared__ __align__(16) char smem[];
    const uint32_t sb = smem_u32(smem);
    const int tid = threadIdx.x, lane = tid & 31, wid = tid >> 5;
    const int wm = wid >> 1;              // 0..1
    const int wn = wid & 1;               // 0..1

    const int rowA = wm * 64 + (lane & 15);
    const int a_half = lane >> 4;
    const int s_a = lane & 7;
    const int rowB = wn * 64 + ((lane >> 4) << 3) + (lane & 7);
    const int b_half = (lane >> 3) & 1;
    const int s_b = lane & 7;

#pragma unroll 1
    for (int gid = blockIdx.x; gid < ntotal; gid += gridDim.x) {
        const bool second = (gid >= NTILES);
        const int tg = second ? gid - NTILES : gid;
        const __half* Bx = second ? B2 : B;
        const float* biasx = second ? bias2 : bias;
        float* outx = second ? out2 : out;
        __half* ohx = second ? oh2 : oh;

        const int m0 = (((tg & 255) >> 3)) * 128;
        const int n0 = (((tg >> 8) << 3) | (tg & 7)) * 128;

        const __half* gA = Ah + (size_t)m0 * DD;
        const __half* gB = Bx + (size_t)n0 * DD;

        float acc[4][8][4];
#pragma unroll
        for (int i = 0; i < 4; i++)
#pragma unroll
            for (int j = 0; j < 8; j++)
#pragma unroll
                for (int e = 0; e < 4; e++) acc[i][j][e] = 0.f;

#define LOAD_CHUNK(cc, st) do {                                                \
    const uint32_t stage_ = sb + (uint32_t)(st) * STAGE_BYTES;                 \
    _Pragma("unroll")                                                          \
    for (int t_ = 0; t_ < 3; ++t_) {                                           \
        if (t_ == 1) continue;                                                 \
        const __half* gp_ = ((t_ == 0) ? gA : gB) + (size_t)(cc) * KCH;        \
        _Pragma("unroll")                                                      \
        for (int i_ = 0; i_ < 8; ++i_) {                                       \
            int f_ = tid + i_ * 128;              /* 0..1023 */                \
            int r_ = f_ >> 3, g_ = f_ & 7;                                     \
            const void* src_ = gp_ + (size_t)r_ * DD + g_ * 8;                 \
            uint32_t dst_ = stage_ + t_ * TILE_SZ + r_ * 128                   \
                            + ((g_ ^ (r_ & 7)) << 4);                          \
            CP_ASYNC16(dst_, src_);                                            \
        }                                                                      \
    }                                                                          \
    CP_COMMIT();                                                               \
} while (0)

        LOAD_CHUNK(0, 0);

#pragma unroll 1
        for (int c = 0; c < NCHUNK; ++c) {
            if (c + 1 < NCHUNK) {
                LOAD_CHUNK(c + 1, (c + 1) & 1);
                CP_WAIT1();
            } else {
                CP_WAIT0();
            }
            __syncthreads();

            const uint32_t stage = sb + (uint32_t)(c & 1) * STAGE_BYTES;

#pragma unroll
            for (int kk = 0; kk < 4; ++kk) {
                const uint32_t ga = (uint32_t)(((2 * kk + a_half) ^ s_a) << 4);
                const uint32_t gb = (uint32_t)(((2 * kk + b_half) ^ s_b) << 4);
                uint32_t ah_[4][4], bf_[4][4];
#pragma unroll
                for (int i = 0; i < 4; ++i) {
                    const uint32_t ra = (uint32_t)(rowA + i * 16) * 128 + ga;
                    LDSM4(ah_[i], stage + ra);
                }
#pragma unroll
                for (int j = 0; j < 4; ++j)
                    LDSM4(bf_[j], stage + 2 * TILE_SZ
                                  + (uint32_t)(rowB + j * 16) * 128 + gb);
#pragma unroll
                for (int i = 0; i < 4; ++i)
#pragma unroll
                    for (int jn = 0; jn < 8; ++jn)
                        MMA_F16(acc[i][jn], ah_[i], bf_[jn >> 1][(jn & 1) * 2],
                                bf_[jn >> 1][(jn & 1) * 2 + 1]);
            }
            __syncthreads();
        }
#undef LOAD_CHUNK

        // epilogue
#pragma unroll
        for (int i = 0; i < 4; ++i) {
            const int r_lo = m0 + wm * 64 + i * 16 + (lane >> 2);
#pragma unroll
            for (int jn = 0; jn < 8; ++jn) {
                const int colg = n0 + wn * 64 + jn * 8 + (lane & 3) * 2;
                const float bv0 = biasx[colg], bv1 = biasx[colg + 1];
#pragma unroll
                for (int half_ = 0; half_ < 2; ++half_) {
                    const int row = r_lo + half_ * 8;
                    float vx = acc[i][jn][half_ * 2 + 0] + bv0;
                    float vy = acc[i][jn][half_ * 2 + 1] + bv1;
                    if (out_mode == 0) {
                        float2 v; v.x = vx; v.y = vy;
                        *(float2*)(outx + (size_t)row * DD + colg) = v;
                    } else {
                        int b_ = row >> 11, l_ = row & 2047, h_ = colg >> 7, dd = colg & 127;
                        size_t idx = ((((size_t)b_ * HH + h_) * LL + l_) * HDIM) + dd;
                        if (out_mode == 2) {
                            float2 v; v.x = vx; v.y = vy;
                            *(float2*)(outx + idx) = v;
                            *(uint32_t*)(ohx + idx) = pack_h2(vx, vy);
                        } else {
                            float sx = vx * scale, sy = vy * scale;
                            __half hx = __float2half_rn(sx), hy = __float2half_rn(sy);
                            float rx = sx - __half2float(hx), ry = sy - __half2float(hy);
                            __half2 hp; hp.x = hx; hp.y = hy;
                            *(uint32_t*)(ohx + idx) = *(uint32_t*)&hp;
                            *(uint32_t*)(ol + idx) = pack_h2(rx, ry);
                        }
                    }
                }
            }
        }
    }
}

// ---------------------------------------------------------------------------
// Flash attention (causal), HMMA fp16 2-term, 2 CTAs/SM.
// 64 q-rows/CTA, 4 warps (128 threads), single-64 KV tiles double-buffered.
// Longest-first: qt = gridDim.x-1-blockIdx.x.
// ctx output: fp16 hi only (Wo consumes 1-term).
// ---------------------------------------------------------------------------
#define AROWSTR 272                        // 128 fp16 = 256 B + 16 pad
#define ATILE (64 * AROWSTR)               // 17408
#define ATT_SMEM (6 * ATILE)               // 104448: Qh, Ql, K0, V0, K1, V1

__global__ __launch_bounds__(128, 2) void attn_mma_kernel(
    const __half* __restrict__ qh, const __half* __restrict__ ql,
    const __half* __restrict__ kh, const __half* __restrict__ vh,
    __half* __restrict__ cth)
{
    extern __shared__ __align__(16) char smem[];
    const uint32_t sb = smem_u32(smem);
    const int tid = threadIdx.x, lane = tid & 31, wid = tid >> 5;
    const int wr = wid * 16;

    const int qt = gridDim.x - 1 - blockIdx.x;   // longest-first
    const int h = blockIdx.y, b = blockIdx.z;
    const int q0 = qt * 64;
    const size_t hb = ((size_t)b * HH + h) * LL * HDIM;

    // load Q tiles (hi, lo): 64 rows x 16 granules each
    {
        const __half* srcs[2] = { qh + hb, ql + hb };
#pragma unroll
        for (int t = 0; t < 2; ++t)
#pragma unroll
            for (int i = 0; i < 8; ++i) {
                int f = tid + i * 128;      // 0..1023
                int r = f >> 4, s = f & 15;
                CP_ASYNC16(sb + t * ATILE + r * AROWSTR + s * 16,
                           srcs[t] + (size_t)(q0 + r) * HDIM + s * 8);
            }
        CP_COMMIT();
    }

#define LOAD_KV(kt_, buf_) do {                                                \
    const int k0_ = (kt_) * 64;                                                \
    const __half* srcs_[2] = { kh + hb, vh + hb };                             \
    _Pragma("unroll")                                                          \
    for (int t_ = 0; t_ < 2; ++t_)                                             \
        _Pragma("unroll")                                                      \
        for (int i_ = 0; i_ < 8; ++i_) {                                       \
            int f_ = tid + i_ * 128;                                           \
            int r_ = f_ >> 4, s_ = f_ & 15;                                    \
            CP_ASYNC16(sb + (2 + 2 * (buf_) + t_) * ATILE + r_ * AROWSTR + s_ * 16, \
                       srcs_[t_] + (size_t)(k0_ + r_) * HDIM + s_ * 8);        \
        }                                                                      \
    CP_COMMIT();                                                               \
} while (0)

    LOAD_KV(0, 0);

    float o[16][4];
#pragma unroll
    for (int i = 0; i < 16; ++i)
#pragma unroll
        for (int e = 0; e < 4; ++e) o[i][e] = 0.f;
    float m_i[2] = { -1e30f, -1e30f };
    float l_i[2] = { 0.f, 0.f };

    const uint32_t qa_off = (uint32_t)(wr + (lane & 15)) * AROWSTR + ((lane >> 4) << 4);
    const uint32_t kb_off = (uint32_t)(((lane >> 4) << 3) + (lane & 7)) * AROWSTR
                            + (((lane >> 3) & 1) << 4);
    const uint32_t vb_off = (uint32_t)(((lane >> 3) & 1) * 8 + (lane & 7)) * AROWSTR
                            + ((lane >> 4) << 4);

#pragma unroll 1
    for (int kt = 0; kt <= qt; ++kt) {
        const int k0 = kt * 64;
        __syncthreads();
        if (kt + 1 <= qt) {
            LOAD_KV(kt + 1, (kt + 1) & 1);
            CP_WAIT1();
        } else {
            CP_WAIT0();
        }
        __syncthreads();

        const bool active = (k0 <= q0 + wr + 15);
        if (active) {
            const uint32_t kt_s = sb + (2 + 2 * (kt & 1)) * ATILE;
            const uint32_t vt_s = kt_s + ATILE;

            float s[8][4];
#pragma unroll
            for (int i = 0; i < 8; ++i)
#pragma unroll
                for (int e = 0; e < 4; ++e) s[i][e] = 0.f;

            // ---- S = Q @ K^T (2-term) ----
#pragma unroll
            for (int kk = 0; kk < 8; ++kk) {
                uint32_t qa_h[4], qa_l[4], kb_[4][4];
                LDSM4(qa_h, sb + 0 * ATILE + qa_off + kk * 32);
                LDSM4(qa_l, sb + 1 * ATILE + qa_off + kk * 32);
#pragma unroll
                for (int g = 0; g < 4; ++g)
                    LDSM4(kb_[g], kt_s + g * 16 * AROWSTR + kb_off + kk * 32);
#pragma unroll
                for (int g = 0; g < 4; ++g)
#pragma unroll
                    for (int jj = 0; jj < 2; ++jj)
                        MMA_F16(s[2 * g + jj], qa_h, kb_[g][jj * 2], kb_[g][jj * 2 + 1]);
#pragma unroll
                for (int g = 0; g < 4; ++g)
#pragma unroll
                    for (int jj = 0; jj < 2; ++jj)
                        MMA_F16(s[2 * g + jj], qa_l, kb_[g][jj * 2], kb_[g][jj * 2 + 1]);
            }

            // ---- causal mask ----
            const int r0g = q0 + wr + (lane >> 2);
            if (k0 + 63 > q0 + wr) {
#pragma unroll
                for (int nt = 0; nt < 8; ++nt) {
                    const int cg = k0 + nt * 8 + (lane & 3) * 2;
#pragma unroll
                    for (int e = 0; e < 4; ++e) {
                        const int rr = r0g + (e >> 1) * 8;
                        const int cc = cg + (e & 1);
                        if (cc > rr) s[nt][e] = -1e30f;
                    }
                }
            }

            // ---- online softmax ----
            float scl[2];
#pragma unroll
            for (int rh = 0; rh < 2; ++rh) {
                float mx = -1e30f;
#pragma unroll
                for (int nt = 0; nt < 8; ++nt)
                    mx = fmaxf(mx, fmaxf(s[nt][rh * 2], s[nt][rh * 2 + 1]));
                mx = fmaxf(mx, __shfl_xor_sync(0xffffffffu, mx, 1));
                mx = fmaxf(mx, __shfl_xor_sync(0xffffffffu, mx, 2));
                const float m_new = fmaxf(m_i[rh], mx);
                scl[rh] = __expf(m_i[rh] - m_new);
                float rs = 0.f;
#pragma unroll
                for (int nt = 0; nt < 8; ++nt) {
                    float p0 = __expf(s[nt][rh * 2] - m_new);
                    float p1 = __expf(s[nt][rh * 2 + 1] - m_new);
                    s[nt][rh * 2] = p0;
                    s[nt][rh * 2 + 1] = p1;
                    rs += p0 + p1;
                }
                rs += __shfl_xor_sync(0xffffffffu, rs, 1);
                rs += __shfl_xor_sync(0xffffffffu, rs, 2);
                l_i[rh] = l_i[rh] * scl[rh] + rs;
                m_i[rh] = m_new;
            }
#pragma unroll
            for (int i = 0; i < 16; ++i) {
                o[i][0] *= scl[0]; o[i][1] *= scl[0];
                o[i][2] *= scl[1]; o[i][3] *= scl[1];
            }

            // ---- split P into fp16 hi/lo A-fragments ----
            uint32_t pa_h[4][4], pa_l[4][4];
#pragma unroll
            for (int kk = 0; kk < 4; ++kk) {
                const int t0 = 2 * kk, t1 = 2 * kk + 1;
                const float pv[8] = { s[t0][0], s[t0][1], s[t0][2], s[t0][3],
                                      s[t1][0], s[t1][1], s[t1][2], s[t1][3] };
                float ph[8], pr[8];
#pragma unroll
                for (int e = 0; e < 8; ++e) {
                    __half hh = __float2half_rn(pv[e]);
                    ph[e] = __half2float(hh);
                    pr[e] = pv[e] - ph[e];
                }
                pa_h[kk][0] = pack_h2(ph[0], ph[1]);
                pa_h[kk][1] = pack_h2(ph[2], ph[3]);
                pa_h[kk][2] = pack_h2(ph[4], ph[5]);
                pa_h[kk][3] = pack_h2(ph[6], ph[7]);
                pa_l[kk][0] = pack_h2(pr[0], pr[1]);
                pa_l[kk][1] = pack_h2(pr[2], pr[3]);
                pa_l[kk][2] = pack_h2(pr[4], pr[5]);
                pa_l[kk][3] = pack_h2(pr[6], pr[7]);
            }

            // ---- O += P @ V (2-term), kk-outer ----
#pragma unroll
            for (int kk = 0; kk < 4; ++kk) {
                uint32_t vb_[8][4];
#pragma unroll
                for (int g = 0; g < 8; ++g)
                    LDSM4T(vb_[g], vt_s + (uint32_t)(kk * 16) * AROWSTR + g * 32 + vb_off);
#pragma unroll
                for (int g = 0; g < 8; ++g) {
                    MMA_F16(o[2 * g],     pa_h[kk], vb_[g][0], vb_[g][1]);
                    MMA_F16(o[2 * g + 1], pa_h[kk], vb_[g][2], vb_[g][3]);
                }
#pragma unroll
                for (int g = 0; g < 8; ++g) {
                    MMA_F16(o[2 * g],     pa_l[kk], vb_[g][0], vb_[g][1]);
                    MMA_F16(o[2 * g + 1], pa_l[kk], vb_[g][2], vb_[g][3]);
                }
            }
        }
    }
#undef LOAD_KV

    // ---- epilogue: ctx fp16 hi, row-major [B*L, D] ----
    const float inv0 = 1.0f / l_i[0];
    const float inv1 = 1.0f / l_i[1];
    const int rg0 = b * LL + q0 + wr + (lane >> 2);
    const int rg1 = rg0 + 8;
#pragma unroll
    for (int nt = 0; nt < 16; ++nt) {
        const int col = h * HDIM + nt * 8 + (lane & 3) * 2;
        *(uint32_t*)(cth + (size_t)rg0 * DD + col) =
            pack_h2(o[nt][0] * inv0, o[nt][1] * inv0);
        *(uint32_t*)(cth + (size_t)rg1 * DD + col) =
            pack_h2(o[nt][2] * inv1, o[nt][3] * inv1);
    }
}

// ---------------------------------------------------------------------------
// Launch.  d_out layout: [ out (B*L*D) | k (B*H*L*d) | v (B*H*L*d) ]
// ---------------------------------------------------------------------------
extern "C" void kernel_launch(void* const* d_in, const int* in_sizes, int n_in,
                              void* d_out, int out_size)
{
    const float* x  = (const float*)d_in[0];
    const float* Wq = (const float*)d_in[2];
    const float* bq = (const float*)d_in[3];
    const float* Wk = (const float*)d_in[4];
    const float* bk = (const float*)d_in[5];
    const float* Wv = (const float*)d_in[6];
    const float* bv = (const float*)d_in[7];
    const float* Wo = (const float*)d_in[8];
    const float* bo = (const float*)d_in[9];

    float* out_p = (float*)d_out;
    float* k_out = out_p + (size_t)BB * LL * DD;
    float* v_out = k_out + (size_t)BB * HH * LL * HDIM;

    __half *ah, *btq, *btk, *btv, *bto, *qh, *ql, *kh, *vh;
    cudaGetSymbolAddress((void**)&ah, g_ah);
    cudaGetSymbolAddress((void**)&btq, g_bq);
    cudaGetSymbolAddress((void**)&btk, g_bk);
    cudaGetSymbolAddress((void**)&btv, g_bv);
    cudaGetSymbolAddress((void**)&bto, g_bo);
    cudaGetSymbolAddress((void**)&qh, g_qh);
    cudaGetSymbolAddress((void**)&ql, g_ql);
    cudaGetSymbolAddress((void**)&kh, g_kh);
    cudaGetSymbolAddress((void**)&vh, g_vh);

    cudaFuncSetAttribute(gemm_mma_kernel, cudaFuncAttributeMaxDynamicSharedMemorySize, GEMM_SMEM);
    cudaFuncSetAttribute(attn_mma_kernel, cudaFuncAttributeMaxDynamicSharedMemorySize, ATT_SMEM);

    // persistent grid: 2 CTAs per SM
    int n_sm = 148;
    cudaDeviceGetAttribute(&n_sm, cudaDevAttrMultiProcessorCount, 0);
    const int pgrid = 2 * n_sm;

    const int n4 = MM * DD / 4;
    const int cs_blocks = n4 / 256;
    dim3 tr_grid(DD / 32, DD / 32, 4);
    dim3 tr_block(32, 8);

    // upfront conversions
    conv_h_kernel<<<cs_blocks, 256>>>((const float4*)x, (h16x4*)ah, n4);
    conv_tr4_kernel<<<tr_grid, tr_block>>>(Wq, Wk, Wv, Wo, btq, btk, btv, bto);

    // Q projection: 1-term A, outputs scaled fp16 hi/lo split
    gemm_mma_kernel<<<pgrid, 128, GEMM_SMEM>>>(
        ah, btq, bq, nullptr, qh, ql, ATT_SCALE, 1,
        btq, bq, nullptr, qh, NTILES);

    // K+V projections fused into one persistent launch (2048 tiles)
    gemm_mma_kernel<<<pgrid, 128, GEMM_SMEM>>>(
        ah, btk, bk, k_out, kh, nullptr, 1.0f, 2,
        btv, bv, v_out, vh, 2 * NTILES);

    // attention (64 q-rows/CTA, 2 CTAs/SM) -> ctx fp16 hi into ah
    dim3 ag(LL / 64, HH, BB);
    attn_mma_kernel<<<ag, 128, ATT_SMEM>>>(qh, ql, kh, vh, ah);

    // output projection: 1-term A (ctx hi), persistent
    gemm_mma_kernel<<<pgrid, 128, GEMM_SMEM>>>(
        ah, bto, bo, out_p, nullptr, nullptr, 1.0f, 0,
        bto, bo, out_p, nullptr, NTILES);
}